// round 12
// baseline (speedup 1.0000x reference)
#include <cuda_runtime.h>
#include <cuda_fp16.h>
#include <math.h>
#include <stdint.h>

// ---------------- problem constants ----------------
#define BB   16
#define CC   1024
#define TT   2048
#define DD   96
#define DP   128                 // padded D stride
#define NBQ  4
#define NEQ  2048
#define HH   8
#define CHK  16
#define NCHK 128
#define NTOK 32768
#define M2   2048
#define DH   128

typedef unsigned long long u64;

// ---------------- fp32 scratch ----------------
__device__ float g_qat[(size_t)NTOK*CC];
__device__ float g_ztt[(size_t)NTOK*CC];
__device__ float g_KVb[(size_t)NTOK*2*CC];
__device__ float g_y  [(size_t)NTOK*CC];
__device__ float g_zp [(size_t)NTOK*CC];
__device__ float g_zh [(size_t)NTOK*CC];
__device__ float g_rD [(size_t)NTOK*DP];
__device__ float g_res[(size_t)NTOK*DP];
__device__ float g_qDv[(size_t)NTOK*DP];
__device__ u64   g_keys[(size_t)NTOK];

__device__ float g_q0n [(size_t)M2*CC];
__device__ float g_Q0  [(size_t)M2*CC];
__device__ float g_y0  [(size_t)M2*CC];
__device__ float g_z0  [(size_t)M2*CC];
__device__ float g_zh0 [(size_t)M2*CC];
__device__ float g_rD0 [(size_t)M2*DP];
__device__ float g_res0[(size_t)M2*DP];
__device__ float g_qD0 [(size_t)M2*DP];

__device__ float g_qc  [(size_t)CHK*CC];
__device__ float g_Qc  [(size_t)CHK*CC];
__device__ float g_cn  [(size_t)NBQ*NEQ];
__device__ float g_bdp [DP];                   // padded bd (tails zero)

// ---------------- half hi/lo scratch ----------------
__device__ __half g_kvnh[(size_t)NTOK*CC], g_kvnl[(size_t)NTOK*CC];
__device__ __half g_ctxh[(size_t)NTOK*CC], g_ctxl[(size_t)NTOK*CC];
__device__ __half g_hnh [(size_t)NTOK*CC], g_hnl [(size_t)NTOK*CC];
__device__ __half g_s1h [(size_t)NTOK*2*CC], g_s1l [(size_t)NTOK*2*CC];
__device__ __half g_rNsh[(size_t)NTOK*CC], g_rNsl[(size_t)NTOK*CC];
__device__ __half g_rDh [(size_t)NTOK*DP], g_rDl [(size_t)NTOK*DP];
__device__ __half g_resh[(size_t)NTOK*DP], g_resl[(size_t)NTOK*DP];
__device__ __half g_qDh [(size_t)NTOK*DP], g_qDl [(size_t)NTOK*DP];

__device__ __half g_q0nh[(size_t)M2*CC], g_q0nl[(size_t)M2*CC];
__device__ __half g_c0h [(size_t)M2*CC], g_c0l [(size_t)M2*CC];
__device__ __half g_hn0h[(size_t)M2*CC], g_hn0l[(size_t)M2*CC];
__device__ __half g_g10h[(size_t)M2*2*CC], g_g10l[(size_t)M2*2*CC];
__device__ __half g_rD0h[(size_t)M2*DP], g_rD0l[(size_t)M2*DP];
__device__ __half g_re0h[(size_t)M2*DP], g_re0l[(size_t)M2*DP];
__device__ __half g_qD0h[(size_t)M2*DP], g_qD0l[(size_t)M2*DP];

// split weights [N,K]
__device__ __half g_Wkvh[(size_t)2*CC*CC], g_Wkvl[(size_t)2*CC*CC];
__device__ __half g_Wqh[(size_t)CC*CC], g_Wql[(size_t)CC*CC];
__device__ __half g_Woh[(size_t)CC*CC], g_Wol[(size_t)CC*CC];
__device__ __half g_W1h[(size_t)2*CC*CC], g_W1l[(size_t)2*CC*CC];
__device__ __half g_W2h[(size_t)CC*2*CC], g_W2l[(size_t)CC*2*CC];
__device__ __half g_Wdh[(size_t)DP*CC], g_Wdl[(size_t)DP*CC];   // rows 96..127 zero
__device__ __half g_Wuh[(size_t)CC*DD], g_Wul[(size_t)CC*DD];
__device__ __half g_bkh[(size_t)NBQ*NEQ*DD], g_bkl[(size_t)NBQ*NEQ*DD];

__device__ __forceinline__ uint32_t smem_u32(const void* p) {
    uint32_t a;
    asm("{ .reg .u64 t; cvta.to.shared.u64 t, %1; cvt.u32.u64 %0, t; }" : "=r"(a) : "l"(p));
    return a;
}
__device__ __forceinline__ void mma16816(float* c, const uint32_t* a, const uint32_t* b) {
    asm volatile(
        "mma.sync.aligned.m16n8k16.row.col.f32.f16.f16.f32 "
        "{%0,%1,%2,%3}, {%4,%5,%6,%7}, {%8,%9}, {%0,%1,%2,%3};"
        : "+f"(c[0]), "+f"(c[1]), "+f"(c[2]), "+f"(c[3])
        : "r"(a[0]), "r"(a[1]), "r"(a[2]), "r"(a[3]), "r"(b[0]), "r"(b[1]));
}
__device__ __forceinline__ void ldmat4(uint32_t* r, uint32_t addr) {
    asm volatile("ldmatrix.sync.aligned.m8n8.x4.shared.b16 {%0,%1,%2,%3}, [%4];"
                 : "=r"(r[0]), "=r"(r[1]), "=r"(r[2]), "=r"(r[3]) : "r"(addr));
}
__device__ __forceinline__ void cp16(uint32_t dst, const void* src) {
    asm volatile("cp.async.cg.shared.global [%0], [%1], 16;\n" :: "r"(dst), "l"(src));
}
__device__ __forceinline__ void cpa_commit() { asm volatile("cp.async.commit_group;\n"); }
#define CPA_WAIT2() asm volatile("cp.async.wait_group 2;\n")
__device__ __forceinline__ void cpa_wait0() { asm volatile("cp.async.wait_group 0;\n"); }

// swizzled smem address: 128 rows x 64B, chunk-XOR swizzle
__device__ __forceinline__ uint32_t sw_addr(int row, int q) {
    return (uint32_t)(row * 64 + ((q ^ ((row >> 1) & 3)) << 4));
}

__device__ __forceinline__ float pe_val(int c, int t) {
    int ii = c >> 1;
    float div = expf((float)(2 * ii) * (-9.210340371976184f / (float)CC));
    float ang = (float)t * div;
    return (c & 1) ? cosf(ang) : sinf(ang);
}

// ---------------- split-input 3xFP16 GEMM: 128x128 tile, 128 thr, 3-stage, occ 2 ----
// EPI 0: fp32 (+bias)(+add[rowsel]); EPI 2: gelu(r+bias)->halves;
// EPI 3: argmax keys; EPI 4: fp32 (+bias) AND halves.
#define HP_STAGE 32768
#define HP_SMEM  (3 * HP_STAGE)

template <int EPI>
__global__ __launch_bounds__(128, 2) void hgemmP(
    const __half* __restrict__ Ah, const __half* __restrict__ Al,
    const __half* __restrict__ Bh, const __half* __restrict__ Bl,
    float* __restrict__ Co, __half* __restrict__ Oh, __half* __restrict__ Ol,
    int M, int N, int K, int lda, int ldb,
    const float* __restrict__ bias, const float* __restrict__ add, int addPeriod,
    const float* __restrict__ cn, u64* __restrict__ keys) {
    extern __shared__ char sm[];
    const uint32_t sb = smem_u32(sm);
    const int tid = threadIdx.x;
    const int wid = tid >> 5, lane = tid & 31;
    const int wm = wid >> 1, wn = wid & 1;
    const int bm = blockIdx.y * 128, bn = blockIdx.x * 128;
    const int g = lane >> 2, tg = lane & 3;
    const int nt = K / 32;

    float acc[4][8][4];
#pragma unroll
    for (int i = 0; i < 4; i++)
#pragma unroll
        for (int j = 0; j < 8; j++)
#pragma unroll
            for (int q = 0; q < 4; q++) acc[i][j][q] = 0.f;

    const int lrow = (lane & 7) + ((lane >> 3) & 1) * 8;
    const int lq   = (lane >> 4) & 1;
    const int brow = (lane & 7) + ((lane >> 4) ? 8 : 0);
    const int bq   = (lane >> 3) & 1;

#define HP_LOAD(T) do {                                                         \
    int _t = (T);                                                               \
    if (_t < nt) {                                                              \
        uint32_t d0 = sb + (_t % 3) * HP_STAGE;                                 \
        _Pragma("unroll")                                                       \
        for (int j = 0; j < 16; j++) {                                          \
            int c = tid + j * 128;                                              \
            int mat = c >> 9;                                                   \
            int cc = c & 511;                                                   \
            int row = cc >> 2, q = cc & 3;                                      \
            const __half* src;                                                  \
            if (mat == 0)      src = Ah + (size_t)(bm + row) * lda + _t * 32 + q * 8; \
            else if (mat == 1) src = Al + (size_t)(bm + row) * lda + _t * 32 + q * 8; \
            else if (mat == 2) src = Bh + (size_t)(bn + row) * ldb + _t * 32 + q * 8; \
            else               src = Bl + (size_t)(bn + row) * ldb + _t * 32 + q * 8; \
            cp16(d0 + mat * 8192 + sw_addr(row, q), src);                       \
        }                                                                       \
    }                                                                           \
    cpa_commit();                                                               \
} while (0)

    HP_LOAD(0);
    HP_LOAD(1);
    HP_LOAD(2);

    for (int t = 0; t < nt; t++) {
        CPA_WAIT2();
        __syncthreads();
        const uint32_t tb = sb + (t % 3) * HP_STAGE;
#pragma unroll
        for (int ks = 0; ks < 2; ks++) {
            uint32_t ah[4][4], al[4][4];
#pragma unroll
            for (int mt = 0; mt < 4; mt++) {
                int row = wm * 64 + mt * 16 + lrow;
                uint32_t ad = tb + sw_addr(row, ks * 2 + lq);
                ldmat4(ah[mt], ad);
                ldmat4(al[mt], ad + 8192);
            }
            uint32_t bf[4][4];
#pragma unroll
            for (int p = 0; p < 4; p++) {
                int row = wn * 64 + p * 16 + brow;
                uint32_t bd = tb + 16384 + sw_addr(row, ks * 2 + bq);
                ldmat4(bf[p], bd);
            }
#pragma unroll
            for (int mt = 0; mt < 4; mt++)
#pragma unroll
                for (int p = 0; p < 4; p++) {
                    mma16816(acc[mt][2 * p],     ah[mt], &bf[p][0]);
                    mma16816(acc[mt][2 * p + 1], ah[mt], &bf[p][2]);
                    mma16816(acc[mt][2 * p],     al[mt], &bf[p][0]);
                    mma16816(acc[mt][2 * p + 1], al[mt], &bf[p][2]);
                }
#pragma unroll
            for (int p = 0; p < 4; p++) {
                int row = wn * 64 + p * 16 + brow;
                uint32_t bd = tb + 24576 + sw_addr(row, ks * 2 + bq);
                ldmat4(bf[p], bd);
            }
#pragma unroll
            for (int mt = 0; mt < 4; mt++)
#pragma unroll
                for (int p = 0; p < 4; p++) {
                    mma16816(acc[mt][2 * p],     ah[mt], &bf[p][0]);
                    mma16816(acc[mt][2 * p + 1], ah[mt], &bf[p][2]);
                }
        }
        __syncthreads();
        HP_LOAD(t + 3);
    }
#undef HP_LOAD

    if (EPI == 3) {
#pragma unroll
        for (int mt = 0; mt < 4; mt++) {
            int m0 = bm + wm * 64 + mt * 16 + g;
            int m1 = m0 + 8;
            u64 b0 = 0ull, b1 = 0ull;
#pragma unroll
            for (int nb = 0; nb < 8; nb++) {
                int n0 = bn + wn * 64 + nb * 8 + tg * 2;
                float s00 = acc[mt][nb][0] - cn[n0];
                float s01 = acc[mt][nb][1] - cn[n0 + 1];
                float s10 = acc[mt][nb][2] - cn[n0];
                float s11 = acc[mt][nb][3] - cn[n0 + 1];
                unsigned u;
                u = __float_as_uint(s00); u = (u & 0x80000000u) ? ~u : (u | 0x80000000u);
                u64 k = ((u64)u << 32) | (unsigned)(~n0);
                if (k > b0) b0 = k;
                u = __float_as_uint(s01); u = (u & 0x80000000u) ? ~u : (u | 0x80000000u);
                k = ((u64)u << 32) | (unsigned)(~(n0 + 1));
                if (k > b0) b0 = k;
                u = __float_as_uint(s10); u = (u & 0x80000000u) ? ~u : (u | 0x80000000u);
                k = ((u64)u << 32) | (unsigned)(~n0);
                if (k > b1) b1 = k;
                u = __float_as_uint(s11); u = (u & 0x80000000u) ? ~u : (u | 0x80000000u);
                k = ((u64)u << 32) | (unsigned)(~(n0 + 1));
                if (k > b1) b1 = k;
            }
#pragma unroll
            for (int o = 1; o < 4; o <<= 1) {
                u64 t0 = __shfl_xor_sync(0xffffffffu, b0, o);
                u64 t1 = __shfl_xor_sync(0xffffffffu, b1, o);
                if (t0 > b0) b0 = t0;
                if (t1 > b1) b1 = t1;
            }
            if (tg == 0) {
                atomicMax(&keys[m0], b0);
                atomicMax(&keys[m1], b1);
            }
        }
    } else {
#pragma unroll
        for (int mt = 0; mt < 4; mt++) {
            int m0 = bm + wm * 64 + mt * 16 + g;
            int m1 = m0 + 8;
            const float* add0 = (EPI == 0 && add)
                ? add + (size_t)((addPeriod > 0) ? (m0 % addPeriod) : m0) * N : nullptr;
            const float* add1 = (EPI == 0 && add)
                ? add + (size_t)((addPeriod > 0) ? (m1 % addPeriod) : m1) * N : nullptr;
#pragma unroll
            for (int nb = 0; nb < 8; nb++) {
                int n0 = bn + wn * 64 + nb * 8 + tg * 2;
                float v0 = acc[mt][nb][0], v1 = acc[mt][nb][1];
                float v2 = acc[mt][nb][2], v3 = acc[mt][nb][3];
                if (bias) {
                    float c0 = bias[n0], c1 = bias[n0 + 1];
                    v0 += c0; v1 += c1; v2 += c0; v3 += c1;
                }
                if (EPI == 0) {
                    if (add0) { v0 += add0[n0]; v1 += add0[n0 + 1]; }
                    if (add1) { v2 += add1[n0]; v3 += add1[n0 + 1]; }
                    *(float2*)(Co + (size_t)m0 * N + n0) = make_float2(v0, v1);
                    *(float2*)(Co + (size_t)m1 * N + n0) = make_float2(v2, v3);
                } else if (EPI == 4) {
                    *(float2*)(Co + (size_t)m0 * N + n0) = make_float2(v0, v1);
                    *(float2*)(Co + (size_t)m1 * N + n0) = make_float2(v2, v3);
                    __half2 h0 = __floats2half2_rn(v0, v1);
                    float2 f0 = __half22float2(h0);
                    __half2 l0 = __floats2half2_rn(v0 - f0.x, v1 - f0.y);
                    __half2 h1 = __floats2half2_rn(v2, v3);
                    float2 f1 = __half22float2(h1);
                    __half2 l1 = __floats2half2_rn(v2 - f1.x, v3 - f1.y);
                    *(__half2*)(Oh + (size_t)m0 * N + n0) = h0;
                    *(__half2*)(Ol + (size_t)m0 * N + n0) = l0;
                    *(__half2*)(Oh + (size_t)m1 * N + n0) = h1;
                    *(__half2*)(Ol + (size_t)m1 * N + n0) = l1;
                } else {  // EPI == 2: gelu -> halves
                    v0 = 0.5f * v0 * (1.0f + erff(v0 * 0.70710678118654752f));
                    v1 = 0.5f * v1 * (1.0f + erff(v1 * 0.70710678118654752f));
                    v2 = 0.5f * v2 * (1.0f + erff(v2 * 0.70710678118654752f));
                    v3 = 0.5f * v3 * (1.0f + erff(v3 * 0.70710678118654752f));
                    __half2 h0 = __floats2half2_rn(v0, v1);
                    float2 f0 = __half22float2(h0);
                    __half2 l0 = __floats2half2_rn(v0 - f0.x, v1 - f0.y);
                    __half2 h1 = __floats2half2_rn(v2, v3);
                    float2 f1 = __half22float2(h1);
                    __half2 l1 = __floats2half2_rn(v2 - f1.x, v3 - f1.y);
                    *(__half2*)(Oh + (size_t)m0 * N + n0) = h0;
                    *(__half2*)(Ol + (size_t)m0 * N + n0) = l0;
                    *(__half2*)(Oh + (size_t)m1 * N + n0) = h1;
                    *(__half2*)(Ol + (size_t)m1 * N + n0) = l1;
                }
            }
        }
    }
}

// ---------------- setup kernels ----------------
__global__ void prep_books(const float* __restrict__ books, float* __restrict__ cn,
                           __half* __restrict__ bh, __half* __restrict__ bl) {
    int i = blockIdx.x * 256 + threadIdx.x;
    if (i >= NBQ * NEQ) return;
    const float* src = books + (size_t)i * DD;
    float s = 0.f;
    for (int d = 0; d < DD; d++) {
        float v = src[d];
        s += v * v;
        __half h = __float2half_rn(v);
        bh[(size_t)i * DD + d] = h;
        bl[(size_t)i * DD + d] = __float2half_rn(v - __half2float(h));
    }
    cn[i] = 0.5f * s;
}

__global__ void prep_bd(const float* __restrict__ bd, float* __restrict__ bdp) {
    int i = threadIdx.x;
    bdp[i] = (i < DD) ? bd[i] : 0.0f;
}

__global__ void split_f32(const float* __restrict__ src, __half* __restrict__ h,
                          __half* __restrict__ l, int n) {
    int i = blockIdx.x * 256 + threadIdx.x;
    if (i >= n) return;
    float v = src[i];
    __half hi = __float2half_rn(v);
    h[i] = hi;
    l[i] = __float2half_rn(v - __half2float(hi));
}

// ---------------- transposes ----------------
__global__ void transpose_ct_to_tc(const float* __restrict__ in, float* __restrict__ out,
                                   int Cdim, int Tdim) {
    __shared__ float tile[32][33];
    int b = blockIdx.z;
    int c0 = blockIdx.y * 32, t0 = blockIdx.x * 32;
    int x = threadIdx.x, y = threadIdx.y;
    for (int i = 0; i < 32; i += 8)
        tile[y + i][x] = in[((size_t)b * Cdim + c0 + y + i) * Tdim + t0 + x];
    __syncthreads();
    for (int i = 0; i < 32; i += 8)
        out[((size_t)b * Tdim + t0 + y + i) * Cdim + c0 + x] = tile[x][y + i];
}

__global__ void transpose_split2(const float* __restrict__ inA, __half* __restrict__ ohA,
                                 __half* __restrict__ olA,
                                 const float* __restrict__ inB, __half* __restrict__ ohB,
                                 __half* __restrict__ olB, int Cdim, int Tdim) {
    __shared__ float tile[32][33];
    int which = blockIdx.z;
    const float* in = which ? inB : inA;
    __half* oh = which ? ohB : ohA;
    __half* ol = which ? olB : olA;
    int c0 = blockIdx.y * 32, t0 = blockIdx.x * 32;
    int x = threadIdx.x, y = threadIdx.y;
    for (int i = 0; i < 32; i += 8)
        tile[y + i][x] = in[(size_t)(c0 + y + i) * Tdim + t0 + x];
    __syncthreads();
    for (int i = 0; i < 32; i += 8) {
        float v = tile[x][y + i];
        __half h = __float2half_rn(v);
        size_t o = (size_t)(t0 + y + i) * Cdim + c0 + x;
        oh[o] = h;
        ol[o] = __float2half_rn(v - __half2float(h));
    }
}

// srcLd: row stride of token-major input (>= Cdim)
template <int NANFIX>
__global__ void transpose_tc_to_ct(const float* __restrict__ in, float* __restrict__ out,
                                   int Cdim, int Tdim, int srcLd) {
    __shared__ float tile[32][33];
    int b = blockIdx.z;
    int c0 = blockIdx.y * 32, t0 = blockIdx.x * 32;
    int x = threadIdx.x, y = threadIdx.y;
    for (int i = 0; i < 32; i += 8)
        tile[y + i][x] = in[((size_t)b * Tdim + t0 + y + i) * srcLd + c0 + x];
    __syncthreads();
    for (int i = 0; i < 32; i += 8) {
        float v = tile[x][y + i];
        if (NANFIX) { if (!isfinite(v)) v = 0.0f; }
        out[((size_t)b * Cdim + c0 + y + i) * Tdim + t0 + x] = v;
    }
}

// ---------------- LayerNorm ----------------
// SRC 0: in0 row m; 1: carry (row m*16-1 of in0, zero if m%128==0); 2: gather (row m*16)
template <int POST, int SPLIT, int PE, int SRC>
__global__ __launch_bounds__(256) void ln_kernel(
    const float* __restrict__ in0, const float* __restrict__ in1,
    const float* __restrict__ gamma, const float* __restrict__ beta,
    const float* __restrict__ scale_ptr, float* __restrict__ out,
    __half* __restrict__ oh, __half* __restrict__ ol, int Mrows) {
    int m = blockIdx.x;
    if (m >= Mrows) return;
    int tid = threadIdx.x;
    int lane = tid & 31, warp = tid >> 5;
    __shared__ float red[8];
    float x[4];
#pragma unroll
    for (int k = 0; k < 4; k++) {
        int c = tid + k * 256;
        float v;
        if (SRC == 1) {
            v = (m & (NCHK - 1)) ? in0[((size_t)m * 16 - 1) * CC + c] : 0.0f;
        } else if (SRC == 2) {
            v = in0[((size_t)m * 16) * CC + c];
        } else {
            v = in0 ? in0[(size_t)m * CC + c] : 0.0f;
        }
        if (in1) v -= in1[(size_t)m * CC + c];
        if (PE == 1) v += pe_val(c, m & 15);
        else if (PE == 2) v += pe_val(c, 0);
        x[k] = v;
    }
    float s = x[0] + x[1] + x[2] + x[3];
#pragma unroll
    for (int o = 16; o; o >>= 1) s += __shfl_xor_sync(0xffffffffu, s, o);
    if (lane == 0) red[warp] = s;
    __syncthreads();
    float mean;
    {
        float t = (lane < 8) ? red[lane] : 0.f;
#pragma unroll
        for (int o = 4; o; o >>= 1) t += __shfl_xor_sync(0xffffffffu, t, o);
        mean = __shfl_sync(0xffffffffu, t, 0) * (1.0f / (float)CC);
    }
    float vs = 0.f;
#pragma unroll
    for (int k = 0; k < 4; k++) { float d = x[k] - mean; vs += d * d; }
#pragma unroll
    for (int o = 16; o; o >>= 1) vs += __shfl_xor_sync(0xffffffffu, vs, o);
    __syncthreads();
    if (lane == 0) red[warp] = vs;
    __syncthreads();
    float var;
    {
        float t = (lane < 8) ? red[lane] : 0.f;
#pragma unroll
        for (int o = 4; o; o >>= 1) t += __shfl_xor_sync(0xffffffffu, t, o);
        var = __shfl_sync(0xffffffffu, t, 0) * (1.0f / (float)CC);
    }
    float rstd = rsqrtf(var + 1e-5f);
    float sc = 1.0f;
    if (POST == 1) {
        float t = scale_ptr[0];
        sc = fminf(fmaxf(t, 0.005f), 0.5f);
    }
#pragma unroll
    for (int k = 0; k < 4; k++) {
        int c = tid + k * 256;
        float yv = (x[k] - mean) * rstd * gamma[c] + beta[c];
        if (POST == 1) yv = tanhf(yv) * sc;
        if (SPLIT != 1) out[(size_t)m * CC + c] = yv;
        if (SPLIT >= 1) {
            __half h = __float2half_rn(yv);
            oh[(size_t)m * CC + c] = h;
            ol[(size_t)m * CC + c] = __float2half_rn(yv - __half2float(h));
        }
    }
}

// ---------------- f32x2 helpers (scalar GEMM for tiny Qc) ----------------
__device__ __forceinline__ u64 pack2(float x) {
    u64 r;
    asm("mov.b64 %0, {%1, %1};" : "=l"(r) : "f"(x));
    return r;
}
__device__ __forceinline__ float2 unpack2(u64 v) {
    float2 f;
    asm("mov.b64 {%0, %1}, %2;" : "=f"(f.x), "=f"(f.y) : "l"(v));
    return f;
}
#define FFMA2(d, a, b) asm("fma.rn.f32x2 %0, %1, %2, %0;" : "+l"(d) : "l"(a), "l"(b))

__device__ __forceinline__ void cpa16p(void* dst, const void* src, bool pred) {
    unsigned int d = (unsigned int)__cvta_generic_to_shared(dst);
    int sz = pred ? 16 : 0;
    asm volatile("cp.async.ca.shared.global [%0], [%1], 16, %2;\n" :: "r"(d), "l"(src), "r"(sz));
}

template <bool GUARD>
__global__ __launch_bounds__(256, 2) void sgemm2(
    const float* __restrict__ A, const float* __restrict__ Bm, float* __restrict__ Co,
    int M, int N, int K, const float* __restrict__ bias) {
    __shared__ __align__(16) float As[2][16][128];
    __shared__ __align__(16) float Bs[2][16][128];
    const int tid = threadIdx.x;
    const int bm = blockIdx.y * 128, bn = blockIdx.x * 128;
    const int tx = tid & 15, ty = tid >> 4;

    const int a_row  = tid >> 1;
    const int a_koff = (tid & 1) * 8;
    const int b_row  = tid >> 5;
    const int b_col  = (tid & 31) * 4;

    const bool a_ok = !GUARD || (bm + a_row < M);
    const bool b_ok = !GUARD || (bn + b_col < N);
    const float* a_src0 = A + (size_t)(GUARD ? (a_ok ? bm + a_row : 0) : (bm + a_row)) * K + a_koff;
    const float* b_src0 = Bm + (size_t)b_row * N + (GUARD ? (b_ok ? bn + b_col : 0) : (bn + b_col));
    const float* b_src1 = b_src0 + (size_t)8 * N;

    u64 acc2[8][4];
#pragma unroll
    for (int i = 0; i < 8; i++)
#pragma unroll
        for (int q = 0; q < 4; q++) acc2[i][q] = 0ull;

    float a_reg[8];
    const int nt = K / 16;

    {
        if (a_ok) {
            float4 v0 = *(const float4*)(a_src0);
            float4 v1 = *(const float4*)(a_src0 + 4);
            a_reg[0]=v0.x; a_reg[1]=v0.y; a_reg[2]=v0.z; a_reg[3]=v0.w;
            a_reg[4]=v1.x; a_reg[5]=v1.y; a_reg[6]=v1.z; a_reg[7]=v1.w;
        } else {
#pragma unroll
            for (int c = 0; c < 8; c++) a_reg[c] = 0.f;
        }
        cpa16p(&Bs[0][b_row][b_col],     b_src0, b_ok);
        cpa16p(&Bs[0][8 + b_row][b_col], b_src1, b_ok);
        cpa_commit();
#pragma unroll
        for (int c = 0; c < 8; c++) As[0][a_koff + c][a_row] = a_reg[c];
        cpa_wait0();
        __syncthreads();
    }

    int buf = 0;
    for (int t = 0; t < nt; t++) {
        const bool has_next = (t + 1 < nt);
        if (has_next) {
            const float* ap = a_src0 + (size_t)(t + 1) * 16;
            if (a_ok) {
                float4 v0 = *(const float4*)(ap);
                float4 v1 = *(const float4*)(ap + 4);
                a_reg[0]=v0.x; a_reg[1]=v0.y; a_reg[2]=v0.z; a_reg[3]=v0.w;
                a_reg[4]=v1.x; a_reg[5]=v1.y; a_reg[6]=v1.z; a_reg[7]=v1.w;
            }
            cpa16p(&Bs[buf ^ 1][b_row][b_col],     b_src0 + (size_t)(t + 1) * 16 * N, b_ok);
            cpa16p(&Bs[buf ^ 1][8 + b_row][b_col], b_src1 + (size_t)(t + 1) * 16 * N, b_ok);
            cpa_commit();
        }
#pragma unroll
        for (int kk = 0; kk < 16; kk++) {
            float4 a0 = *(const float4*)&As[buf][kk][ty * 8];
            float4 a1 = *(const float4*)&As[buf][kk][ty * 8 + 4];
            ulonglong2 bl = *(const ulonglong2*)&Bs[buf][kk][tx * 4];
            ulonglong2 bh = *(const ulonglong2*)&Bs[buf][kk][64 + tx * 4];
            float am[8] = {a0.x, a0.y, a0.z, a0.w, a1.x, a1.y, a1.z, a1.w};
#pragma unroll
            for (int i = 0; i < 8; i++) {
                u64 ai = pack2(am[i]);
                FFMA2(acc2[i][0], ai, bl.x);
                FFMA2(acc2[i][1], ai, bl.y);
                FFMA2(acc2[i][2], ai, bh.x);
                FFMA2(acc2[i][3], ai, bh.y);
            }
        }
        if (has_next) {
#pragma unroll
            for (int c = 0; c < 8; c++) As[buf ^ 1][a_koff + c][a_row] = a_reg[c];
            cpa_wait0();
            __syncthreads();
            buf ^= 1;
        }
    }

#pragma unroll
    for (int i = 0; i < 8; i++) {
        int m = bm + ty * 8 + i;
        if (GUARD && m >= M) continue;
#pragma unroll
        for (int q = 0; q < 4; q++) {
            float2 v2 = unpack2(acc2[i][q]);
            int n0 = bn + ((q < 2) ? (tx * 4 + q * 2) : (64 + tx * 4 + (q - 2) * 2));
#pragma unroll
            for (int h = 0; h < 2; h++) {
                int n = n0 + h;
                if (GUARD && n >= N) continue;
                float v = h ? v2.y : v2.x;
                if (bias) v += bias[n];
                Co[(size_t)m * N + n] = v;
            }
        }
    }
}

// ---------------- attention ----------------
__global__ __launch_bounds__(256) void attn_a(const float* __restrict__ KVb,
                                              const float* __restrict__ Qc,
                                              __half* __restrict__ ctxh,
                                              __half* __restrict__ ctxl) {
    int gb = blockIdx.x;
    int h = blockIdx.y;
    int tid = threadIdx.x;
    __shared__ float Ks[16][133], Vs[16][133], Qs[16][133];
    __shared__ float Ss[16][17];
    for (int i = tid; i < 16 * DH; i += 256) {
        int t = i >> 7, d = i & 127;
        size_t base = ((size_t)(gb * 16 + t)) * (2 * CC) + (size_t)h * DH + d;
        Ks[t][d] = KVb[base];
        Vs[t][d] = KVb[base + CC];
        Qs[t][d] = Qc[(size_t)t * CC + (size_t)h * DH + d];
    }
    __syncthreads();
    {
        int q = tid >> 4, k = tid & 15;
        float s = 0.f;
#pragma unroll 8
        for (int d = 0; d < DH; d++) s = fmaf(Qs[q][d], Ks[k][d], s);
        Ss[q][k] = s * 0.08838834764831845f;
    }
    __syncthreads();
    if (tid < 16) {
        float mx = -1e30f;
        for (int k = 0; k < 16; k++) mx = fmaxf(mx, Ss[tid][k]);
        float e[16], sum = 0.f;
        for (int k = 0; k < 16; k++) { e[k] = expf(Ss[tid][k] - mx); sum += e[k]; }
        float inv = 1.0f / sum;
        for (int k = 0; k < 16; k++) Ss[tid][k] = e[k] * inv;
    }
    __syncthreads();
    for (int i = tid; i < 16 * DH; i += 256) {
        int t = i >> 7, d = i & 127;
        float a = 0.f;
#pragma unroll
        for (int k = 0; k < 16; k++) a = fmaf(Ss[t][k], Vs[k][d], a);
        size_t o = ((size_t)(gb * 16 + t)) * CC + (size_t)h * DH + d;
        __half hh = __float2half_rn(a);
        ctxh[o] = hh;
        ctxl[o] = __float2half_rn(a - __half2float(hh));
    }
}

__global__ __launch_bounds__(128) void attn_b(const float* __restrict__ KVb,
                                              const float* __restrict__ Q0,
                                              __half* __restrict__ ctxh,
                                              __half* __restrict__ ctxl) {
    int p = blockIdx.x;
    int h = blockIdx.y;
    int tid = threadIdx.x;
    __shared__ float Ks[16][128], Vs[16][128], Qs[128];
    __shared__ float sc[16];
    for (int i = tid; i < 16 * DH; i += 128) {
        int t = i >> 7, d = i & 127;
        size_t base = ((size_t)(p * 16 + t)) * (2 * CC) + (size_t)h * DH + d;
        Ks[t][d] = KVb[base];
        Vs[t][d] = KVb[base + CC];
    }
    Qs[tid] = Q0[(size_t)p * CC + (size_t)h * DH + tid];
    __syncthreads();
    int w = tid >> 5, l = tid & 31;
    for (int k = w; k < 16; k += 4) {
        float s = Qs[l] * Ks[k][l] + Qs[l + 32] * Ks[k][l + 32] +
                  Qs[l + 64] * Ks[k][l + 64] + Qs[l + 96] * Ks[k][l + 96];
        for (int o = 16; o; o >>= 1) s += __shfl_xor_sync(0xffffffffu, s, o);
        if (l == 0) sc[k] = s * 0.08838834764831845f;
    }
    __syncthreads();
    if (tid == 0) {
        float mx = -1e30f;
        for (int k = 0; k < 16; k++) mx = fmaxf(mx, sc[k]);
        float e[16], sum = 0.f;
        for (int k = 0; k < 16; k++) { e[k] = expf(sc[k] - mx); sum += e[k]; }
        float inv = 1.0f / sum;
        for (int k = 0; k < 16; k++) sc[k] = e[k] * inv;
    }
    __syncthreads();
    float a = 0.f;
#pragma unroll
    for (int k = 0; k < 16; k++) a = fmaf(sc[k], Vs[k][tid], a);
    size_t o = (size_t)p * CC + (size_t)h * DH + tid;
    __half hh = __float2half_rn(a);
    ctxh[o] = hh;
    ctxl[o] = __float2half_rn(a - __half2float(hh));
}

// ---------------- RVQ update (padded stride DP; resets keys) ----------------
__global__ void rvq_update3(u64* __restrict__ keys,
                            const float* __restrict__ books_st,
                            const float* __restrict__ resid_in,
                            float* __restrict__ resid_out,
                            __half* __restrict__ resh, __half* __restrict__ resl,
                            float* __restrict__ qD,
                            __half* __restrict__ qDh, __half* __restrict__ qDl,
                            int firstStage, int lastStage) {
    int m = blockIdx.x;
    int d = threadIdx.x;   // 96 threads
    int idx = (int)(~(unsigned)(keys[m] & 0xffffffffu)) & (NEQ - 1);
    __syncthreads();
    if (d == 0) keys[m] = 0ull;
    float e = books_st[(size_t)idx * DD + d];
    float r = resid_in[(size_t)m * DP + d];
    float nr = r - e;
    resid_out[(size_t)m * DP + d] = nr;
    __half hh = __float2half_rn(nr);
    resh[(size_t)m * DP + d] = hh;
    resl[(size_t)m * DP + d] = __float2half_rn(nr - __half2float(hh));
    float q = firstStage ? e : (qD[(size_t)m * DP + d] + e);
    qD[(size_t)m * DP + d] = q;
    if (lastStage) {
        __half qh = __float2half_rn(q);
        qDh[(size_t)m * DP + d] = qh;
        qDl[(size_t)m * DP + d] = __float2half_rn(q - __half2float(qh));
    }
}

// ---------------- misc ----------------
__global__ void scatter_rows16(const float* __restrict__ in, float* __restrict__ out,
                               int count, int ld) {
    int p = blockIdx.x;
    for (int c = threadIdx.x; c < count; c += blockDim.x)
        out[((size_t)p * 16) * ld + c] = in[(size_t)p * ld + c];
}

// ---------------- host ----------------
static inline dim3 gemm_grid(int M, int N) { return dim3((N + 127) / 128, (M + 127) / 128); }
static inline dim3 hp_grid(int M, int N) { return dim3(N / 128, M / 128); }

extern "C" void kernel_launch(void* const* d_in, const int* in_sizes, int n_in,
                              void* d_out, int out_size) {
    const float* qa     = (const float*)d_in[0];
    const float* ztt    = (const float*)d_in[1];
    const float* ln_q_g = (const float*)d_in[2];
    const float* ln_q_b = (const float*)d_in[3];
    const float* ln_kv_g= (const float*)d_in[4];
    const float* ln_kv_b= (const float*)d_in[5];
    const float* Wq     = (const float*)d_in[6];
    const float* Wk     = (const float*)d_in[7];
    const float* Wv     = (const float*)d_in[8];
    const float* Wo     = (const float*)d_in[9];
    const float* ffg    = (const float*)d_in[10];
    const float* ffb    = (const float*)d_in[11];
    const float* W1     = (const float*)d_in[12];
    const float* b1     = (const float*)d_in[13];
    const float* W2     = (const float*)d_in[14];
    const float* b2     = (const float*)d_in[15];
    const float* tng    = (const float*)d_in[16];
    const float* tnb    = (const float*)d_in[17];
    const float* scale  = (const float*)d_in[18];
    const float* Wd     = (const float*)d_in[19];
    const float* bd     = (const float*)d_in[20];
    const float* Wu     = (const float*)d_in[21];
    const float* bu     = (const float*)d_in[22];
    const float* books  = (const float*)d_in[23];

    float* out = (float*)d_out;
    float* o_y = out;
    float* o_r = out + (size_t)BB * CC * TT;

#define SYMF(p, s) float* p; cudaGetSymbolAddress((void**)&p, s)
#define SYMH(p, s) __half* p; cudaGetSymbolAddress((void**)&p, s)
    SYMF(p_qat, g_qat); SYMF(p_ztt, g_ztt);
    SYMF(p_KVb, g_KVb);
    SYMF(p_y, g_y);     SYMF(p_zp, g_zp);   SYMF(p_zh, g_zh);
    SYMF(p_rD, g_rD);   SYMF(p_res, g_res); SYMF(p_qDv, g_qDv);
    SYMF(p_q0n, g_q0n); SYMF(p_Q0, g_Q0);
    SYMF(p_y0, g_y0);   SYMF(p_z0, g_z0);
    SYMF(p_zh0, g_zh0);
    SYMF(p_rD0, g_rD0); SYMF(p_res0, g_res0); SYMF(p_qD0, g_qD0);
    SYMF(p_qc, g_qc);   SYMF(p_Qc, g_Qc);
    SYMF(p_cn, g_cn);   SYMF(p_bdp, g_bdp);
    SYMH(p_kvnh, g_kvnh); SYMH(p_kvnl, g_kvnl);
    SYMH(p_ctxh, g_ctxh); SYMH(p_ctxl, g_ctxl);
    SYMH(p_hnh, g_hnh);   SYMH(p_hnl, g_hnl);
    SYMH(p_s1h, g_s1h);   SYMH(p_s1l, g_s1l);
    SYMH(p_rNsh, g_rNsh); SYMH(p_rNsl, g_rNsl);
    SYMH(p_rDh, g_rDh);   SYMH(p_rDl, g_rDl);
    SYMH(p_resh, g_resh); SYMH(p_resl, g_resl);
    SYMH(p_qDh, g_qDh);   SYMH(p_qDl, g_qDl);
    SYMH(p_q0nh, g_q0nh); SYMH(p_q0nl, g_q0nl);
    SYMH(p_c0h, g_c0h);   SYMH(p_c0l, g_c0l);
    SYMH(p_hn0h, g_hn0h); SYMH(p_hn0l, g_hn0l);
    SYMH(p_g10h, g_g10h); SYMH(p_g10l, g_g10l);
    SYMH(p_rD0h, g_rD0h); SYMH(p_rD0l, g_rD0l);
    SYMH(p_re0h, g_re0h); SYMH(p_re0l, g_re0l);
    SYMH(p_qD0h, g_qD0h); SYMH(p_qD0l, g_qD0l);
    SYMH(p_Wkvh, g_Wkvh); SYMH(p_Wkvl, g_Wkvl);
    SYMH(p_Wqh, g_Wqh); SYMH(p_Wql, g_Wql);
    SYMH(p_Woh, g_Woh); SYMH(p_Wol, g_Wol);
    SYMH(p_W1h, g_W1h); SYMH(p_W1l, g_W1l);
    SYMH(p_W2h, g_W2h); SYMH(p_W2l, g_W2l);
    SYMH(p_Wdh, g_Wdh); SYMH(p_Wdl, g_Wdl);
    SYMH(p_Wuh, g_Wuh); SYMH(p_Wul, g_Wul);
    SYMH(p_bkh, g_bkh); SYMH(p_bkl, g_bkl);
#undef SYMF
#undef SYMH
    u64* p_keys; cudaGetSymbolAddress((void**)&p_keys, g_keys);

    cudaFuncSetAttribute(hgemmP<0>, cudaFuncAttributeMaxDynamicSharedMemorySize, HP_SMEM);
    cudaFuncSetAttribute(hgemmP<2>, cudaFuncAttributeMaxDynamicSharedMemorySize, HP_SMEM);
    cudaFuncSetAttribute(hgemmP<3>, cudaFuncAttributeMaxDynamicSharedMemorySize, HP_SMEM);
    cudaFuncSetAttribute(hgemmP<4>, cudaFuncAttributeMaxDynamicSharedMemorySize, HP_SMEM);

    // ---- launches 1-3 setup; 4 = merged KV GEMM (ncu slot) ----
    transpose_ct_to_tc<<<dim3(TT / 32, CC / 32, BB), dim3(32, 8)>>>(qa, p_qat, CC, TT); // 1
    ln_kernel<0, 1, 1, 0><<<NTOK, 256>>>(p_qat, nullptr, ln_kv_g, ln_kv_b, nullptr,
                                         nullptr, p_kvnh, p_kvnl, NTOK);                // 2
    transpose_split2<<<dim3(32, 32, 2), dim3(32, 8)>>>(Wk, p_Wkvh, p_Wkvl,
                                                       Wv, p_Wkvh + (size_t)CC * CC,
                                                       p_Wkvl + (size_t)CC * CC, CC, CC); // 3
    hgemmP<0><<<hp_grid(NTOK, 2 * CC), 128, HP_SMEM>>>(p_kvnh, p_kvnl, p_Wkvh, p_Wkvl,
        p_KVb, nullptr, nullptr, NTOK, 2 * CC, CC, CC, CC,
        nullptr, nullptr, 0, nullptr, nullptr);                                          // 4

    // ---- remaining setup ----
    transpose_ct_to_tc<<<dim3(TT / 32, CC / 32, BB), dim3(32, 8)>>>(ztt, p_ztt, CC, TT);
    prep_books<<<(NBQ * NEQ + 255) / 256, 256>>>(books, p_cn, p_bkh, p_bkl);
    prep_bd<<<1, DP>>>(bd, p_bdp);
    transpose_split2<<<dim3(32, 32, 2), dim3(32, 8)>>>(Wq, p_Wqh, p_Wql,
                                                       Wo, p_Woh, p_Wol, CC, CC);
    transpose_split2<<<dim3(64, 32, 1), dim3(32, 8)>>>(W1, p_W1h, p_W1l,
                                                       nullptr, nullptr, nullptr, CC, 2 * CC);
    transpose_split2<<<dim3(32, 64, 1), dim3(32, 8)>>>(W2, p_W2h, p_W2l,
                                                       nullptr, nullptr, nullptr, 2 * CC, CC);
    split_f32<<<(DD * CC + 255) / 256, 256>>>(Wd, p_Wdh, p_Wdl, DD * CC);   // rows 96..127 stay 0
    split_f32<<<(CC * DD + 255) / 256, 256>>>(Wu, p_Wuh, p_Wul, CC * DD);
    ln_kernel<0, 0, 1, 0><<<CHK, 256>>>(nullptr, nullptr, ln_q_g, ln_q_b, nullptr,
                                        p_qc, nullptr, nullptr, CHK);
    sgemm2<true><<<gemm_grid(CHK, CC), 256>>>(p_qc, Wq, p_Qc, CHK, CC, CC, nullptr);
    cudaMemsetAsync(p_keys, 0, (size_t)NTOK * sizeof(u64), 0);

    // ---- pass A ----
    attn_a<<<dim3(M2, HH), 256>>>(p_KVb, p_Qc, p_ctxh, p_ctxl);
    hgemmP<0><<<hp_grid(NTOK, CC), 128, HP_SMEM>>>(p_ctxh, p_ctxl, p_Woh, p_Wol,
        p_y, nullptr, nullptr, NTOK, CC, CC, CC, CC, nullptr, p_qc, CHK, nullptr, nullptr);
    ln_kernel<0, 1, 0, 0><<<NTOK, 256>>>(p_y, nullptr, ffg, ffb, nullptr,
                                         nullptr, p_hnh, p_hnl, NTOK);
    hgemmP<2><<<hp_grid(NTOK, 2 * CC), 128, HP_SMEM>>>(p_hnh, p_hnl, p_W1h, p_W1l,
        nullptr, p_s1h, p_s1l, NTOK, 2 * CC, CC, CC, CC, b1, nullptr, 0, nullptr, nullptr);
    hgemmP<0><<<hp_grid(NTOK, CC), 128, HP_SMEM>>>(p_s1h, p_s1l, p_W2h, p_W2l,
        p_zp, nullptr, nullptr, NTOK, CC, 2 * CC, 2 * CC, 2 * CC, b2, p_y, 0, nullptr, nullptr);
    ln_kernel<1, 1, 0, 0><<<NTOK, 256>>>(p_ztt, p_zp, tng, tnb, scale,
                                         nullptr, p_rNsh, p_rNsl, NTOK);
    hgemmP<4><<<hp_grid(NTOK, DP), 128, HP_SMEM>>>(p_rNsh, p_rNsl, p_Wdh, p_Wdl,
        p_rD, p_rDh, p_rDl, NTOK, DP, CC, CC, CC, p_bdp, nullptr, 0, nullptr, nullptr);
    for (int st = 0; st < NBQ; st++) {
        const __half* Ahp = (st == 0) ? p_rDh : p_resh;
        const __half* Alp = (st == 0) ? p_rDl : p_resl;
        const float* Rin = (st == 0) ? p_rD : p_res;
        hgemmP<3><<<hp_grid(NTOK, NEQ), 128, HP_SMEM>>>(Ahp, Alp,
            p_bkh + (size_t)st * NEQ * DD, p_bkl + (size_t)st * NEQ * DD,
            nullptr, nullptr, nullptr, NTOK, NEQ, DD, DP, DD, nullptr, nullptr, 0,
            p_cn + (size_t)st * NEQ, p_keys);
        rvq_update3<<<NTOK, DD>>>(p_keys, books + (size_t)st * NEQ * DD,
                                  Rin, p_res, p_resh, p_resl,
                                  p_qDv, p_qDh, p_qDl,
                                  st == 0 ? 1 : 0, st == NBQ - 1 ? 1 : 0);
    }
    hgemmP<0><<<hp_grid(NTOK, CC), 128, HP_SMEM>>>(p_qDh, p_qDl, p_Wuh, p_Wul,
        p_zh, nullptr, nullptr, NTOK, CC, DD, DP, DD, bu, p_zp, 0, nullptr, nullptr);

    // ---- pass B ----
    ln_kernel<0, 2, 2, 1><<<M2, 256>>>(p_zh, nullptr, ln_q_g, ln_q_b, nullptr,
                                       p_q0n, p_q0nh, p_q0nl, M2);
    hgemmP<0><<<hp_grid(M2, CC), 128, HP_SMEM>>>(p_q0nh, p_q0nl, p_Wqh, p_Wql,
        p_Q0, nullptr, nullptr, M2, CC, CC, CC, CC, nullptr, nullptr, 0, nullptr, nullptr);
    attn_b<<<dim3(M2, HH), 128>>>(p_KVb, p_Q0, p_c0h, p_c0l);
    hgemmP<0><<<hp_grid(M2, CC), 128, HP_SMEM>>>(p_c0h, p_c0l, p_Woh, p_Wol,
        p_y0, nullptr, nullptr, M2, CC, CC, CC, CC, nullptr, p_q0n, 0, nullptr, nullptr);
    ln_kernel<0, 1, 0, 0><<<M2, 256>>>(p_y0, nullptr, ffg, ffb, nullptr,
                                       nullptr, p_hn0h, p_hn0l, M2);
    hgemmP<2><<<hp_grid(M2, 2 * CC), 128, HP_SMEM>>>(p_hn0h, p_hn0l, p_W1h, p_W1l,
        nullptr, p_g10h, p_g10l, M2, 2 * CC, CC, CC, CC, b1, nullptr, 0, nullptr, nullptr);
    hgemmP<0><<<hp_grid(M2, CC), 128, HP_SMEM>>>(p_g10h, p_g10l, p_W2h, p_W2l,
        p_z0, nullptr, nullptr, M2, CC, 2 * CC, 2 * CC, 2 * CC, b2, p_y0, 0, nullptr, nullptr);
    ln_kernel<1, 1, 0, 2><<<M2, 256>>>(p_ztt, p_z0, tng, tnb, scale,
                                       nullptr, p_rNsh, p_rNsl, M2);
    hgemmP<4><<<hp_grid(M2, DP), 128, HP_SMEM>>>(p_rNsh, p_rNsl, p_Wdh, p_Wdl,
        p_rD0, p_rD0h, p_rD0l, M2, DP, CC, CC, CC, p_bdp, nullptr, 0, nullptr, nullptr);
    for (int st = 0; st < NBQ; st++) {
        const __half* Ahp = (st == 0) ? p_rD0h : p_re0h;
        const __half* Alp = (st == 0) ? p_rD0l : p_re0l;
        const float* Rin = (st == 0) ? p_rD0 : p_res0;
        hgemmP<3><<<hp_grid(M2, NEQ), 128, HP_SMEM>>>(Ahp, Alp,
            p_bkh + (size_t)st * NEQ * DD, p_bkl + (size_t)st * NEQ * DD,
            nullptr, nullptr, nullptr, M2, NEQ, DD, DP, DD, nullptr, nullptr, 0,
            p_cn + (size_t)st * NEQ, p_keys);
        rvq_update3<<<M2, DD>>>(p_keys, books + (size_t)st * NEQ * DD,
                                Rin, p_res0, p_re0h, p_re0l,
                                p_qD0, p_qD0h, p_qD0l,
                                st == 0 ? 1 : 0, st == NBQ - 1 ? 1 : 0);
    }
    hgemmP<0><<<hp_grid(M2, CC), 128, HP_SMEM>>>(p_qD0h, p_qD0l, p_Wuh, p_Wul,
        p_zh0, nullptr, nullptr, M2, CC, DD, DP, DD, bu, p_z0, 0, nullptr, nullptr);
    scatter_rows16<<<M2, 256>>>(p_zh0, p_zh, CC, CC);
    scatter_rows16<<<M2, 128>>>(p_rD0, p_rD, DD, DP);

    // ---- outputs ----
    transpose_tc_to_ct<1><<<dim3(TT / 32, CC / 32, BB), dim3(32, 8)>>>(p_zh, o_y, CC, TT, CC);
    if ((size_t)out_size >= (size_t)BB * CC * TT + (size_t)BB * DD * TT)
        transpose_tc_to_ct<0><<<dim3(TT / 32, DD / 32, BB), dim3(32, 8)>>>(p_rD, o_r, DD, TT, DP);
}

// round 13
// speedup vs baseline: 1.0243x; 1.0243x over previous
#include <cuda_runtime.h>
#include <cuda_fp16.h>
#include <math.h>
#include <stdint.h>

// ---------------- problem constants ----------------
#define BB   16
#define CC   1024
#define TT   2048
#define DD   96
#define DP   128                 // padded D stride
#define NBQ  4
#define NEQ  2048
#define HH   8
#define CHK  16
#define NCHK 128
#define NTOK 32768
#define M2   2048
#define DH   128

typedef unsigned long long u64;

// ---------------- fp32 scratch ----------------
__device__ float g_qat[(size_t)NTOK*CC];
__device__ float g_ztt[(size_t)NTOK*CC];
__device__ float g_KVb[(size_t)NTOK*2*CC];
__device__ float g_y  [(size_t)NTOK*CC];
__device__ float g_zp [(size_t)NTOK*CC];
__device__ float g_zh [(size_t)NTOK*CC];
__device__ float g_rD [(size_t)NTOK*DP];
__device__ float g_res[(size_t)NTOK*DP];
__device__ float g_qDv[(size_t)NTOK*DP];
__device__ u64   g_keys[(size_t)NTOK];

__device__ float g_q0n [(size_t)M2*CC];
__device__ float g_Q0  [(size_t)M2*CC];
__device__ float g_y0  [(size_t)M2*CC];
__device__ float g_z0  [(size_t)M2*CC];
__device__ float g_zh0 [(size_t)M2*CC];
__device__ float g_rD0 [(size_t)M2*DP];
__device__ float g_res0[(size_t)M2*DP];
__device__ float g_qD0 [(size_t)M2*DP];

__device__ float g_qc  [(size_t)CHK*CC];
__device__ float g_Qc  [(size_t)CHK*CC];
__device__ float g_cn  [(size_t)NBQ*NEQ];
__device__ float g_bdp [DP];

// ---------------- half hi/lo scratch ----------------
__device__ __half g_kvnh[(size_t)NTOK*CC], g_kvnl[(size_t)NTOK*CC];
__device__ __half g_ctxh[(size_t)NTOK*CC], g_ctxl[(size_t)NTOK*CC];
__device__ __half g_hnh [(size_t)NTOK*CC], g_hnl [(size_t)NTOK*CC];
__device__ __half g_s1h [(size_t)NTOK*2*CC], g_s1l [(size_t)NTOK*2*CC];
__device__ __half g_rNsh[(size_t)NTOK*CC], g_rNsl[(size_t)NTOK*CC];
__device__ __half g_rDh [(size_t)NTOK*DP], g_rDl [(size_t)NTOK*DP];
__device__ __half g_resh[(size_t)NTOK*DP], g_resl[(size_t)NTOK*DP];
__device__ __half g_qDh [(size_t)NTOK*DP], g_qDl [(size_t)NTOK*DP];

__device__ __half g_q0nh[(size_t)M2*CC], g_q0nl[(size_t)M2*CC];
__device__ __half g_c0h [(size_t)M2*CC], g_c0l [(size_t)M2*CC];
__device__ __half g_hn0h[(size_t)M2*CC], g_hn0l[(size_t)M2*CC];
__device__ __half g_g10h[(size_t)M2*2*CC], g_g10l[(size_t)M2*2*CC];
__device__ __half g_rD0h[(size_t)M2*DP], g_rD0l[(size_t)M2*DP];
__device__ __half g_re0h[(size_t)M2*DP], g_re0l[(size_t)M2*DP];
__device__ __half g_qD0h[(size_t)M2*DP], g_qD0l[(size_t)M2*DP];

// split weights [N,K]
__device__ __half g_Wkvh[(size_t)2*CC*CC], g_Wkvl[(size_t)2*CC*CC];
__device__ __half g_Wqh[(size_t)CC*CC], g_Wql[(size_t)CC*CC];
__device__ __half g_Woh[(size_t)CC*CC], g_Wol[(size_t)CC*CC];
__device__ __half g_W1h[(size_t)2*CC*CC], g_W1l[(size_t)2*CC*CC];
__device__ __half g_W2h[(size_t)CC*2*CC], g_W2l[(size_t)CC*2*CC];
__device__ __half g_Wdh[(size_t)DP*CC], g_Wdl[(size_t)DP*CC];
__device__ __half g_Wuh[(size_t)CC*DD], g_Wul[(size_t)CC*DD];
__device__ __half g_bkh[(size_t)NBQ*NEQ*DD], g_bkl[(size_t)NBQ*NEQ*DD];

__device__ __forceinline__ uint32_t smem_u32(const void* p) {
    uint32_t a;
    asm("{ .reg .u64 t; cvta.to.shared.u64 t, %1; cvt.u32.u64 %0, t; }" : "=r"(a) : "l"(p));
    return a;
}
__device__ __forceinline__ void mma16816(float* c, const uint32_t* a, const uint32_t* b) {
    asm volatile(
        "mma.sync.aligned.m16n8k16.row.col.f32.f16.f16.f32 "
        "{%0,%1,%2,%3}, {%4,%5,%6,%7}, {%8,%9}, {%0,%1,%2,%3};"
        : "+f"(c[0]), "+f"(c[1]), "+f"(c[2]), "+f"(c[3])
        : "r"(a[0]), "r"(a[1]), "r"(a[2]), "r"(a[3]), "r"(b[0]), "r"(b[1]));
}
__device__ __forceinline__ void ldmat4(uint32_t* r, uint32_t addr) {
    asm volatile("ldmatrix.sync.aligned.m8n8.x4.shared.b16 {%0,%1,%2,%3}, [%4];"
                 : "=r"(r[0]), "=r"(r[1]), "=r"(r[2]), "=r"(r[3]) : "r"(addr));
}
__device__ __forceinline__ void cp16(uint32_t dst, const void* src) {
    asm volatile("cp.async.cg.shared.global [%0], [%1], 16;\n" :: "r"(dst), "l"(src));
}
__device__ __forceinline__ void cpa_commit() { asm volatile("cp.async.commit_group;\n"); }
#define CPA_WAIT2() asm volatile("cp.async.wait_group 2;\n")
__device__ __forceinline__ void cpa_wait0() { asm volatile("cp.async.wait_group 0;\n"); }

// swizzled smem address: 128 rows x 64B, chunk-XOR swizzle
__device__ __forceinline__ uint32_t sw_addr(int row, int q) {
    return (uint32_t)(row * 64 + ((q ^ ((row >> 1) & 3)) << 4));
}

__device__ __forceinline__ float pe_val(int c, int t) {
    int ii = c >> 1;
    float div = expf((float)(2 * ii) * (-9.210340371976184f / (float)CC));
    float ang = (float)t * div;
    return (c & 1) ? cosf(ang) : sinf(ang);
}

// ---------------- split-input 3xFP16 GEMM: 128x128 tile, 128 thr, 3-stage, occ 2 ----
// Compile-time LDA/LDB so loader addressing is constant-folded.
// EPI 0: fp32 (+bias)(+add[rowsel]); EPI 2: gelu(r+bias)->halves;
// EPI 3: argmax keys; EPI 4: fp32 (+bias) AND halves.
#define HP_STAGE 32768
#define HP_SMEM  (3 * HP_STAGE)

template <int EPI, int LDA, int LDB>
__global__ __launch_bounds__(128, 2) void hgemmP(
    const __half* __restrict__ Ah, const __half* __restrict__ Al,
    const __half* __restrict__ Bh, const __half* __restrict__ Bl,
    float* __restrict__ Co, __half* __restrict__ Oh, __half* __restrict__ Ol,
    int M, int N, int K,
    const float* __restrict__ bias, const float* __restrict__ add, int addPeriod,
    const float* __restrict__ cn, u64* __restrict__ keys) {
    extern __shared__ char sm[];
    const uint32_t sb = smem_u32(sm);
    const int tid = threadIdx.x;
    const int wid = tid >> 5, lane = tid & 31;
    const int wm = wid >> 1, wn = wid & 1;
    const int bm = blockIdx.y * 128, bn = blockIdx.x * 128;
    const int g = lane >> 2, tg = lane & 3;
    const int nt = K / 32;

    float acc[4][8][4];
#pragma unroll
    for (int i = 0; i < 4; i++)
#pragma unroll
        for (int j = 0; j < 8; j++)
#pragma unroll
            for (int q = 0; q < 4; q++) acc[i][j][q] = 0.f;

    const int lrow = (lane & 7) + ((lane >> 3) & 1) * 8;
    const int lq   = (lane >> 4) & 1;
    const int brow = (lane & 7) + ((lane >> 4) ? 8 : 0);
    const int bq   = (lane >> 3) & 1;

#define HP_LOAD(T) do {                                                         \
    int _t = (T);                                                               \
    if (_t < nt) {                                                              \
        uint32_t d0 = sb + (_t % 3) * HP_STAGE;                                 \
        _Pragma("unroll")                                                       \
        for (int j = 0; j < 16; j++) {                                          \
            int c = tid + j * 128;                                              \
            int mat = c >> 9;                                                   \
            int cc = c & 511;                                                   \
            int row = cc >> 2, q = cc & 3;                                      \
            const __half* src;                                                  \
            if (mat == 0)      src = Ah + (size_t)(bm + row) * LDA + _t * 32 + q * 8; \
            else if (mat == 1) src = Al + (size_t)(bm + row) * LDA + _t * 32 + q * 8; \
            else if (mat == 2) src = Bh + (size_t)(bn + row) * LDB + _t * 32 + q * 8; \
            else               src = Bl + (size_t)(bn + row) * LDB + _t * 32 + q * 8; \
            cp16(d0 + mat * 8192 + sw_addr(row, q), src);                       \
        }                                                                       \
    }                                                                           \
    cpa_commit();                                                               \
} while (0)

    HP_LOAD(0);
    HP_LOAD(1);
    HP_LOAD(2);

    for (int t = 0; t < nt; t++) {
        CPA_WAIT2();
        __syncthreads();
        const uint32_t tb = sb + (t % 3) * HP_STAGE;
#pragma unroll
        for (int ks = 0; ks < 2; ks++) {
            uint32_t ah[4][4], al[4][4];
#pragma unroll
            for (int mt = 0; mt < 4; mt++) {
                int row = wm * 64 + mt * 16 + lrow;
                uint32_t ad = tb + sw_addr(row, ks * 2 + lq);
                ldmat4(ah[mt], ad);
                ldmat4(al[mt], ad + 8192);
            }
            uint32_t bf[4][4];
#pragma unroll
            for (int p = 0; p < 4; p++) {
                int row = wn * 64 + p * 16 + brow;
                uint32_t bd = tb + 16384 + sw_addr(row, ks * 2 + bq);
                ldmat4(bf[p], bd);
            }
#pragma unroll
            for (int mt = 0; mt < 4; mt++)
#pragma unroll
                for (int p = 0; p < 4; p++) {
                    mma16816(acc[mt][2 * p],     ah[mt], &bf[p][0]);
                    mma16816(acc[mt][2 * p + 1], ah[mt], &bf[p][2]);
                    mma16816(acc[mt][2 * p],     al[mt], &bf[p][0]);
                    mma16816(acc[mt][2 * p + 1], al[mt], &bf[p][2]);
                }
#pragma unroll
            for (int p = 0; p < 4; p++) {
                int row = wn * 64 + p * 16 + brow;
                uint32_t bd = tb + 24576 + sw_addr(row, ks * 2 + bq);
                ldmat4(bf[p], bd);
            }
#pragma unroll
            for (int mt = 0; mt < 4; mt++)
#pragma unroll
                for (int p = 0; p < 4; p++) {
                    mma16816(acc[mt][2 * p],     ah[mt], &bf[p][0]);
                    mma16816(acc[mt][2 * p + 1], ah[mt], &bf[p][2]);
                }
        }
        __syncthreads();
        HP_LOAD(t + 3);
    }
#undef HP_LOAD

    if (EPI == 3) {
#pragma unroll
        for (int mt = 0; mt < 4; mt++) {
            int m0 = bm + wm * 64 + mt * 16 + g;
            int m1 = m0 + 8;
            u64 b0 = 0ull, b1 = 0ull;
#pragma unroll
            for (int nb = 0; nb < 8; nb++) {
                int n0 = bn + wn * 64 + nb * 8 + tg * 2;
                float s00 = acc[mt][nb][0] - cn[n0];
                float s01 = acc[mt][nb][1] - cn[n0 + 1];
                float s10 = acc[mt][nb][2] - cn[n0];
                float s11 = acc[mt][nb][3] - cn[n0 + 1];
                unsigned u;
                u = __float_as_uint(s00); u = (u & 0x80000000u) ? ~u : (u | 0x80000000u);
                u64 k = ((u64)u << 32) | (unsigned)(~n0);
                if (k > b0) b0 = k;
                u = __float_as_uint(s01); u = (u & 0x80000000u) ? ~u : (u | 0x80000000u);
                k = ((u64)u << 32) | (unsigned)(~(n0 + 1));
                if (k > b0) b0 = k;
                u = __float_as_uint(s10); u = (u & 0x80000000u) ? ~u : (u | 0x80000000u);
                k = ((u64)u << 32) | (unsigned)(~n0);
                if (k > b1) b1 = k;
                u = __float_as_uint(s11); u = (u & 0x80000000u) ? ~u : (u | 0x80000000u);
                k = ((u64)u << 32) | (unsigned)(~(n0 + 1));
                if (k > b1) b1 = k;
            }
#pragma unroll
            for (int o = 1; o < 4; o <<= 1) {
                u64 t0 = __shfl_xor_sync(0xffffffffu, b0, o);
                u64 t1 = __shfl_xor_sync(0xffffffffu, b1, o);
                if (t0 > b0) b0 = t0;
                if (t1 > b1) b1 = t1;
            }
            if (tg == 0) {
                atomicMax(&keys[m0], b0);
                atomicMax(&keys[m1], b1);
            }
        }
    } else {
#pragma unroll
        for (int mt = 0; mt < 4; mt++) {
            int m0 = bm + wm * 64 + mt * 16 + g;
            int m1 = m0 + 8;
            const float* add0 = (EPI == 0 && add)
                ? add + (size_t)((addPeriod > 0) ? (m0 % addPeriod) : m0) * N : nullptr;
            const float* add1 = (EPI == 0 && add)
                ? add + (size_t)((addPeriod > 0) ? (m1 % addPeriod) : m1) * N : nullptr;
#pragma unroll
            for (int nb = 0; nb < 8; nb++) {
                int n0 = bn + wn * 64 + nb * 8 + tg * 2;
                float v0 = acc[mt][nb][0], v1 = acc[mt][nb][1];
                float v2 = acc[mt][nb][2], v3 = acc[mt][nb][3];
                if (bias) {
                    float c0 = bias[n0], c1 = bias[n0 + 1];
                    v0 += c0; v1 += c1; v2 += c0; v3 += c1;
                }
                if (EPI == 0) {
                    if (add0) { v0 += add0[n0]; v1 += add0[n0 + 1]; }
                    if (add1) { v2 += add1[n0]; v3 += add1[n0 + 1]; }
                    *(float2*)(Co + (size_t)m0 * N + n0) = make_float2(v0, v1);
                    *(float2*)(Co + (size_t)m1 * N + n0) = make_float2(v2, v3);
                } else if (EPI == 4) {
                    *(float2*)(Co + (size_t)m0 * N + n0) = make_float2(v0, v1);
                    *(float2*)(Co + (size_t)m1 * N + n0) = make_float2(v2, v3);
                    __half2 h0 = __floats2half2_rn(v0, v1);
                    float2 f0 = __half22float2(h0);
                    __half2 l0 = __floats2half2_rn(v0 - f0.x, v1 - f0.y);
                    __half2 h1 = __floats2half2_rn(v2, v3);
                    float2 f1 = __half22float2(h1);
                    __half2 l1 = __floats2half2_rn(v2 - f1.x, v3 - f1.y);
                    *(__half2*)(Oh + (size_t)m0 * N + n0) = h0;
                    *(__half2*)(Ol + (size_t)m0 * N + n0) = l0;
                    *(__half2*)(Oh + (size_t)m1 * N + n0) = h1;
                    *(__half2*)(Ol + (size_t)m1 * N + n0) = l1;
                } else {  // EPI == 2
                    v0 = 0.5f * v0 * (1.0f + erff(v0 * 0.70710678118654752f));
                    v1 = 0.5f * v1 * (1.0f + erff(v1 * 0.70710678118654752f));
                    v2 = 0.5f * v2 * (1.0f + erff(v2 * 0.70710678118654752f));
                    v3 = 0.5f * v3 * (1.0f + erff(v3 * 0.70710678118654752f));
                    __half2 h0 = __floats2half2_rn(v0, v1);
                    float2 f0 = __half22float2(h0);
                    __half2 l0 = __floats2half2_rn(v0 - f0.x, v1 - f0.y);
                    __half2 h1 = __floats2half2_rn(v2, v3);
                    float2 f1 = __half22float2(h1);
                    __half2 l1 = __floats2half2_rn(v2 - f1.x, v3 - f1.y);
                    *(__half2*)(Oh + (size_t)m0 * N + n0) = h0;
                    *(__half2*)(Ol + (size_t)m0 * N + n0) = l0;
                    *(__half2*)(Oh + (size_t)m1 * N + n0) = h1;
                    *(__half2*)(Ol + (size_t)m1 * N + n0) = l1;
                }
            }
        }
    }
}

// ---------------- setup kernels ----------------
__global__ void prep_books(const float* __restrict__ books, float* __restrict__ cn,
                           __half* __restrict__ bh, __half* __restrict__ bl) {
    int i = blockIdx.x * 256 + threadIdx.x;
    if (i >= NBQ * NEQ) return;
    const float* src = books + (size_t)i * DD;
    float s = 0.f;
    for (int d = 0; d < DD; d++) {
        float v = src[d];
        s += v * v;
        __half h = __float2half_rn(v);
        bh[(size_t)i * DD + d] = h;
        bl[(size_t)i * DD + d] = __float2half_rn(v - __half2float(h));
    }
    cn[i] = 0.5f * s;
}

__global__ void prep_bd(const float* __restrict__ bd, float* __restrict__ bdp) {
    int i = threadIdx.x;
    bdp[i] = (i < DD) ? bd[i] : 0.0f;
}

__global__ void split_f32(const float* __restrict__ src, __half* __restrict__ h,
                          __half* __restrict__ l, int n) {
    int i = blockIdx.x * 256 + threadIdx.x;
    if (i >= n) return;
    float v = src[i];
    __half hi = __float2half_rn(v);
    h[i] = hi;
    l[i] = __float2half_rn(v - __half2float(hi));
}

// ---------------- transposes ----------------
__global__ void transpose_ct_to_tc(const float* __restrict__ in, float* __restrict__ out,
                                   int Cdim, int Tdim) {
    __shared__ float tile[32][33];
    int b = blockIdx.z;
    int c0 = blockIdx.y * 32, t0 = blockIdx.x * 32;
    int x = threadIdx.x, y = threadIdx.y;
    for (int i = 0; i < 32; i += 8)
        tile[y + i][x] = in[((size_t)b * Cdim + c0 + y + i) * Tdim + t0 + x];
    __syncthreads();
    for (int i = 0; i < 32; i += 8)
        out[((size_t)b * Tdim + t0 + y + i) * Cdim + c0 + x] = tile[x][y + i];
}

__global__ void transpose_split2(const float* __restrict__ inA, __half* __restrict__ ohA,
                                 __half* __restrict__ olA,
                                 const float* __restrict__ inB, __half* __restrict__ ohB,
                                 __half* __restrict__ olB, int Cdim, int Tdim) {
    __shared__ float tile[32][33];
    int which = blockIdx.z;
    const float* in = which ? inB : inA;
    __half* oh = which ? ohB : ohA;
    __half* ol = which ? olB : olA;
    int c0 = blockIdx.y * 32, t0 = blockIdx.x * 32;
    int x = threadIdx.x, y = threadIdx.y;
    for (int i = 0; i < 32; i += 8)
        tile[y + i][x] = in[(size_t)(c0 + y + i) * Tdim + t0 + x];
    __syncthreads();
    for (int i = 0; i < 32; i += 8) {
        float v = tile[x][y + i];
        __half h = __float2half_rn(v);
        size_t o = (size_t)(t0 + y + i) * Cdim + c0 + x;
        oh[o] = h;
        ol[o] = __float2half_rn(v - __half2float(h));
    }
}

template <int NANFIX>
__global__ void transpose_tc_to_ct(const float* __restrict__ in, float* __restrict__ out,
                                   int Cdim, int Tdim, int srcLd) {
    __shared__ float tile[32][33];
    int b = blockIdx.z;
    int c0 = blockIdx.y * 32, t0 = blockIdx.x * 32;
    int x = threadIdx.x, y = threadIdx.y;
    for (int i = 0; i < 32; i += 8)
        tile[y + i][x] = in[((size_t)b * Tdim + t0 + y + i) * srcLd + c0 + x];
    __syncthreads();
    for (int i = 0; i < 32; i += 8) {
        float v = tile[x][y + i];
        if (NANFIX) { if (!isfinite(v)) v = 0.0f; }
        out[((size_t)b * Cdim + c0 + y + i) * Tdim + t0 + x] = v;
    }
}

// ---------------- LayerNorm ----------------
// SRC 0: in0 row m; 1: carry (row m*16-1, zero if m%128==0); 2: gather (row m*16)
template <int POST, int SPLIT, int PE, int SRC>
__global__ __launch_bounds__(256) void ln_kernel(
    const float* __restrict__ in0, const float* __restrict__ in1,
    const float* __restrict__ gamma, const float* __restrict__ beta,
    const float* __restrict__ scale_ptr, float* __restrict__ out,
    __half* __restrict__ oh, __half* __restrict__ ol, int Mrows) {
    int m = blockIdx.x;
    if (m >= Mrows) return;
    int tid = threadIdx.x;
    int lane = tid & 31, warp = tid >> 5;
    __shared__ float red[8];
    float x[4];
#pragma unroll
    for (int k = 0; k < 4; k++) {
        int c = tid + k * 256;
        float v;
        if (SRC == 1) {
            v = (m & (NCHK - 1)) ? in0[((size_t)m * 16 - 1) * CC + c] : 0.0f;
        } else if (SRC == 2) {
            v = in0[((size_t)m * 16) * CC + c];
        } else {
            v = in0 ? in0[(size_t)m * CC + c] : 0.0f;
        }
        if (in1) v -= in1[(size_t)m * CC + c];
        if (PE == 1) v += pe_val(c, m & 15);
        else if (PE == 2) v += pe_val(c, 0);
        x[k] = v;
    }
    float s = x[0] + x[1] + x[2] + x[3];
#pragma unroll
    for (int o = 16; o; o >>= 1) s += __shfl_xor_sync(0xffffffffu, s, o);
    if (lane == 0) red[warp] = s;
    __syncthreads();
    float mean;
    {
        float t = (lane < 8) ? red[lane] : 0.f;
#pragma unroll
        for (int o = 4; o; o >>= 1) t += __shfl_xor_sync(0xffffffffu, t, o);
        mean = __shfl_sync(0xffffffffu, t, 0) * (1.0f / (float)CC);
    }
    float vs = 0.f;
#pragma unroll
    for (int k = 0; k < 4; k++) { float d = x[k] - mean; vs += d * d; }
#pragma unroll
    for (int o = 16; o; o >>= 1) vs += __shfl_xor_sync(0xffffffffu, vs, o);
    __syncthreads();
    if (lane == 0) red[warp] = vs;
    __syncthreads();
    float var;
    {
        float t = (lane < 8) ? red[lane] : 0.f;
#pragma unroll
        for (int o = 4; o; o >>= 1) t += __shfl_xor_sync(0xffffffffu, t, o);
        var = __shfl_sync(0xffffffffu, t, 0) * (1.0f / (float)CC);
    }
    float rstd = rsqrtf(var + 1e-5f);
    float sc = 1.0f;
    if (POST == 1) {
        float t = scale_ptr[0];
        sc = fminf(fmaxf(t, 0.005f), 0.5f);
    }
#pragma unroll
    for (int k = 0; k < 4; k++) {
        int c = tid + k * 256;
        float yv = (x[k] - mean) * rstd * gamma[c] + beta[c];
        if (POST == 1) yv = tanhf(yv) * sc;
        if (SPLIT != 1) out[(size_t)m * CC + c] = yv;
        if (SPLIT >= 1) {
            __half h = __float2half_rn(yv);
            oh[(size_t)m * CC + c] = h;
            ol[(size_t)m * CC + c] = __float2half_rn(yv - __half2float(h));
        }
    }
}

// ---------------- f32x2 helpers (scalar GEMM for tiny Qc) ----------------
__device__ __forceinline__ u64 pack2(float x) {
    u64 r;
    asm("mov.b64 %0, {%1, %1};" : "=l"(r) : "f"(x));
    return r;
}
__device__ __forceinline__ float2 unpack2(u64 v) {
    float2 f;
    asm("mov.b64 {%0, %1}, %2;" : "=f"(f.x), "=f"(f.y) : "l"(v));
    return f;
}
#define FFMA2(d, a, b) asm("fma.rn.f32x2 %0, %1, %2, %0;" : "+l"(d) : "l"(a), "l"(b))

__device__ __forceinline__ void cpa16p(void* dst, const void* src, bool pred) {
    unsigned int d = (unsigned int)__cvta_generic_to_shared(dst);
    int sz = pred ? 16 : 0;
    asm volatile("cp.async.ca.shared.global [%0], [%1], 16, %2;\n" :: "r"(d), "l"(src), "r"(sz));
}

template <bool GUARD>
__global__ __launch_bounds__(256, 2) void sgemm2(
    const float* __restrict__ A, const float* __restrict__ Bm, float* __restrict__ Co,
    int M, int N, int K, const float* __restrict__ bias) {
    __shared__ __align__(16) float As[2][16][128];
    __shared__ __align__(16) float Bs[2][16][128];
    const int tid = threadIdx.x;
    const int bm = blockIdx.y * 128, bn = blockIdx.x * 128;
    const int tx = tid & 15, ty = tid >> 4;

    const int a_row  = tid >> 1;
    const int a_koff = (tid & 1) * 8;
    const int b_row  = tid >> 5;
    const int b_col  = (tid & 31) * 4;

    const bool a_ok = !GUARD || (bm + a_row < M);
    const bool b_ok = !GUARD || (bn + b_col < N);
    const float* a_src0 = A + (size_t)(GUARD ? (a_ok ? bm + a_row : 0) : (bm + a_row)) * K + a_koff;
    const float* b_src0 = Bm + (size_t)b_row * N + (GUARD ? (b_ok ? bn + b_col : 0) : (bn + b_col));
    const float* b_src1 = b_src0 + (size_t)8 * N;

    u64 acc2[8][4];
#pragma unroll
    for (int i = 0; i < 8; i++)
#pragma unroll
        for (int q = 0; q < 4; q++) acc2[i][q] = 0ull;

    float a_reg[8];
    const int nt = K / 16;

    {
        if (a_ok) {
            float4 v0 = *(const float4*)(a_src0);
            float4 v1 = *(const float4*)(a_src0 + 4);
            a_reg[0]=v0.x; a_reg[1]=v0.y; a_reg[2]=v0.z; a_reg[3]=v0.w;
            a_reg[4]=v1.x; a_reg[5]=v1.y; a_reg[6]=v1.z; a_reg[7]=v1.w;
        } else {
#pragma unroll
            for (int c = 0; c < 8; c++) a_reg[c] = 0.f;
        }
        cpa16p(&Bs[0][b_row][b_col],     b_src0, b_ok);
        cpa16p(&Bs[0][8 + b_row][b_col], b_src1, b_ok);
        cpa_commit();
#pragma unroll
        for (int c = 0; c < 8; c++) As[0][a_koff + c][a_row] = a_reg[c];
        cpa_wait0();
        __syncthreads();
    }

    int buf = 0;
    for (int t = 0; t < nt; t++) {
        const bool has_next = (t + 1 < nt);
        if (has_next) {
            const float* ap = a_src0 + (size_t)(t + 1) * 16;
            if (a_ok) {
                float4 v0 = *(const float4*)(ap);
                float4 v1 = *(const float4*)(ap + 4);
                a_reg[0]=v0.x; a_reg[1]=v0.y; a_reg[2]=v0.z; a_reg[3]=v0.w;
                a_reg[4]=v1.x; a_reg[5]=v1.y; a_reg[6]=v1.z; a_reg[7]=v1.w;
            }
            cpa16p(&Bs[buf ^ 1][b_row][b_col],     b_src0 + (size_t)(t + 1) * 16 * N, b_ok);
            cpa16p(&Bs[buf ^ 1][8 + b_row][b_col], b_src1 + (size_t)(t + 1) * 16 * N, b_ok);
            cpa_commit();
        }
#pragma unroll
        for (int kk = 0; kk < 16; kk++) {
            float4 a0 = *(const float4*)&As[buf][kk][ty * 8];
            float4 a1 = *(const float4*)&As[buf][kk][ty * 8 + 4];
            ulonglong2 bl = *(const ulonglong2*)&Bs[buf][kk][tx * 4];
            ulonglong2 bh = *(const ulonglong2*)&Bs[buf][kk][64 + tx * 4];
            float am[8] = {a0.x, a0.y, a0.z, a0.w, a1.x, a1.y, a1.z, a1.w};
#pragma unroll
            for (int i = 0; i < 8; i++) {
                u64 ai = pack2(am[i]);
                FFMA2(acc2[i][0], ai, bl.x);
                FFMA2(acc2[i][1], ai, bl.y);
                FFMA2(acc2[i][2], ai, bh.x);
                FFMA2(acc2[i][3], ai, bh.y);
            }
        }
        if (has_next) {
#pragma unroll
            for (int c = 0; c < 8; c++) As[buf ^ 1][a_koff + c][a_row] = a_reg[c];
            cpa_wait0();
            __syncthreads();
            buf ^= 1;
        }
    }

#pragma unroll
    for (int i = 0; i < 8; i++) {
        int m = bm + ty * 8 + i;
        if (GUARD && m >= M) continue;
#pragma unroll
        for (int q = 0; q < 4; q++) {
            float2 v2 = unpack2(acc2[i][q]);
            int n0 = bn + ((q < 2) ? (tx * 4 + q * 2) : (64 + tx * 4 + (q - 2) * 2));
#pragma unroll
            for (int h = 0; h < 2; h++) {
                int n = n0 + h;
                if (GUARD && n >= N) continue;
                float v = h ? v2.y : v2.x;
                if (bias) v += bias[n];
                Co[(size_t)m * N + n] = v;
            }
        }
    }
}

// ---------------- attention ----------------
__global__ __launch_bounds__(256) void attn_a(const float* __restrict__ KVb,
                                              const float* __restrict__ Qc,
                                              __half* __restrict__ ctxh,
                                              __half* __restrict__ ctxl) {
    int gb = blockIdx.x;
    int h = blockIdx.y;
    int tid = threadIdx.x;
    __shared__ float Ks[16][133], Vs[16][133], Qs[16][133];
    __shared__ float Ss[16][17];
    for (int i = tid; i < 16 * DH; i += 256) {
        int t = i >> 7, d = i & 127;
        size_t base = ((size_t)(gb * 16 + t)) * (2 * CC) + (size_t)h * DH + d;
        Ks[t][d] = KVb[base];
        Vs[t][d] = KVb[base + CC];
        Qs[t][d] = Qc[(size_t)t * CC + (size_t)h * DH + d];
    }
    __syncthreads();
    {
        int q = tid >> 4, k = tid & 15;
        float s = 0.f;
#pragma unroll 8
        for (int d = 0; d < DH; d++) s = fmaf(Qs[q][d], Ks[k][d], s);
        Ss[q][k] = s * 0.08838834764831845f;
    }
    __syncthreads();
    if (tid < 16) {
        float mx = -1e30f;
        for (int k = 0; k < 16; k++) mx = fmaxf(mx, Ss[tid][k]);
        float e[16], sum = 0.f;
        for (int k = 0; k < 16; k++) { e[k] = expf(Ss[tid][k] - mx); sum += e[k]; }
        float inv = 1.0f / sum;
        for (int k = 0; k < 16; k++) Ss[tid][k] = e[k] * inv;
    }
    __syncthreads();
    for (int i = tid; i < 16 * DH; i += 256) {
        int t = i >> 7, d = i & 127;
        float a = 0.f;
#pragma unroll
        for (int k = 0; k < 16; k++) a = fmaf(Ss[t][k], Vs[k][d], a);
        size_t o = ((size_t)(gb * 16 + t)) * CC + (size_t)h * DH + d;
        __half hh = __float2half_rn(a);
        ctxh[o] = hh;
        ctxl[o] = __float2half_rn(a - __half2float(hh));
    }
}

__global__ __launch_bounds__(128) void attn_b(const float* __restrict__ KVb,
                                              const float* __restrict__ Q0,
                                              __half* __restrict__ ctxh,
                                              __half* __restrict__ ctxl) {
    int p = blockIdx.x;
    int h = blockIdx.y;
    int tid = threadIdx.x;
    __shared__ float Ks[16][128], Vs[16][128], Qs[128];
    __shared__ float sc[16];
    for (int i = tid; i < 16 * DH; i += 128) {
        int t = i >> 7, d = i & 127;
        size_t base = ((size_t)(p * 16 + t)) * (2 * CC) + (size_t)h * DH + d;
        Ks[t][d] = KVb[base];
        Vs[t][d] = KVb[base + CC];
    }
    Qs[tid] = Q0[(size_t)p * CC + (size_t)h * DH + tid];
    __syncthreads();
    int w = tid >> 5, l = tid & 31;
    for (int k = w; k < 16; k += 4) {
        float s = Qs[l] * Ks[k][l] + Qs[l + 32] * Ks[k][l + 32] +
                  Qs[l + 64] * Ks[k][l + 64] + Qs[l + 96] * Ks[k][l + 96];
        for (int o = 16; o; o >>= 1) s += __shfl_xor_sync(0xffffffffu, s, o);
        if (l == 0) sc[k] = s * 0.08838834764831845f;
    }
    __syncthreads();
    if (tid == 0) {
        float mx = -1e30f;
        for (int k = 0; k < 16; k++) mx = fmaxf(mx, sc[k]);
        float e[16], sum = 0.f;
        for (int k = 0; k < 16; k++) { e[k] = expf(sc[k] - mx); sum += e[k]; }
        float inv = 1.0f / sum;
        for (int k = 0; k < 16; k++) sc[k] = e[k] * inv;
    }
    __syncthreads();
    float a = 0.f;
#pragma unroll
    for (int k = 0; k < 16; k++) a = fmaf(sc[k], Vs[k][tid], a);
    size_t o = (size_t)p * CC + (size_t)h * DH + tid;
    __half hh = __float2half_rn(a);
    ctxh[o] = hh;
    ctxl[o] = __float2half_rn(a - __half2float(hh));
}

// ---------------- RVQ update (padded stride DP; resets keys) ----------------
__global__ void rvq_update3(u64* __restrict__ keys,
                            const float* __restrict__ books_st,
                            const float* __restrict__ resid_in,
                            float* __restrict__ resid_out,
                            __half* __restrict__ resh, __half* __restrict__ resl,
                            float* __restrict__ qD,
                            __half* __restrict__ qDh, __half* __restrict__ qDl,
                            int firstStage, int lastStage) {
    int m = blockIdx.x;
    int d = threadIdx.x;   // 96 threads
    int idx = (int)(~(unsigned)(keys[m] & 0xffffffffu)) & (NEQ - 1);
    __syncthreads();
    if (d == 0) keys[m] = 0ull;
    float e = books_st[(size_t)idx * DD + d];
    float r = resid_in[(size_t)m * DP + d];
    float nr = r - e;
    resid_out[(size_t)m * DP + d] = nr;
    __half hh = __float2half_rn(nr);
    resh[(size_t)m * DP + d] = hh;
    resl[(size_t)m * DP + d] = __float2half_rn(nr - __half2float(hh));
    float q = firstStage ? e : (qD[(size_t)m * DP + d] + e);
    qD[(size_t)m * DP + d] = q;
    if (lastStage) {
        __half qh = __float2half_rn(q);
        qDh[(size_t)m * DP + d] = qh;
        qDl[(size_t)m * DP + d] = __float2half_rn(q - __half2float(qh));
    }
}

// ---------------- misc ----------------
__global__ void scatter_rows16(const float* __restrict__ in, float* __restrict__ out,
                               int count, int ld) {
    int p = blockIdx.x;
    for (int c = threadIdx.x; c < count; c += blockDim.x)
        out[((size_t)p * 16) * ld + c] = in[(size_t)p * ld + c];
}

// ---------------- host ----------------
static inline dim3 gemm_grid(int M, int N) { return dim3((N + 127) / 128, (M + 127) / 128); }
static inline dim3 hp_grid(int M, int N) { return dim3(N / 128, M / 128); }

extern "C" void kernel_launch(void* const* d_in, const int* in_sizes, int n_in,
                              void* d_out, int out_size) {
    const float* qa     = (const float*)d_in[0];
    const float* ztt    = (const float*)d_in[1];
    const float* ln_q_g = (const float*)d_in[2];
    const float* ln_q_b = (const float*)d_in[3];
    const float* ln_kv_g= (const float*)d_in[4];
    const float* ln_kv_b= (const float*)d_in[5];
    const float* Wq     = (const float*)d_in[6];
    const float* Wk     = (const float*)d_in[7];
    const float* Wv     = (const float*)d_in[8];
    const float* Wo     = (const float*)d_in[9];
    const float* ffg    = (const float*)d_in[10];
    const float* ffb    = (const float*)d_in[11];
    const float* W1     = (const float*)d_in[12];
    const float* b1     = (const float*)d_in[13];
    const float* W2     = (const float*)d_in[14];
    const float* b2     = (const float*)d_in[15];
    const float* tng    = (const float*)d_in[16];
    const float* tnb    = (const float*)d_in[17];
    const float* scale  = (const float*)d_in[18];
    const float* Wd     = (const float*)d_in[19];
    const float* bd     = (const float*)d_in[20];
    const float* Wu     = (const float*)d_in[21];
    const float* bu     = (const float*)d_in[22];
    const float* books  = (const float*)d_in[23];

    float* out = (float*)d_out;
    float* o_y = out;
    float* o_r = out + (size_t)BB * CC * TT;

#define SYMF(p, s) float* p; cudaGetSymbolAddress((void**)&p, s)
#define SYMH(p, s) __half* p; cudaGetSymbolAddress((void**)&p, s)
    SYMF(p_qat, g_qat); SYMF(p_ztt, g_ztt);
    SYMF(p_KVb, g_KVb);
    SYMF(p_y, g_y);     SYMF(p_zp, g_zp);   SYMF(p_zh, g_zh);
    SYMF(p_rD, g_rD);   SYMF(p_res, g_res); SYMF(p_qDv, g_qDv);
    SYMF(p_q0n, g_q0n); SYMF(p_Q0, g_Q0);
    SYMF(p_y0, g_y0);   SYMF(p_z0, g_z0);
    SYMF(p_zh0, g_zh0);
    SYMF(p_rD0, g_rD0); SYMF(p_res0, g_res0); SYMF(p_qD0, g_qD0);
    SYMF(p_qc, g_qc);   SYMF(p_Qc, g_Qc);
    SYMF(p_cn, g_cn);   SYMF(p_bdp, g_bdp);
    SYMH(p_kvnh, g_kvnh); SYMH(p_kvnl, g_kvnl);
    SYMH(p_ctxh, g_ctxh); SYMH(p_ctxl, g_ctxl);
    SYMH(p_hnh, g_hnh);   SYMH(p_hnl, g_hnl);
    SYMH(p_s1h, g_s1h);   SYMH(p_s1l, g_s1l);
    SYMH(p_rNsh, g_rNsh); SYMH(p_rNsl, g_rNsl);
    SYMH(p_rDh, g_rDh);   SYMH(p_rDl, g_rDl);
    SYMH(p_resh, g_resh); SYMH(p_resl, g_resl);
    SYMH(p_qDh, g_qDh);   SYMH(p_qDl, g_qDl);
    SYMH(p_q0nh, g_q0nh); SYMH(p_q0nl, g_q0nl);
    SYMH(p_c0h, g_c0h);   SYMH(p_c0l, g_c0l);
    SYMH(p_hn0h, g_hn0h); SYMH(p_hn0l, g_hn0l);
    SYMH(p_g10h, g_g10h); SYMH(p_g10l, g_g10l);
    SYMH(p_rD0h, g_rD0h); SYMH(p_rD0l, g_rD0l);
    SYMH(p_re0h, g_re0h); SYMH(p_re0l, g_re0l);
    SYMH(p_qD0h, g_qD0h); SYMH(p_qD0l, g_qD0l);
    SYMH(p_Wkvh, g_Wkvh); SYMH(p_Wkvl, g_Wkvl);
    SYMH(p_Wqh, g_Wqh); SYMH(p_Wql, g_Wql);
    SYMH(p_Woh, g_Woh); SYMH(p_Wol, g_Wol);
    SYMH(p_W1h, g_W1h); SYMH(p_W1l, g_W1l);
    SYMH(p_W2h, g_W2h); SYMH(p_W2l, g_W2l);
    SYMH(p_Wdh, g_Wdh); SYMH(p_Wdl, g_Wdl);
    SYMH(p_Wuh, g_Wuh); SYMH(p_Wul, g_Wul);
    SYMH(p_bkh, g_bkh); SYMH(p_bkl, g_bkl);
#undef SYMF
#undef SYMH
    u64* p_keys; cudaGetSymbolAddress((void**)&p_keys, g_keys);

    cudaFuncSetAttribute(hgemmP<0, CC, CC>, cudaFuncAttributeMaxDynamicSharedMemorySize, HP_SMEM);
    cudaFuncSetAttribute(hgemmP<2, CC, CC>, cudaFuncAttributeMaxDynamicSharedMemorySize, HP_SMEM);
    cudaFuncSetAttribute(hgemmP<0, 2 * CC, 2 * CC>, cudaFuncAttributeMaxDynamicSharedMemorySize, HP_SMEM);
    cudaFuncSetAttribute(hgemmP<4, CC, CC>, cudaFuncAttributeMaxDynamicSharedMemorySize, HP_SMEM);
    cudaFuncSetAttribute(hgemmP<3, DP, DD>, cudaFuncAttributeMaxDynamicSharedMemorySize, HP_SMEM);
    cudaFuncSetAttribute(hgemmP<0, DP, DD>, cudaFuncAttributeMaxDynamicSharedMemorySize, HP_SMEM);

    // ---- launches 1-3 setup; 4 = merged KV GEMM (ncu slot) ----
    transpose_ct_to_tc<<<dim3(TT / 32, CC / 32, BB), dim3(32, 8)>>>(qa, p_qat, CC, TT); // 1
    ln_kernel<0, 1, 1, 0><<<NTOK, 256>>>(p_qat, nullptr, ln_kv_g, ln_kv_b, nullptr,
                                         nullptr, p_kvnh, p_kvnl, NTOK);                // 2
    transpose_split2<<<dim3(32, 32, 2), dim3(32, 8)>>>(Wk, p_Wkvh, p_Wkvl,
                                                       Wv, p_Wkvh + (size_t)CC * CC,
                                                       p_Wkvl + (size_t)CC * CC, CC, CC); // 3
    hgemmP<0, CC, CC><<<hp_grid(NTOK, 2 * CC), 128, HP_SMEM>>>(p_kvnh, p_kvnl, p_Wkvh, p_Wkvl,
        p_KVb, nullptr, nullptr, NTOK, 2 * CC, CC, nullptr, nullptr, 0, nullptr, nullptr); // 4

    // ---- remaining setup ----
    transpose_ct_to_tc<<<dim3(TT / 32, CC / 32, BB), dim3(32, 8)>>>(ztt, p_ztt, CC, TT);
    prep_books<<<(NBQ * NEQ + 255) / 256, 256>>>(books, p_cn, p_bkh, p_bkl);
    prep_bd<<<1, DP>>>(bd, p_bdp);
    transpose_split2<<<dim3(32, 32, 2), dim3(32, 8)>>>(Wq, p_Wqh, p_Wql,
                                                       Wo, p_Woh, p_Wol, CC, CC);
    transpose_split2<<<dim3(64, 32, 1), dim3(32, 8)>>>(W1, p_W1h, p_W1l,
                                                       nullptr, nullptr, nullptr, CC, 2 * CC);
    transpose_split2<<<dim3(32, 64, 1), dim3(32, 8)>>>(W2, p_W2h, p_W2l,
                                                       nullptr, nullptr, nullptr, 2 * CC, CC);
    split_f32<<<(DD * CC + 255) / 256, 256>>>(Wd, p_Wdh, p_Wdl, DD * CC);
    split_f32<<<(CC * DD + 255) / 256, 256>>>(Wu, p_Wuh, p_Wul, CC * DD);
    ln_kernel<0, 0, 1, 0><<<CHK, 256>>>(nullptr, nullptr, ln_q_g, ln_q_b, nullptr,
                                        p_qc, nullptr, nullptr, CHK);
    sgemm2<true><<<gemm_grid(CHK, CC), 256>>>(p_qc, Wq, p_Qc, CHK, CC, CC, nullptr);
    cudaMemsetAsync(p_keys, 0, (size_t)NTOK * sizeof(u64), 0);

    // ---- pass A ----
    attn_a<<<dim3(M2, HH), 256>>>(p_KVb, p_Qc, p_ctxh, p_ctxl);
    hgemmP<0, CC, CC><<<hp_grid(NTOK, CC), 128, HP_SMEM>>>(p_ctxh, p_ctxl, p_Woh, p_Wol,
        p_y, nullptr, nullptr, NTOK, CC, CC, nullptr, p_qc, CHK, nullptr, nullptr);
    ln_kernel<0, 1, 0, 0><<<NTOK, 256>>>(p_y, nullptr, ffg, ffb, nullptr,
                                         nullptr, p_hnh, p_hnl, NTOK);
    hgemmP<2, CC, CC><<<hp_grid(NTOK, 2 * CC), 128, HP_SMEM>>>(p_hnh, p_hnl, p_W1h, p_W1l,
        nullptr, p_s1h, p_s1l, NTOK, 2 * CC, CC, b1, nullptr, 0, nullptr, nullptr);
    hgemmP<0, 2 * CC, 2 * CC><<<hp_grid(NTOK, CC), 128, HP_SMEM>>>(p_s1h, p_s1l, p_W2h, p_W2l,
        p_zp, nullptr, nullptr, NTOK, CC, 2 * CC, b2, p_y, 0, nullptr, nullptr);
    ln_kernel<1, 1, 0, 0><<<NTOK, 256>>>(p_ztt, p_zp, tng, tnb, scale,
                                         nullptr, p_rNsh, p_rNsl, NTOK);
    hgemmP<4, CC, CC><<<hp_grid(NTOK, DP), 128, HP_SMEM>>>(p_rNsh, p_rNsl, p_Wdh, p_Wdl,
        p_rD, p_rDh, p_rDl, NTOK, DP, CC, p_bdp, nullptr, 0, nullptr, nullptr);
    for (int st = 0; st < NBQ; st++) {
        const __half* Ahp = (st == 0) ? p_rDh : p_resh;
        const __half* Alp = (st == 0) ? p_rDl : p_resl;
        const float* Rin = (st == 0) ? p_rD : p_res;
        hgemmP<3, DP, DD><<<hp_grid(NTOK, NEQ), 128, HP_SMEM>>>(Ahp, Alp,
            p_bkh + (size_t)st * NEQ * DD, p_bkl + (size_t)st * NEQ * DD,
            nullptr, nullptr, nullptr, NTOK, NEQ, DD, nullptr, nullptr, 0,
            p_cn + (size_t)st * NEQ, p_keys);
        rvq_update3<<<NTOK, DD>>>(p_keys, books + (size_t)st * NEQ * DD,
                                  Rin, p_res, p_resh, p_resl,
                                  p_qDv, p_qDh, p_qDl,
                                  st == 0 ? 1 : 0, st == NBQ - 1 ? 1 : 0);
    }
    hgemmP<0, DP, DD><<<hp_grid(NTOK, CC), 128, HP_SMEM>>>(p_qDh, p_qDl, p_Wuh, p_Wul,
        p_zh, nullptr, nullptr, NTOK, CC, DD, bu, p_zp, 0, nullptr, nullptr);

    // ---- pass B ----
    ln_kernel<0, 2, 2, 1><<<M2, 256>>>(p_zh, nullptr, ln_q_g, ln_q_b, nullptr,
                                       p_q0n, p_q0nh, p_q0nl, M2);
    hgemmP<0, CC, CC><<<hp_grid(M2, CC), 128, HP_SMEM>>>(p_q0nh, p_q0nl, p_Wqh, p_Wql,
        p_Q0, nullptr, nullptr, M2, CC, CC, nullptr, nullptr, 0, nullptr, nullptr);
    attn_b<<<dim3(M2, HH), 128>>>(p_KVb, p_Q0, p_c0h, p_c0l);
    hgemmP<0, CC, CC><<<hp_grid(M2, CC), 128, HP_SMEM>>>(p_c0h, p_c0l, p_Woh, p_Wol,
        p_y0, nullptr, nullptr, M2, CC, CC, nullptr, p_q0n, 0, nullptr, nullptr);
    ln_kernel<0, 1, 0, 0><<<M2, 256>>>(p_y0, nullptr, ffg, ffb, nullptr,
                                       nullptr, p_hn0h, p_hn0l, M2);
    hgemmP<2, CC, CC><<<hp_grid(M2, 2 * CC), 128, HP_SMEM>>>(p_hn0h, p_hn0l, p_W1h, p_W1l,
        nullptr, p_g10h, p_g10l, M2, 2 * CC, CC, b1, nullptr, 0, nullptr, nullptr);
    hgemmP<0, 2 * CC, 2 * CC><<<hp_grid(M2, CC), 128, HP_SMEM>>>(p_g10h, p_g10l, p_W2h, p_W2l,
        p_z0, nullptr, nullptr, M2, CC, 2 * CC, b2, p_y0, 0, nullptr, nullptr);
    ln_kernel<1, 1, 0, 2><<<M2, 256>>>(p_ztt, p_z0, tng, tnb, scale,
                                       nullptr, p_rNsh, p_rNsl, M2);
    hgemmP<4, CC, CC><<<hp_grid(M2, DP), 128, HP_SMEM>>>(p_rNsh, p_rNsl, p_Wdh, p_Wdl,
        p_rD0, p_rD0h, p_rD0l, M2, DP, CC, p_bdp, nullptr, 0, nullptr, nullptr);
    for (int st = 0; st < NBQ; st++) {
        const __half* Ahp = (st == 0) ? p_rD0h : p_re0h;
        const __half* Alp = (st == 0) ? p_rD0l : p_re0l;
        const float* Rin = (st == 0) ? p_rD0 : p_res0;
        hgemmP<3, DP, DD><<<hp_grid(M2, NEQ), 128, HP_SMEM>>>(Ahp, Alp,
            p_bkh + (size_t)st * NEQ * DD, p_bkl + (size_t)st * NEQ * DD,
            nullptr, nullptr, nullptr, M2, NEQ, DD, nullptr, nullptr, 0,
            p_cn + (size_t)st * NEQ, p_keys);
        rvq_update3<<<M2, DD>>>(p_keys, books + (size_t)st * NEQ * DD,
                                Rin, p_res0, p_re0h, p_re0l,
                                p_qD0, p_qD0h, p_qD0l,
                                st == 0 ? 1 : 0, st == NBQ - 1 ? 1 : 0);
    }
    hgemmP<0, DP, DD><<<hp_grid(M2, CC), 128, HP_SMEM>>>(p_qD0h, p_qD0l, p_Wuh, p_Wul,
        p_zh0, nullptr, nullptr, M2, CC, DD, bu, p_z0, 0, nullptr, nullptr);
    scatter_rows16<<<M2, 256>>>(p_zh0, p_zh, CC, CC);
    scatter_rows16<<<M2, 128>>>(p_rD0, p_rD, DD, DP);

    // ---- outputs ----
    transpose_tc_to_ct<1><<<dim3(TT / 32, CC / 32, BB), dim3(32, 8)>>>(p_zh, o_y, CC, TT, CC);
    if ((size_t)out_size >= (size_t)BB * CC * TT + (size_t)BB * DD * TT)
        transpose_tc_to_ct<0><<<dim3(TT / 32, DD / 32, BB), dim3(32, 8)>>>(p_rD, o_r, DD, TT, DP);
}

// round 14
// speedup vs baseline: 1.0287x; 1.0043x over previous
#include <cuda_runtime.h>
#include <cuda_fp16.h>
#include <math.h>
#include <stdint.h>

// ---------------- problem constants ----------------
#define BB   16
#define CC   1024
#define TT   2048
#define DD   96
#define DP   128                 // padded D stride
#define NBQ  4
#define NEQ  2048
#define HH   8
#define CHK  16
#define NCHK 128
#define NTOK 32768
#define M2   2048
#define DH   128

typedef unsigned long long u64;

// ---------------- fp32 scratch ----------------
__device__ float g_KVb[(size_t)NTOK*2*CC];
__device__ float g_y  [(size_t)NTOK*CC];
__device__ float g_zp [(size_t)NTOK*CC];
__device__ float g_zh [(size_t)NTOK*CC];
__device__ float g_rD [(size_t)NTOK*DP];
__device__ float g_res[(size_t)NTOK*DP];
__device__ float g_qDv[(size_t)NTOK*DP];
__device__ u64   g_keys[(size_t)NTOK];

__device__ float g_q0n [(size_t)M2*CC];
__device__ float g_Q0  [(size_t)M2*CC];
__device__ float g_y0  [(size_t)M2*CC];
__device__ float g_z0  [(size_t)M2*CC];
__device__ float g_zh0 [(size_t)M2*CC];
__device__ float g_rD0 [(size_t)M2*DP];
__device__ float g_res0[(size_t)M2*DP];
__device__ float g_qD0 [(size_t)M2*DP];

__device__ float g_qc  [(size_t)CHK*CC];
__device__ float g_Qc  [(size_t)CHK*CC];
__device__ float g_cn  [(size_t)NBQ*NEQ];
__device__ float g_bdp [DP];

// ---------------- half hi/lo scratch ----------------
__device__ __half g_kvnh[(size_t)NTOK*CC], g_kvnl[(size_t)NTOK*CC];
__device__ __half g_ctxh[(size_t)NTOK*CC], g_ctxl[(size_t)NTOK*CC];
__device__ __half g_hnh [(size_t)NTOK*CC], g_hnl [(size_t)NTOK*CC];
__device__ __half g_s1h [(size_t)NTOK*2*CC], g_s1l [(size_t)NTOK*2*CC];
__device__ __half g_rNsh[(size_t)NTOK*CC], g_rNsl[(size_t)NTOK*CC];
__device__ __half g_rDh [(size_t)NTOK*DP], g_rDl [(size_t)NTOK*DP];
__device__ __half g_resh[(size_t)NTOK*DP], g_resl[(size_t)NTOK*DP];
__device__ __half g_qDh [(size_t)NTOK*DP], g_qDl [(size_t)NTOK*DP];

__device__ __half g_q0nh[(size_t)M2*CC], g_q0nl[(size_t)M2*CC];
__device__ __half g_c0h [(size_t)M2*CC], g_c0l [(size_t)M2*CC];
__device__ __half g_hn0h[(size_t)M2*CC], g_hn0l[(size_t)M2*CC];
__device__ __half g_g10h[(size_t)M2*2*CC], g_g10l[(size_t)M2*2*CC];
__device__ __half g_rD0h[(size_t)M2*DP], g_rD0l[(size_t)M2*DP];
__device__ __half g_re0h[(size_t)M2*DP], g_re0l[(size_t)M2*DP];
__device__ __half g_qD0h[(size_t)M2*DP], g_qD0l[(size_t)M2*DP];

// split weights [N,K]
__device__ __half g_Wkvh[(size_t)2*CC*CC], g_Wkvl[(size_t)2*CC*CC];
__device__ __half g_Wqh[(size_t)CC*CC], g_Wql[(size_t)CC*CC];
__device__ __half g_Woh[(size_t)CC*CC], g_Wol[(size_t)CC*CC];
__device__ __half g_W1h[(size_t)2*CC*CC], g_W1l[(size_t)2*CC*CC];
__device__ __half g_W2h[(size_t)CC*2*CC], g_W2l[(size_t)CC*2*CC];
__device__ __half g_Wdh[(size_t)DP*CC], g_Wdl[(size_t)DP*CC];
__device__ __half g_Wuh[(size_t)CC*DD], g_Wul[(size_t)CC*DD];
__device__ __half g_bkh[(size_t)NBQ*NEQ*DD], g_bkl[(size_t)NBQ*NEQ*DD];

__device__ __forceinline__ uint32_t smem_u32(const void* p) {
    uint32_t a;
    asm("{ .reg .u64 t; cvta.to.shared.u64 t, %1; cvt.u32.u64 %0, t; }" : "=r"(a) : "l"(p));
    return a;
}
__device__ __forceinline__ void mma16816(float* c, const uint32_t* a, const uint32_t* b) {
    asm volatile(
        "mma.sync.aligned.m16n8k16.row.col.f32.f16.f16.f32 "
        "{%0,%1,%2,%3}, {%4,%5,%6,%7}, {%8,%9}, {%0,%1,%2,%3};"
        : "+f"(c[0]), "+f"(c[1]), "+f"(c[2]), "+f"(c[3])
        : "r"(a[0]), "r"(a[1]), "r"(a[2]), "r"(a[3]), "r"(b[0]), "r"(b[1]));
}
__device__ __forceinline__ void ldmat4(uint32_t* r, uint32_t addr) {
    asm volatile("ldmatrix.sync.aligned.m8n8.x4.shared.b16 {%0,%1,%2,%3}, [%4];"
                 : "=r"(r[0]), "=r"(r[1]), "=r"(r[2]), "=r"(r[3]) : "r"(addr));
}
__device__ __forceinline__ void cp16(uint32_t dst, const void* src) {
    asm volatile("cp.async.cg.shared.global [%0], [%1], 16;\n" :: "r"(dst), "l"(src));
}
__device__ __forceinline__ void cpa_commit() { asm volatile("cp.async.commit_group;\n"); }
#define CPA_WAIT2() asm volatile("cp.async.wait_group 2;\n")
__device__ __forceinline__ void cpa_wait0() { asm volatile("cp.async.wait_group 0;\n"); }

// swizzled smem address: 128 rows x 64B, chunk-XOR swizzle
__device__ __forceinline__ uint32_t sw_addr(int row, int q) {
    return (uint32_t)(row * 64 + ((q ^ ((row >> 1) & 3)) << 4));
}

__device__ __forceinline__ float pe_val(int c, int t) {
    int ii = c >> 1;
    float div = expf((float)(2 * ii) * (-9.210340371976184f / (float)CC));
    float ang = (float)t * div;
    return (c & 1) ? cosf(ang) : sinf(ang);
}

// ---------------- split-input 3xFP16 GEMM: 128x128 tile, 128 thr, 3-stage, occ 2 ----
#define HP_STAGE 32768
#define HP_SMEM  (3 * HP_STAGE)

template <int EPI, int LDA, int LDB>
__global__ __launch_bounds__(128, 2) void hgemmP(
    const __half* __restrict__ Ah, const __half* __restrict__ Al,
    const __half* __restrict__ Bh, const __half* __restrict__ Bl,
    float* __restrict__ Co, __half* __restrict__ Oh, __half* __restrict__ Ol,
    int M, int N, int K,
    const float* __restrict__ bias, const float* __restrict__ add, int addPeriod,
    const float* __restrict__ cn, u64* __restrict__ keys) {
    extern __shared__ char sm[];
    const uint32_t sb = smem_u32(sm);
    const int tid = threadIdx.x;
    const int wid = tid >> 5, lane = tid & 31;
    const int wm = wid >> 1, wn = wid & 1;
    const int bm = blockIdx.y * 128, bn = blockIdx.x * 128;
    const int g = lane >> 2, tg = lane & 3;
    const int nt = K / 32;

    float acc[4][8][4];
#pragma unroll
    for (int i = 0; i < 4; i++)
#pragma unroll
        for (int j = 0; j < 8; j++)
#pragma unroll
            for (int q = 0; q < 4; q++) acc[i][j][q] = 0.f;

    const int lrow = (lane & 7) + ((lane >> 3) & 1) * 8;
    const int lq   = (lane >> 4) & 1;
    const int brow = (lane & 7) + ((lane >> 4) ? 8 : 0);
    const int bq   = (lane >> 3) & 1;

#define HP_LOAD(T) do {                                                         \
    int _t = (T);                                                               \
    if (_t < nt) {                                                              \
        uint32_t d0 = sb + (_t % 3) * HP_STAGE;                                 \
        _Pragma("unroll")                                                       \
        for (int j = 0; j < 16; j++) {                                          \
            int c = tid + j * 128;                                              \
            int mat = c >> 9;                                                   \
            int cc = c & 511;                                                   \
            int row = cc >> 2, q = cc & 3;                                      \
            const __half* src;                                                  \
            if (mat == 0)      src = Ah + (size_t)(bm + row) * LDA + _t * 32 + q * 8; \
            else if (mat == 1) src = Al + (size_t)(bm + row) * LDA + _t * 32 + q * 8; \
            else if (mat == 2) src = Bh + (size_t)(bn + row) * LDB + _t * 32 + q * 8; \
            else               src = Bl + (size_t)(bn + row) * LDB + _t * 32 + q * 8; \
            cp16(d0 + mat * 8192 + sw_addr(row, q), src);                       \
        }                                                                       \
    }                                                                           \
    cpa_commit();                                                               \
} while (0)

    HP_LOAD(0);
    HP_LOAD(1);
    HP_LOAD(2);

    for (int t = 0; t < nt; t++) {
        CPA_WAIT2();
        __syncthreads();
        const uint32_t tb = sb + (t % 3) * HP_STAGE;
#pragma unroll
        for (int ks = 0; ks < 2; ks++) {
            uint32_t ah[4][4], al[4][4];
#pragma unroll
            for (int mt = 0; mt < 4; mt++) {
                int row = wm * 64 + mt * 16 + lrow;
                uint32_t ad = tb + sw_addr(row, ks * 2 + lq);
                ldmat4(ah[mt], ad);
                ldmat4(al[mt], ad + 8192);
            }
            uint32_t bf[4][4];
#pragma unroll
            for (int p = 0; p < 4; p++) {
                int row = wn * 64 + p * 16 + brow;
                uint32_t bd = tb + 16384 + sw_addr(row, ks * 2 + bq);
                ldmat4(bf[p], bd);
            }
#pragma unroll
            for (int mt = 0; mt < 4; mt++)
#pragma unroll
                for (int p = 0; p < 4; p++) {
                    mma16816(acc[mt][2 * p],     ah[mt], &bf[p][0]);
                    mma16816(acc[mt][2 * p + 1], ah[mt], &bf[p][2]);
                    mma16816(acc[mt][2 * p],     al[mt], &bf[p][0]);
                    mma16816(acc[mt][2 * p + 1], al[mt], &bf[p][2]);
                }
#pragma unroll
            for (int p = 0; p < 4; p++) {
                int row = wn * 64 + p * 16 + brow;
                uint32_t bd = tb + 24576 + sw_addr(row, ks * 2 + bq);
                ldmat4(bf[p], bd);
            }
#pragma unroll
            for (int mt = 0; mt < 4; mt++)
#pragma unroll
                for (int p = 0; p < 4; p++) {
                    mma16816(acc[mt][2 * p],     ah[mt], &bf[p][0]);
                    mma16816(acc[mt][2 * p + 1], ah[mt], &bf[p][2]);
                }
        }
        __syncthreads();
        HP_LOAD(t + 3);
    }
#undef HP_LOAD

    if (EPI == 3) {
#pragma unroll
        for (int mt = 0; mt < 4; mt++) {
            int m0 = bm + wm * 64 + mt * 16 + g;
            int m1 = m0 + 8;
            u64 b0 = 0ull, b1 = 0ull;
#pragma unroll
            for (int nb = 0; nb < 8; nb++) {
                int n0 = bn + wn * 64 + nb * 8 + tg * 2;
                float s00 = acc[mt][nb][0] - cn[n0];
                float s01 = acc[mt][nb][1] - cn[n0 + 1];
                float s10 = acc[mt][nb][2] - cn[n0];
                float s11 = acc[mt][nb][3] - cn[n0 + 1];
                unsigned u;
                u = __float_as_uint(s00); u = (u & 0x80000000u) ? ~u : (u | 0x80000000u);
                u64 k = ((u64)u << 32) | (unsigned)(~n0);
                if (k > b0) b0 = k;
                u = __float_as_uint(s01); u = (u & 0x80000000u) ? ~u : (u | 0x80000000u);
                k = ((u64)u << 32) | (unsigned)(~(n0 + 1));
                if (k > b0) b0 = k;
                u = __float_as_uint(s10); u = (u & 0x80000000u) ? ~u : (u | 0x80000000u);
                k = ((u64)u << 32) | (unsigned)(~n0);
                if (k > b1) b1 = k;
                u = __float_as_uint(s11); u = (u & 0x80000000u) ? ~u : (u | 0x80000000u);
                k = ((u64)u << 32) | (unsigned)(~(n0 + 1));
                if (k > b1) b1 = k;
            }
#pragma unroll
            for (int o = 1; o < 4; o <<= 1) {
                u64 t0 = __shfl_xor_sync(0xffffffffu, b0, o);
                u64 t1 = __shfl_xor_sync(0xffffffffu, b1, o);
                if (t0 > b0) b0 = t0;
                if (t1 > b1) b1 = t1;
            }
            if (tg == 0) {
                atomicMax(&keys[m0], b0);
                atomicMax(&keys[m1], b1);
            }
        }
    } else {
#pragma unroll
        for (int mt = 0; mt < 4; mt++) {
            int m0 = bm + wm * 64 + mt * 16 + g;
            int m1 = m0 + 8;
            const float* add0 = (EPI == 0 && add)
                ? add + (size_t)((addPeriod > 0) ? (m0 % addPeriod) : m0) * N : nullptr;
            const float* add1 = (EPI == 0 && add)
                ? add + (size_t)((addPeriod > 0) ? (m1 % addPeriod) : m1) * N : nullptr;
#pragma unroll
            for (int nb = 0; nb < 8; nb++) {
                int n0 = bn + wn * 64 + nb * 8 + tg * 2;
                float v0 = acc[mt][nb][0], v1 = acc[mt][nb][1];
                float v2 = acc[mt][nb][2], v3 = acc[mt][nb][3];
                if (bias) {
                    float c0 = bias[n0], c1 = bias[n0 + 1];
                    v0 += c0; v1 += c1; v2 += c0; v3 += c1;
                }
                if (EPI == 0) {
                    if (add0) { v0 += add0[n0]; v1 += add0[n0 + 1]; }
                    if (add1) { v2 += add1[n0]; v3 += add1[n0 + 1]; }
                    *(float2*)(Co + (size_t)m0 * N + n0) = make_float2(v0, v1);
                    *(float2*)(Co + (size_t)m1 * N + n0) = make_float2(v2, v3);
                } else if (EPI == 4) {
                    *(float2*)(Co + (size_t)m0 * N + n0) = make_float2(v0, v1);
                    *(float2*)(Co + (size_t)m1 * N + n0) = make_float2(v2, v3);
                    __half2 h0 = __floats2half2_rn(v0, v1);
                    float2 f0 = __half22float2(h0);
                    __half2 l0 = __floats2half2_rn(v0 - f0.x, v1 - f0.y);
                    __half2 h1 = __floats2half2_rn(v2, v3);
                    float2 f1 = __half22float2(h1);
                    __half2 l1 = __floats2half2_rn(v2 - f1.x, v3 - f1.y);
                    *(__half2*)(Oh + (size_t)m0 * N + n0) = h0;
                    *(__half2*)(Ol + (size_t)m0 * N + n0) = l0;
                    *(__half2*)(Oh + (size_t)m1 * N + n0) = h1;
                    *(__half2*)(Ol + (size_t)m1 * N + n0) = l1;
                } else {  // EPI == 2
                    v0 = 0.5f * v0 * (1.0f + erff(v0 * 0.70710678118654752f));
                    v1 = 0.5f * v1 * (1.0f + erff(v1 * 0.70710678118654752f));
                    v2 = 0.5f * v2 * (1.0f + erff(v2 * 0.70710678118654752f));
                    v3 = 0.5f * v3 * (1.0f + erff(v3 * 0.70710678118654752f));
                    __half2 h0 = __floats2half2_rn(v0, v1);
                    float2 f0 = __half22float2(h0);
                    __half2 l0 = __floats2half2_rn(v0 - f0.x, v1 - f0.y);
                    __half2 h1 = __floats2half2_rn(v2, v3);
                    float2 f1 = __half22float2(h1);
                    __half2 l1 = __floats2half2_rn(v2 - f1.x, v3 - f1.y);
                    *(__half2*)(Oh + (size_t)m0 * N + n0) = h0;
                    *(__half2*)(Ol + (size_t)m0 * N + n0) = l0;
                    *(__half2*)(Oh + (size_t)m1 * N + n0) = h1;
                    *(__half2*)(Ol + (size_t)m1 * N + n0) = l1;
                }
            }
        }
    }
}

// ---------------- setup kernels ----------------
__global__ void prep_books(const float* __restrict__ books, float* __restrict__ cn,
                           __half* __restrict__ bh, __half* __restrict__ bl) {
    int i = blockIdx.x * 256 + threadIdx.x;
    if (i >= NBQ * NEQ) return;
    const float* src = books + (size_t)i * DD;
    float s = 0.f;
    for (int d = 0; d < DD; d++) {
        float v = src[d];
        s += v * v;
        __half h = __float2half_rn(v);
        bh[(size_t)i * DD + d] = h;
        bl[(size_t)i * DD + d] = __float2half_rn(v - __half2float(h));
    }
    cn[i] = 0.5f * s;
}

__global__ void prep_bd(const float* __restrict__ bd, float* __restrict__ bdp) {
    int i = threadIdx.x;
    bdp[i] = (i < DD) ? bd[i] : 0.0f;
}

__global__ void split_f32(const float* __restrict__ src, __half* __restrict__ h,
                          __half* __restrict__ l, int n) {
    int i = blockIdx.x * 256 + threadIdx.x;
    if (i >= n) return;
    float v = src[i];
    __half hi = __float2half_rn(v);
    h[i] = hi;
    l[i] = __float2half_rn(v - __half2float(hi));
}

// ---------------- transposes ----------------
__global__ void transpose_split2(const float* __restrict__ inA, __half* __restrict__ ohA,
                                 __half* __restrict__ olA,
                                 const float* __restrict__ inB, __half* __restrict__ ohB,
                                 __half* __restrict__ olB, int Cdim, int Tdim) {
    __shared__ float tile[32][33];
    int which = blockIdx.z;
    const float* in = which ? inB : inA;
    __half* oh = which ? ohB : ohA;
    __half* ol = which ? olB : olA;
    int c0 = blockIdx.y * 32, t0 = blockIdx.x * 32;
    int x = threadIdx.x, y = threadIdx.y;
    for (int i = 0; i < 32; i += 8)
        tile[y + i][x] = in[(size_t)(c0 + y + i) * Tdim + t0 + x];
    __syncthreads();
    for (int i = 0; i < 32; i += 8) {
        float v = tile[x][y + i];
        __half h = __float2half_rn(v);
        size_t o = (size_t)(t0 + y + i) * Cdim + c0 + x;
        oh[o] = h;
        ol[o] = __float2half_rn(v - __half2float(h));
    }
}

template <int NANFIX>
__global__ void transpose_tc_to_ct(const float* __restrict__ in, float* __restrict__ out,
                                   int Cdim, int Tdim, int srcLd) {
    __shared__ float tile[32][33];
    int b = blockIdx.z;
    int c0 = blockIdx.y * 32, t0 = blockIdx.x * 32;
    int x = threadIdx.x, y = threadIdx.y;
    for (int i = 0; i < 32; i += 8)
        tile[y + i][x] = in[((size_t)b * Tdim + t0 + y + i) * srcLd + c0 + x];
    __syncthreads();
    for (int i = 0; i < 32; i += 8) {
        float v = tile[x][y + i];
        if (NANFIX) { if (!isfinite(v)) v = 0.0f; }
        out[((size_t)b * Cdim + c0 + y + i) * Tdim + t0 + x] = v;
    }
}

// ---------------- LN reading directly from (B,C,T) layout ----------------
// 8 tokens per block (one warp each); cooperative tile load 1024 x 8.
// GATHER 0: token index m = blockIdx.x*8 + warp over B*T (b = m/TT, t = m%TT)
// GATHER 1: m over M2 rows; b = m/NCHK, t = (m%NCHK)*16 (chunk start)
// in1 (optional) is token-major [m*CC + c].
template <int POST, int PE, int GATHER>
__global__ __launch_bounds__(256) void ln_ct(
    const float* __restrict__ ct, const float* __restrict__ in1,
    const float* __restrict__ gamma, const float* __restrict__ beta,
    const float* __restrict__ scale_ptr,
    __half* __restrict__ oh, __half* __restrict__ ol) {
    __shared__ float tile[CC * 9];
    const int tid = threadIdx.x;
    const int m8 = blockIdx.x * 8;
#pragma unroll
    for (int i = 0; i < 32; i++) {
        int idx = tid + i * 256;
        int c = idx >> 3, x = idx & 7;
        int m = m8 + x;
        size_t src;
        if (GATHER) {
            int b = m / NCHK, t = (m % NCHK) * 16;
            src = ((size_t)b * CC + c) * TT + t;
        } else {
            int b = m >> 11, t = m & (TT - 1);   // TT = 2048
            src = ((size_t)b * CC + c) * TT + t;
        }
        tile[c * 9 + x] = ct[src];
    }
    __syncthreads();

    const int w = tid >> 5, lane = tid & 31;
    const int m = m8 + w;
    float x[32];
    float s = 0.f;
#pragma unroll
    for (int k = 0; k < 32; k++) {
        int c = lane + k * 32;
        float v = tile[c * 9 + w];
        if (in1) v -= in1[(size_t)m * CC + c];
        if (PE == 1) v += pe_val(c, m & 15);
        x[k] = v;
        s += v;
    }
#pragma unroll
    for (int o = 16; o; o >>= 1) s += __shfl_xor_sync(0xffffffffu, s, o);
    float mean = s * (1.0f / (float)CC);
    float vs = 0.f;
#pragma unroll
    for (int k = 0; k < 32; k++) { float d = x[k] - mean; vs += d * d; }
#pragma unroll
    for (int o = 16; o; o >>= 1) vs += __shfl_xor_sync(0xffffffffu, vs, o);
    float rstd = rsqrtf(vs * (1.0f / (float)CC) + 1e-5f);
    float sc = 1.0f;
    if (POST == 1) {
        float t = scale_ptr[0];
        sc = fminf(fmaxf(t, 0.005f), 0.5f);
    }
#pragma unroll
    for (int k = 0; k < 32; k++) {
        int c = lane + k * 32;
        float yv = (x[k] - mean) * rstd * gamma[c] + beta[c];
        if (POST == 1) yv = tanhf(yv) * sc;
        __half h = __float2half_rn(yv);
        oh[(size_t)m * CC + c] = h;
        ol[(size_t)m * CC + c] = __float2half_rn(yv - __half2float(h));
    }
}

// ---------------- token-major LayerNorm ----------------
// SRC 0: in0 row m; 1: carry (row m*16-1, zero if m%128==0)
template <int POST, int SPLIT, int PE, int SRC>
__global__ __launch_bounds__(256) void ln_kernel(
    const float* __restrict__ in0, const float* __restrict__ in1,
    const float* __restrict__ gamma, const float* __restrict__ beta,
    const float* __restrict__ scale_ptr, float* __restrict__ out,
    __half* __restrict__ oh, __half* __restrict__ ol, int Mrows) {
    int m = blockIdx.x;
    if (m >= Mrows) return;
    int tid = threadIdx.x;
    int lane = tid & 31, warp = tid >> 5;
    __shared__ float red[8];
    float x[4];
#pragma unroll
    for (int k = 0; k < 4; k++) {
        int c = tid + k * 256;
        float v;
        if (SRC == 1) {
            v = (m & (NCHK - 1)) ? in0[((size_t)m * 16 - 1) * CC + c] : 0.0f;
        } else {
            v = in0 ? in0[(size_t)m * CC + c] : 0.0f;
        }
        if (in1) v -= in1[(size_t)m * CC + c];
        if (PE == 1) v += pe_val(c, m & 15);
        else if (PE == 2) v += pe_val(c, 0);
        x[k] = v;
    }
    float s = x[0] + x[1] + x[2] + x[3];
#pragma unroll
    for (int o = 16; o; o >>= 1) s += __shfl_xor_sync(0xffffffffu, s, o);
    if (lane == 0) red[warp] = s;
    __syncthreads();
    float mean;
    {
        float t = (lane < 8) ? red[lane] : 0.f;
#pragma unroll
        for (int o = 4; o; o >>= 1) t += __shfl_xor_sync(0xffffffffu, t, o);
        mean = __shfl_sync(0xffffffffu, t, 0) * (1.0f / (float)CC);
    }
    float vs = 0.f;
#pragma unroll
    for (int k = 0; k < 4; k++) { float d = x[k] - mean; vs += d * d; }
#pragma unroll
    for (int o = 16; o; o >>= 1) vs += __shfl_xor_sync(0xffffffffu, vs, o);
    __syncthreads();
    if (lane == 0) red[warp] = vs;
    __syncthreads();
    float var;
    {
        float t = (lane < 8) ? red[lane] : 0.f;
#pragma unroll
        for (int o = 4; o; o >>= 1) t += __shfl_xor_sync(0xffffffffu, t, o);
        var = __shfl_sync(0xffffffffu, t, 0) * (1.0f / (float)CC);
    }
    float rstd = rsqrtf(var + 1e-5f);
    float sc = 1.0f;
    if (POST == 1) {
        float t = scale_ptr[0];
        sc = fminf(fmaxf(t, 0.005f), 0.5f);
    }
#pragma unroll
    for (int k = 0; k < 4; k++) {
        int c = tid + k * 256;
        float yv = (x[k] - mean) * rstd * gamma[c] + beta[c];
        if (POST == 1) yv = tanhf(yv) * sc;
        if (SPLIT != 1) out[(size_t)m * CC + c] = yv;
        if (SPLIT >= 1) {
            __half h = __float2half_rn(yv);
            oh[(size_t)m * CC + c] = h;
            ol[(size_t)m * CC + c] = __float2half_rn(yv - __half2float(h));
        }
    }
}

// ---------------- f32x2 helpers (scalar GEMM for tiny Qc) ----------------
__device__ __forceinline__ u64 pack2(float x) {
    u64 r;
    asm("mov.b64 %0, {%1, %1};" : "=l"(r) : "f"(x));
    return r;
}
__device__ __forceinline__ float2 unpack2(u64 v) {
    float2 f;
    asm("mov.b64 {%0, %1}, %2;" : "=f"(f.x), "=f"(f.y) : "l"(v));
    return f;
}
#define FFMA2(d, a, b) asm("fma.rn.f32x2 %0, %1, %2, %0;" : "+l"(d) : "l"(a), "l"(b))

__device__ __forceinline__ void cpa16p(void* dst, const void* src, bool pred) {
    unsigned int d = (unsigned int)__cvta_generic_to_shared(dst);
    int sz = pred ? 16 : 0;
    asm volatile("cp.async.ca.shared.global [%0], [%1], 16, %2;\n" :: "r"(d), "l"(src), "r"(sz));
}

template <bool GUARD>
__global__ __launch_bounds__(256, 2) void sgemm2(
    const float* __restrict__ A, const float* __restrict__ Bm, float* __restrict__ Co,
    int M, int N, int K, const float* __restrict__ bias) {
    __shared__ __align__(16) float As[2][16][128];
    __shared__ __align__(16) float Bs[2][16][128];
    const int tid = threadIdx.x;
    const int bm = blockIdx.y * 128, bn = blockIdx.x * 128;
    const int tx = tid & 15, ty = tid >> 4;

    const int a_row  = tid >> 1;
    const int a_koff = (tid & 1) * 8;
    const int b_row  = tid >> 5;
    const int b_col  = (tid & 31) * 4;

    const bool a_ok = !GUARD || (bm + a_row < M);
    const bool b_ok = !GUARD || (bn + b_col < N);
    const float* a_src0 = A + (size_t)(GUARD ? (a_ok ? bm + a_row : 0) : (bm + a_row)) * K + a_koff;
    const float* b_src0 = Bm + (size_t)b_row * N + (GUARD ? (b_ok ? bn + b_col : 0) : (bn + b_col));
    const float* b_src1 = b_src0 + (size_t)8 * N;

    u64 acc2[8][4];
#pragma unroll
    for (int i = 0; i < 8; i++)
#pragma unroll
        for (int q = 0; q < 4; q++) acc2[i][q] = 0ull;

    float a_reg[8];
    const int nt = K / 16;

    {
        if (a_ok) {
            float4 v0 = *(const float4*)(a_src0);
            float4 v1 = *(const float4*)(a_src0 + 4);
            a_reg[0]=v0.x; a_reg[1]=v0.y; a_reg[2]=v0.z; a_reg[3]=v0.w;
            a_reg[4]=v1.x; a_reg[5]=v1.y; a_reg[6]=v1.z; a_reg[7]=v1.w;
        } else {
#pragma unroll
            for (int c = 0; c < 8; c++) a_reg[c] = 0.f;
        }
        cpa16p(&Bs[0][b_row][b_col],     b_src0, b_ok);
        cpa16p(&Bs[0][8 + b_row][b_col], b_src1, b_ok);
        cpa_commit();
#pragma unroll
        for (int c = 0; c < 8; c++) As[0][a_koff + c][a_row] = a_reg[c];
        cpa_wait0();
        __syncthreads();
    }

    int buf = 0;
    for (int t = 0; t < nt; t++) {
        const bool has_next = (t + 1 < nt);
        if (has_next) {
            const float* ap = a_src0 + (size_t)(t + 1) * 16;
            if (a_ok) {
                float4 v0 = *(const float4*)(ap);
                float4 v1 = *(const float4*)(ap + 4);
                a_reg[0]=v0.x; a_reg[1]=v0.y; a_reg[2]=v0.z; a_reg[3]=v0.w;
                a_reg[4]=v1.x; a_reg[5]=v1.y; a_reg[6]=v1.z; a_reg[7]=v1.w;
            }
            cpa16p(&Bs[buf ^ 1][b_row][b_col],     b_src0 + (size_t)(t + 1) * 16 * N, b_ok);
            cpa16p(&Bs[buf ^ 1][8 + b_row][b_col], b_src1 + (size_t)(t + 1) * 16 * N, b_ok);
            cpa_commit();
        }
#pragma unroll
        for (int kk = 0; kk < 16; kk++) {
            float4 a0 = *(const float4*)&As[buf][kk][ty * 8];
            float4 a1 = *(const float4*)&As[buf][kk][ty * 8 + 4];
            ulonglong2 bl = *(const ulonglong2*)&Bs[buf][kk][tx * 4];
            ulonglong2 bh = *(const ulonglong2*)&Bs[buf][kk][64 + tx * 4];
            float am[8] = {a0.x, a0.y, a0.z, a0.w, a1.x, a1.y, a1.z, a1.w};
#pragma unroll
            for (int i = 0; i < 8; i++) {
                u64 ai = pack2(am[i]);
                FFMA2(acc2[i][0], ai, bl.x);
                FFMA2(acc2[i][1], ai, bl.y);
                FFMA2(acc2[i][2], ai, bh.x);
                FFMA2(acc2[i][3], ai, bh.y);
            }
        }
        if (has_next) {
#pragma unroll
            for (int c = 0; c < 8; c++) As[buf ^ 1][a_koff + c][a_row] = a_reg[c];
            cpa_wait0();
            __syncthreads();
            buf ^= 1;
        }
    }

#pragma unroll
    for (int i = 0; i < 8; i++) {
        int m = bm + ty * 8 + i;
        if (GUARD && m >= M) continue;
#pragma unroll
        for (int q = 0; q < 4; q++) {
            float2 v2 = unpack2(acc2[i][q]);
            int n0 = bn + ((q < 2) ? (tx * 4 + q * 2) : (64 + tx * 4 + (q - 2) * 2));
#pragma unroll
            for (int h = 0; h < 2; h++) {
                int n = n0 + h;
                if (GUARD && n >= N) continue;
                float v = h ? v2.y : v2.x;
                if (bias) v += bias[n];
                Co[(size_t)m * N + n] = v;
            }
        }
    }
}

// ---------------- attention ----------------
__global__ __launch_bounds__(256) void attn_a(const float* __restrict__ KVb,
                                              const float* __restrict__ Qc,
                                              __half* __restrict__ ctxh,
                                              __half* __restrict__ ctxl) {
    int gb = blockIdx.x;
    int h = blockIdx.y;
    int tid = threadIdx.x;
    __shared__ float Ks[16][133], Vs[16][133], Qs[16][133];
    __shared__ float Ss[16][17];
    for (int i = tid; i < 16 * DH; i += 256) {
        int t = i >> 7, d = i & 127;
        size_t base = ((size_t)(gb * 16 + t)) * (2 * CC) + (size_t)h * DH + d;
        Ks[t][d] = KVb[base];
        Vs[t][d] = KVb[base + CC];
        Qs[t][d] = Qc[(size_t)t * CC + (size_t)h * DH + d];
    }
    __syncthreads();
    {
        int q = tid >> 4, k = tid & 15;
        float s = 0.f;
#pragma unroll 8
        for (int d = 0; d < DH; d++) s = fmaf(Qs[q][d], Ks[k][d], s);
        Ss[q][k] = s * 0.08838834764831845f;
    }
    __syncthreads();
    if (tid < 16) {
        float mx = -1e30f;
        for (int k = 0; k < 16; k++) mx = fmaxf(mx, Ss[tid][k]);
        float e[16], sum = 0.f;
        for (int k = 0; k < 16; k++) { e[k] = expf(Ss[tid][k] - mx); sum += e[k]; }
        float inv = 1.0f / sum;
        for (int k = 0; k < 16; k++) Ss[tid][k] = e[k] * inv;
    }
    __syncthreads();
    for (int i = tid; i < 16 * DH; i += 256) {
        int t = i >> 7, d = i & 127;
        float a = 0.f;
#pragma unroll
        for (int k = 0; k < 16; k++) a = fmaf(Ss[t][k], Vs[k][d], a);
        size_t o = ((size_t)(gb * 16 + t)) * CC + (size_t)h * DH + d;
        __half hh = __float2half_rn(a);
        ctxh[o] = hh;
        ctxl[o] = __float2half_rn(a - __half2float(hh));
    }
}

__global__ __launch_bounds__(128) void attn_b(const float* __restrict__ KVb,
                                              const float* __restrict__ Q0,
                                              __half* __restrict__ ctxh,
                                              __half* __restrict__ ctxl) {
    int p = blockIdx.x;
    int h = blockIdx.y;
    int tid = threadIdx.x;
    __shared__ float Ks[16][128], Vs[16][128], Qs[128];
    __shared__ float sc[16];
    for (int i = tid; i < 16 * DH; i += 128) {
        int t = i >> 7, d = i & 127;
        size_t base = ((size_t)(p * 16 + t)) * (2 * CC) + (size_t)h * DH + d;
        Ks[t][d] = KVb[base];
        Vs[t][d] = KVb[base + CC];
    }
    Qs[tid] = Q0[(size_t)p * CC + (size_t)h * DH + tid];
    __syncthreads();
    int w = tid >> 5, l = tid & 31;
    for (int k = w; k < 16; k += 4) {
        float s = Qs[l] * Ks[k][l] + Qs[l + 32] * Ks[k][l + 32] +
                  Qs[l + 64] * Ks[k][l + 64] + Qs[l + 96] * Ks[k][l + 96];
        for (int o = 16; o; o >>= 1) s += __shfl_xor_sync(0xffffffffu, s, o);
        if (l == 0) sc[k] = s * 0.08838834764831845f;
    }
    __syncthreads();
    if (tid == 0) {
        float mx = -1e30f;
        for (int k = 0; k < 16; k++) mx = fmaxf(mx, sc[k]);
        float e[16], sum = 0.f;
        for (int k = 0; k < 16; k++) { e[k] = expf(sc[k] - mx); sum += e[k]; }
        float inv = 1.0f / sum;
        for (int k = 0; k < 16; k++) sc[k] = e[k] * inv;
    }
    __syncthreads();
    float a = 0.f;
#pragma unroll
    for (int k = 0; k < 16; k++) a = fmaf(sc[k], Vs[k][tid], a);
    size_t o = (size_t)p * CC + (size_t)h * DH + tid;
    __half hh = __float2half_rn(a);
    ctxh[o] = hh;
    ctxl[o] = __float2half_rn(a - __half2float(hh));
}

// ---------------- RVQ update (padded stride DP; resets keys) ----------------
__global__ void rvq_update3(u64* __restrict__ keys,
                            const float* __restrict__ books_st,
                            const float* __restrict__ resid_in,
                            float* __restrict__ resid_out,
                            __half* __restrict__ resh, __half* __restrict__ resl,
                            float* __restrict__ qD,
                            __half* __restrict__ qDh, __half* __restrict__ qDl,
                            int firstStage, int lastStage) {
    int m = blockIdx.x;
    int d = threadIdx.x;   // 96 threads
    int idx = (int)(~(unsigned)(keys[m] & 0xffffffffu)) & (NEQ - 1);
    __syncthreads();
    if (d == 0) keys[m] = 0ull;
    float e = books_st[(size_t)idx * DD + d];
    float r = resid_in[(size_t)m * DP + d];
    float nr = r - e;
    resid_out[(size_t)m * DP + d] = nr;
    __half hh = __float2half_rn(nr);
    resh[(size_t)m * DP + d] = hh;
    resl[(size_t)m * DP + d] = __float2half_rn(nr - __half2float(hh));
    float q = firstStage ? e : (qD[(size_t)m * DP + d] + e);
    qD[(size_t)m * DP + d] = q;
    if (lastStage) {
        __half qh = __float2half_rn(q);
        qDh[(size_t)m * DP + d] = qh;
        qDl[(size_t)m * DP + d] = __float2half_rn(q - __half2float(qh));
    }
}

// ---------------- misc ----------------
__global__ void scatter_rows16(const float* __restrict__ in, float* __restrict__ out,
                               int count, int ld) {
    int p = blockIdx.x;
    for (int c = threadIdx.x; c < count; c += blockDim.x)
        out[((size_t)p * 16) * ld + c] = in[(size_t)p * ld + c];
}

// ---------------- host ----------------
static inline dim3 gemm_grid(int M, int N) { return dim3((N + 127) / 128, (M + 127) / 128); }
static inline dim3 hp_grid(int M, int N) { return dim3(N / 128, M / 128); }

extern "C" void kernel_launch(void* const* d_in, const int* in_sizes, int n_in,
                              void* d_out, int out_size) {
    const float* qa     = (const float*)d_in[0];
    const float* ztt    = (const float*)d_in[1];
    const float* ln_q_g = (const float*)d_in[2];
    const float* ln_q_b = (const float*)d_in[3];
    const float* ln_kv_g= (const float*)d_in[4];
    const float* ln_kv_b= (const float*)d_in[5];
    const float* Wq     = (const float*)d_in[6];
    const float* Wk     = (const float*)d_in[7];
    const float* Wv     = (const float*)d_in[8];
    const float* Wo     = (const float*)d_in[9];
    const float* ffg    = (const float*)d_in[10];
    const float* ffb    = (const float*)d_in[11];
    const float* W1     = (const float*)d_in[12];
    const float* b1     = (const float*)d_in[13];
    const float* W2     = (const float*)d_in[14];
    const float* b2     = (const float*)d_in[15];
    const float* tng    = (const float*)d_in[16];
    const float* tnb    = (const float*)d_in[17];
    const float* scale  = (const float*)d_in[18];
    const float* Wd     = (const float*)d_in[19];
    const float* bd     = (const float*)d_in[20];
    const float* Wu     = (const float*)d_in[21];
    const float* bu     = (const float*)d_in[22];
    const float* books  = (const float*)d_in[23];

    float* out = (float*)d_out;
    float* o_y = out;
    float* o_r = out + (size_t)BB * CC * TT;

#define SYMF(p, s) float* p; cudaGetSymbolAddress((void**)&p, s)
#define SYMH(p, s) __half* p; cudaGetSymbolAddress((void**)&p, s)
    SYMF(p_KVb, g_KVb);
    SYMF(p_y, g_y);     SYMF(p_zp, g_zp);   SYMF(p_zh, g_zh);
    SYMF(p_rD, g_rD);   SYMF(p_res, g_res); SYMF(p_qDv, g_qDv);
    SYMF(p_q0n, g_q0n); SYMF(p_Q0, g_Q0);
    SYMF(p_y0, g_y0);   SYMF(p_z0, g_z0);
    SYMF(p_zh0, g_zh0);
    SYMF(p_rD0, g_rD0); SYMF(p_res0, g_res0); SYMF(p_qD0, g_qD0);
    SYMF(p_qc, g_qc);   SYMF(p_Qc, g_Qc);
    SYMF(p_cn, g_cn);   SYMF(p_bdp, g_bdp);
    SYMH(p_kvnh, g_kvnh); SYMH(p_kvnl, g_kvnl);
    SYMH(p_ctxh, g_ctxh); SYMH(p_ctxl, g_ctxl);
    SYMH(p_hnh, g_hnh);   SYMH(p_hnl, g_hnl);
    SYMH(p_s1h, g_s1h);   SYMH(p_s1l, g_s1l);
    SYMH(p_rNsh, g_rNsh); SYMH(p_rNsl, g_rNsl);
    SYMH(p_rDh, g_rDh);   SYMH(p_rDl, g_rDl);
    SYMH(p_resh, g_resh); SYMH(p_resl, g_resl);
    SYMH(p_qDh, g_qDh);   SYMH(p_qDl, g_qDl);
    SYMH(p_q0nh, g_q0nh); SYMH(p_q0nl, g_q0nl);
    SYMH(p_c0h, g_c0h);   SYMH(p_c0l, g_c0l);
    SYMH(p_hn0h, g_hn0h); SYMH(p_hn0l, g_hn0l);
    SYMH(p_g10h, g_g10h); SYMH(p_g10l, g_g10l);
    SYMH(p_rD0h, g_rD0h); SYMH(p_rD0l, g_rD0l);
    SYMH(p_re0h, g_re0h); SYMH(p_re0l, g_re0l);
    SYMH(p_qD0h, g_qD0h); SYMH(p_qD0l, g_qD0l);
    SYMH(p_Wkvh, g_Wkvh); SYMH(p_Wkvl, g_Wkvl);
    SYMH(p_Wqh, g_Wqh); SYMH(p_Wql, g_Wql);
    SYMH(p_Woh, g_Woh); SYMH(p_Wol, g_Wol);
    SYMH(p_W1h, g_W1h); SYMH(p_W1l, g_W1l);
    SYMH(p_W2h, g_W2h); SYMH(p_W2l, g_W2l);
    SYMH(p_Wdh, g_Wdh); SYMH(p_Wdl, g_Wdl);
    SYMH(p_Wuh, g_Wuh); SYMH(p_Wul, g_Wul);
    SYMH(p_bkh, g_bkh); SYMH(p_bkl, g_bkl);
#undef SYMF
#undef SYMH
    u64* p_keys; cudaGetSymbolAddress((void**)&p_keys, g_keys);

    cudaFuncSetAttribute(hgemmP<0, CC, CC>, cudaFuncAttributeMaxDynamicSharedMemorySize, HP_SMEM);
    cudaFuncSetAttribute(hgemmP<2, CC, CC>, cudaFuncAttributeMaxDynamicSharedMemorySize, HP_SMEM);
    cudaFuncSetAttribute(hgemmP<0, 2 * CC, 2 * CC>, cudaFuncAttributeMaxDynamicSharedMemorySize, HP_SMEM);
    cudaFuncSetAttribute(hgemmP<4, CC, CC>, cudaFuncAttributeMaxDynamicSharedMemorySize, HP_SMEM);
    cudaFuncSetAttribute(hgemmP<3, DP, DD>, cudaFuncAttributeMaxDynamicSharedMemorySize, HP_SMEM);
    cudaFuncSetAttribute(hgemmP<0, DP, DD>, cudaFuncAttributeMaxDynamicSharedMemorySize, HP_SMEM);

    // ---- setup head; big KV GEMM early for ncu slot ----
    ln_ct<0, 1, 0><<<NTOK / 8, 256>>>(qa, nullptr, ln_kv_g, ln_kv_b, nullptr,
                                      p_kvnh, p_kvnl);                              // 1
    transpose_split2<<<dim3(32, 32, 2), dim3(32, 8)>>>(Wk, p_Wkvh, p_Wkvl,
                                                       Wv, p_Wkvh + (size_t)CC * CC,
                                                       p_Wkvl + (size_t)CC * CC, CC, CC); // 2
    hgemmP<0, CC, CC><<<hp_grid(NTOK, 2 * CC), 128, HP_SMEM>>>(p_kvnh, p_kvnl, p_Wkvh, p_Wkvl,
        p_KVb, nullptr, nullptr, NTOK, 2 * CC, CC, nullptr, nullptr, 0, nullptr, nullptr); // 3

    // ---- remaining setup ----
    prep_books<<<(NBQ * NEQ + 255) / 256, 256>>>(books, p_cn, p_bkh, p_bkl);
    prep_bd<<<1, DP>>>(bd, p_bdp);
    transpose_split2<<<dim3(32, 32, 2), dim3(32, 8)>>>(Wq, p_Wqh, p_Wql,
                                                       Wo, p_Woh, p_Wol, CC, CC);
    transpose_split2<<<dim3(64, 32, 1), dim3(32, 8)>>>(W1, p_W1h, p_W1l,
                                                       nullptr, nullptr, nullptr, CC, 2 * CC);
    transpose_split2<<<dim3(32, 64, 1), dim3(32, 8)>>>(W2, p_W2h, p_W2l,
                                                       nullptr, nullptr, nullptr, 2 * CC, CC);
    split_f32<<<(DD * CC + 255) / 256, 256>>>(Wd, p_Wdh, p_Wdl, DD * CC);
    split_f32<<<(CC * DD + 255) / 256, 256>>>(Wu, p_Wuh, p_Wul, CC * DD);
    ln_kernel<0, 0, 1, 0><<<CHK, 256>>>(nullptr, nullptr, ln_q_g, ln_q_b, nullptr,
                                        p_qc, nullptr, nullptr, CHK);
    sgemm2<true><<<gemm_grid(CHK, CC), 256>>>(p_qc, Wq, p_Qc, CHK, CC, CC, nullptr);
    cudaMemsetAsync(p_keys, 0, (size_t)NTOK * sizeof(u64), 0);

    // ---- pass A ----
    attn_a<<<dim3(M2, HH), 256>>>(p_KVb, p_Qc, p_ctxh, p_ctxl);
    hgemmP<0, CC, CC><<<hp_grid(NTOK, CC), 128, HP_SMEM>>>(p_ctxh, p_ctxl, p_Woh, p_Wol,
        p_y, nullptr, nullptr, NTOK, CC, CC, nullptr, p_qc, CHK, nullptr, nullptr);
    ln_kernel<0, 1, 0, 0><<<NTOK, 256>>>(p_y, nullptr, ffg, ffb, nullptr,
                                         nullptr, p_hnh, p_hnl, NTOK);
    hgemmP<2, CC, CC><<<hp_grid(NTOK, 2 * CC), 128, HP_SMEM>>>(p_hnh, p_hnl, p_W1h, p_W1l,
        nullptr, p_s1h, p_s1l, NTOK, 2 * CC, CC, b1, nullptr, 0, nullptr, nullptr);
    hgemmP<0, 2 * CC, 2 * CC><<<hp_grid(NTOK, CC), 128, HP_SMEM>>>(p_s1h, p_s1l, p_W2h, p_W2l,
        p_zp, nullptr, nullptr, NTOK, CC, 2 * CC, b2, p_y, 0, nullptr, nullptr);
    ln_ct<1, 0, 0><<<NTOK / 8, 256>>>(ztt, p_zp, tng, tnb, scale, p_rNsh, p_rNsl);
    hgemmP<4, CC, CC><<<hp_grid(NTOK, DP), 128, HP_SMEM>>>(p_rNsh, p_rNsl, p_Wdh, p_Wdl,
        p_rD, p_rDh, p_rDl, NTOK, DP, CC, p_bdp, nullptr, 0, nullptr, nullptr);
    for (int st = 0; st < NBQ; st++) {
        const __half* Ahp = (st == 0) ? p_rDh : p_resh;
        const __half* Alp = (st == 0) ? p_rDl : p_resl;
        const float* Rin = (st == 0) ? p_rD : p_res;
        hgemmP<3, DP, DD><<<hp_grid(NTOK, NEQ), 128, HP_SMEM>>>(Ahp, Alp,
            p_bkh + (size_t)st * NEQ * DD, p_bkl + (size_t)st * NEQ * DD,
            nullptr, nullptr, nullptr, NTOK, NEQ, DD, nullptr, nullptr, 0,
            p_cn + (size_t)st * NEQ, p_keys);
        rvq_update3<<<NTOK, DD>>>(p_keys, books + (size_t)st * NEQ * DD,
                                  Rin, p_res, p_resh, p_resl,
                                  p_qDv, p_qDh, p_qDl,
                                  st == 0 ? 1 : 0, st == NBQ - 1 ? 1 : 0);
    }
    hgemmP<0, DP, DD><<<hp_grid(NTOK, CC), 128, HP_SMEM>>>(p_qDh, p_qDl, p_Wuh, p_Wul,
        p_zh, nullptr, nullptr, NTOK, CC, DD, bu, p_zp, 0, nullptr, nullptr);

    // ---- pass B ----
    ln_kernel<0, 2, 2, 1><<<M2, 256>>>(p_zh, nullptr, ln_q_g, ln_q_b, nullptr,
                                       p_q0n, p_q0nh, p_q0nl, M2);
    hgemmP<0, CC, CC><<<hp_grid(M2, CC), 128, HP_SMEM>>>(p_q0nh, p_q0nl, p_Wqh, p_Wql,
        p_Q0, nullptr, nullptr, M2, CC, CC, nullptr, nullptr, 0, nullptr, nullptr);
    attn_b<<<dim3(M2, HH), 128>>>(p_KVb, p_Q0, p_c0h, p_c0l);
    hgemmP<0, CC, CC><<<hp_grid(M2, CC), 128, HP_SMEM>>>(p_c0h, p_c0l, p_Woh, p_Wol,
        p_y0, nullptr, nullptr, M2, CC, CC, nullptr, p_q0n, 0, nullptr, nullptr);
    ln_kernel<0, 1, 0, 0><<<M2, 256>>>(p_y0, nullptr, ffg, ffb, nullptr,
                                       nullptr, p_hn0h, p_hn0l, M2);
    hgemmP<2, CC, CC><<<hp_grid(M2, 2 * CC), 128, HP_SMEM>>>(p_hn0h, p_hn0l, p_W1h, p_W1l,
        nullptr, p_g10h, p_g10l, M2, 2 * CC, CC, b1, nullptr, 0, nullptr, nullptr);
    hgemmP<0, 2 * CC, 2 * CC><<<hp_grid(M2, CC), 128, HP_SMEM>>>(p_g10h, p_g10l, p_W2h, p_W2l,
        p_z0, nullptr, nullptr, M2, CC, 2 * CC, b2, p_y0, 0, nullptr, nullptr);
    ln_ct<1, 0, 1><<<M2 / 8, 256>>>(ztt, p_z0, tng, tnb, scale, p_rNsh, p_rNsl);
    hgemmP<4, CC, CC><<<hp_grid(M2, DP), 128, HP_SMEM>>>(p_rNsh, p_rNsl, p_Wdh, p_Wdl,
        p_rD0, p_rD0h, p_rD0l, M2, DP, CC, p_bdp, nullptr, 0, nullptr, nullptr);
    for (int st = 0; st < NBQ; st++) {
        const __half* Ahp = (st == 0) ? p_rD0h : p_re0h;
        const __half* Alp = (st == 0) ? p_rD0l : p_re0l;
        const float* Rin = (st == 0) ? p_rD0 : p_res0;
        hgemmP<3, DP, DD><<<hp_grid(M2, NEQ), 128, HP_SMEM>>>(Ahp, Alp,
            p_bkh + (size_t)st * NEQ * DD, p_bkl + (size_t)st * NEQ * DD,
            nullptr, nullptr, nullptr, M2, NEQ, DD, nullptr, nullptr, 0,
            p_cn + (size_t)st * NEQ, p_keys);
        rvq_update3<<<M2, DD>>>(p_keys, books + (size_t)st * NEQ * DD,
                                Rin, p_res0, p_re0h, p_re0l,
                                p_qD0, p_qD0h, p_qD0l,
                                st == 0 ? 1 : 0, st == NBQ - 1 ? 1 : 0);
    }
    hgemmP<0, DP, DD><<<hp_grid(M2, CC), 128, HP_SMEM>>>(p_qD0h, p_qD0l, p_Wuh, p_Wul,
        p_zh0, nullptr, nullptr, M2, CC, DD, bu, p_z0, 0, nullptr, nullptr);
    scatter_rows16<<<M2, 256>>>(p_zh0, p_zh, CC, CC);
    scatter_rows16<<<M2, 128>>>(p_rD0, p_rD, DD, DP);

    // ---- outputs ----
    transpose_tc_to_ct<1><<<dim3(TT / 32, CC / 32, BB), dim3(32, 8)>>>(p_zh, o_y, CC, TT, CC);
    if ((size_t)out_size >= (size_t)BB * CC * TT + (size_t)BB * DD * TT)
        transpose_tc_to_ct<0><<<dim3(TT / 32, DD / 32, BB), dim3(32, 8)>>>(p_rD, o_r, DD, TT, DP);
}

// round 15
// speedup vs baseline: 1.0421x; 1.0131x over previous
#include <cuda_runtime.h>
#include <cuda_fp16.h>
#include <math.h>
#include <stdint.h>

// ---------------- problem constants ----------------
#define BB   16
#define CC   1024
#define TT   2048
#define DD   96
#define DP   128                 // padded D stride
#define NBQ  4
#define NEQ  2048
#define HH   8
#define CHK  16
#define NCHK 128
#define NTOK 32768
#define M2   2048
#define DH   128

typedef unsigned long long u64;

// ---------------- fp32 scratch ----------------
__device__ float g_KVb[(size_t)NTOK*2*CC];
__device__ float g_y  [(size_t)NTOK*CC];
__device__ float g_zp [(size_t)NTOK*CC];
__device__ float g_zh [(size_t)NTOK*CC];
__device__ float g_rD [(size_t)NTOK*DP];
__device__ float g_res[(size_t)NTOK*DP];
__device__ float g_qDv[(size_t)NTOK*DP];
__device__ u64   g_keys[(size_t)NTOK];

__device__ float g_q0n [(size_t)M2*CC];
__device__ float g_Q0  [(size_t)M2*CC];
__device__ float g_y0  [(size_t)M2*CC];
__device__ float g_z0  [(size_t)M2*CC];
__device__ float g_zh0 [(size_t)M2*CC];
__device__ float g_rD0 [(size_t)M2*DP];
__device__ float g_res0[(size_t)M2*DP];
__device__ float g_qD0 [(size_t)M2*DP];

__device__ float g_qc  [(size_t)CHK*CC];
__device__ float g_Qc  [(size_t)CHK*CC];
__device__ float g_cn  [(size_t)NBQ*NEQ];
__device__ float g_bdp [DP];

// ---------------- half hi/lo scratch ----------------
__device__ __half g_kvnh[(size_t)NTOK*CC], g_kvnl[(size_t)NTOK*CC];
__device__ __half g_ctxh[(size_t)NTOK*CC], g_ctxl[(size_t)NTOK*CC];
__device__ __half g_hnh [(size_t)NTOK*CC], g_hnl [(size_t)NTOK*CC];
__device__ __half g_s1h [(size_t)NTOK*2*CC], g_s1l [(size_t)NTOK*2*CC];
__device__ __half g_rNsh[(size_t)NTOK*CC], g_rNsl[(size_t)NTOK*CC];
__device__ __half g_rDh [(size_t)NTOK*DP], g_rDl [(size_t)NTOK*DP];
__device__ __half g_resh[(size_t)NTOK*DP], g_resl[(size_t)NTOK*DP];
__device__ __half g_qDh [(size_t)NTOK*DP], g_qDl [(size_t)NTOK*DP];

__device__ __half g_q0nh[(size_t)M2*CC], g_q0nl[(size_t)M2*CC];
__device__ __half g_c0h [(size_t)M2*CC], g_c0l [(size_t)M2*CC];
__device__ __half g_hn0h[(size_t)M2*CC], g_hn0l[(size_t)M2*CC];
__device__ __half g_g10h[(size_t)M2*2*CC], g_g10l[(size_t)M2*2*CC];
__device__ __half g_rD0h[(size_t)M2*DP], g_rD0l[(size_t)M2*DP];
__device__ __half g_re0h[(size_t)M2*DP], g_re0l[(size_t)M2*DP];
__device__ __half g_qD0h[(size_t)M2*DP], g_qD0l[(size_t)M2*DP];

// split weights [N,K]
__device__ __half g_Wkvh[(size_t)2*CC*CC], g_Wkvl[(size_t)2*CC*CC];
__device__ __half g_Wqh[(size_t)CC*CC], g_Wql[(size_t)CC*CC];
__device__ __half g_Woh[(size_t)CC*CC], g_Wol[(size_t)CC*CC];
__device__ __half g_W1h[(size_t)2*CC*CC], g_W1l[(size_t)2*CC*CC];
__device__ __half g_W2h[(size_t)CC*2*CC], g_W2l[(size_t)CC*2*CC];
__device__ __half g_Wdh[(size_t)DP*CC], g_Wdl[(size_t)DP*CC];
__device__ __half g_Wuh[(size_t)CC*DD], g_Wul[(size_t)CC*DD];
__device__ __half g_bkh[(size_t)NBQ*NEQ*DD], g_bkl[(size_t)NBQ*NEQ*DD];

__device__ __forceinline__ uint32_t smem_u32(const void* p) {
    uint32_t a;
    asm("{ .reg .u64 t; cvta.to.shared.u64 t, %1; cvt.u32.u64 %0, t; }" : "=r"(a) : "l"(p));
    return a;
}
__device__ __forceinline__ void mma16816(float* c, const uint32_t* a, const uint32_t* b) {
    asm volatile(
        "mma.sync.aligned.m16n8k16.row.col.f32.f16.f16.f32 "
        "{%0,%1,%2,%3}, {%4,%5,%6,%7}, {%8,%9}, {%0,%1,%2,%3};"
        : "+f"(c[0]), "+f"(c[1]), "+f"(c[2]), "+f"(c[3])
        : "r"(a[0]), "r"(a[1]), "r"(a[2]), "r"(a[3]), "r"(b[0]), "r"(b[1]));
}
__device__ __forceinline__ void ldmat4(uint32_t* r, uint32_t addr) {
    asm volatile("ldmatrix.sync.aligned.m8n8.x4.shared.b16 {%0,%1,%2,%3}, [%4];"
                 : "=r"(r[0]), "=r"(r[1]), "=r"(r[2]), "=r"(r[3]) : "r"(addr));
}
__device__ __forceinline__ void cp16(uint32_t dst, const void* src) {
    asm volatile("cp.async.cg.shared.global [%0], [%1], 16;\n" :: "r"(dst), "l"(src));
}
__device__ __forceinline__ void cpa_commit() { asm volatile("cp.async.commit_group;\n"); }
#define CPA_WAIT2() asm volatile("cp.async.wait_group 2;\n")
__device__ __forceinline__ void cpa_wait0() { asm volatile("cp.async.wait_group 0;\n"); }

// swizzled smem address: 128 rows x 64B, chunk-XOR swizzle
__device__ __forceinline__ uint32_t sw_addr(int row, int q) {
    return (uint32_t)(row * 64 + ((q ^ ((row >> 1) & 3)) << 4));
}

__device__ __forceinline__ float pe_val(int c, int t) {
    int ii = c >> 1;
    float div = expf((float)(2 * ii) * (-9.210340371976184f / (float)CC));
    float ang = (float)t * div;
    return (c & 1) ? cosf(ang) : sinf(ang);
}

// ---------------- split-input 3xFP16 GEMM: 128x128 tile, 128 thr, 3-stage, occ 2 ----
#define HP_STAGE 32768
#define HP_SMEM  (3 * HP_STAGE)

template <int EPI, int LDA, int LDB>
__global__ __launch_bounds__(128, 2) void hgemmP(
    const __half* __restrict__ Ah, const __half* __restrict__ Al,
    const __half* __restrict__ Bh, const __half* __restrict__ Bl,
    float* __restrict__ Co, __half* __restrict__ Oh, __half* __restrict__ Ol,
    int M, int N, int K,
    const float* __restrict__ bias, const float* __restrict__ add, int addPeriod,
    const float* __restrict__ cn, u64* __restrict__ keys) {
    extern __shared__ char sm[];
    const uint32_t sb = smem_u32(sm);
    const int tid = threadIdx.x;
    const int wid = tid >> 5, lane = tid & 31;
    const int wm = wid >> 1, wn = wid & 1;
    const int bm = blockIdx.y * 128, bn = blockIdx.x * 128;
    const int g = lane >> 2, tg = lane & 3;
    const int nt = K / 32;

    float acc[4][8][4];
#pragma unroll
    for (int i = 0; i < 4; i++)
#pragma unroll
        for (int j = 0; j < 8; j++)
#pragma unroll
            for (int q = 0; q < 4; q++) acc[i][j][q] = 0.f;

    const int lrow = (lane & 7) + ((lane >> 3) & 1) * 8;
    const int lq   = (lane >> 4) & 1;
    const int brow = (lane & 7) + ((lane >> 4) ? 8 : 0);
    const int bq   = (lane >> 3) & 1;

#define HP_LOAD(T) do {                                                         \
    int _t = (T);                                                               \
    if (_t < nt) {                                                              \
        uint32_t d0 = sb + (_t % 3) * HP_STAGE;                                 \
        _Pragma("unroll")                                                       \
        for (int j = 0; j < 16; j++) {                                          \
            int c = tid + j * 128;                                              \
            int mat = c >> 9;                                                   \
            int cc = c & 511;                                                   \
            int row = cc >> 2, q = cc & 3;                                      \
            const __half* src;                                                  \
            if (mat == 0)      src = Ah + (size_t)(bm + row) * LDA + _t * 32 + q * 8; \
            else if (mat == 1) src = Al + (size_t)(bm + row) * LDA + _t * 32 + q * 8; \
            else if (mat == 2) src = Bh + (size_t)(bn + row) * LDB + _t * 32 + q * 8; \
            else               src = Bl + (size_t)(bn + row) * LDB + _t * 32 + q * 8; \
            cp16(d0 + mat * 8192 + sw_addr(row, q), src);                       \
        }                                                                       \
    }                                                                           \
    cpa_commit();                                                               \
} while (0)

    HP_LOAD(0);
    HP_LOAD(1);
    HP_LOAD(2);

    for (int t = 0; t < nt; t++) {
        CPA_WAIT2();
        __syncthreads();
        const uint32_t tb = sb + (t % 3) * HP_STAGE;
#pragma unroll
        for (int ks = 0; ks < 2; ks++) {
            uint32_t ah[4][4], al[4][4];
#pragma unroll
            for (int mt = 0; mt < 4; mt++) {
                int row = wm * 64 + mt * 16 + lrow;
                uint32_t ad = tb + sw_addr(row, ks * 2 + lq);
                ldmat4(ah[mt], ad);
                ldmat4(al[mt], ad + 8192);
            }
            uint32_t bf[4][4];
#pragma unroll
            for (int p = 0; p < 4; p++) {
                int row = wn * 64 + p * 16 + brow;
                uint32_t bd = tb + 16384 + sw_addr(row, ks * 2 + bq);
                ldmat4(bf[p], bd);
            }
#pragma unroll
            for (int mt = 0; mt < 4; mt++)
#pragma unroll
                for (int p = 0; p < 4; p++) {
                    mma16816(acc[mt][2 * p],     ah[mt], &bf[p][0]);
                    mma16816(acc[mt][2 * p + 1], ah[mt], &bf[p][2]);
                    mma16816(acc[mt][2 * p],     al[mt], &bf[p][0]);
                    mma16816(acc[mt][2 * p + 1], al[mt], &bf[p][2]);
                }
#pragma unroll
            for (int p = 0; p < 4; p++) {
                int row = wn * 64 + p * 16 + brow;
                uint32_t bd = tb + 24576 + sw_addr(row, ks * 2 + bq);
                ldmat4(bf[p], bd);
            }
#pragma unroll
            for (int mt = 0; mt < 4; mt++)
#pragma unroll
                for (int p = 0; p < 4; p++) {
                    mma16816(acc[mt][2 * p],     ah[mt], &bf[p][0]);
                    mma16816(acc[mt][2 * p + 1], ah[mt], &bf[p][2]);
                }
        }
        __syncthreads();
        HP_LOAD(t + 3);
    }
#undef HP_LOAD

    if (EPI == 3) {
#pragma unroll
        for (int mt = 0; mt < 4; mt++) {
            int m0 = bm + wm * 64 + mt * 16 + g;
            int m1 = m0 + 8;
            u64 b0 = 0ull, b1 = 0ull;
#pragma unroll
            for (int nb = 0; nb < 8; nb++) {
                int n0 = bn + wn * 64 + nb * 8 + tg * 2;
                float s00 = acc[mt][nb][0] - cn[n0];
                float s01 = acc[mt][nb][1] - cn[n0 + 1];
                float s10 = acc[mt][nb][2] - cn[n0];
                float s11 = acc[mt][nb][3] - cn[n0 + 1];
                unsigned u;
                u = __float_as_uint(s00); u = (u & 0x80000000u) ? ~u : (u | 0x80000000u);
                u64 k = ((u64)u << 32) | (unsigned)(~n0);
                if (k > b0) b0 = k;
                u = __float_as_uint(s01); u = (u & 0x80000000u) ? ~u : (u | 0x80000000u);
                k = ((u64)u << 32) | (unsigned)(~(n0 + 1));
                if (k > b0) b0 = k;
                u = __float_as_uint(s10); u = (u & 0x80000000u) ? ~u : (u | 0x80000000u);
                k = ((u64)u << 32) | (unsigned)(~n0);
                if (k > b1) b1 = k;
                u = __float_as_uint(s11); u = (u & 0x80000000u) ? ~u : (u | 0x80000000u);
                k = ((u64)u << 32) | (unsigned)(~(n0 + 1));
                if (k > b1) b1 = k;
            }
#pragma unroll
            for (int o = 1; o < 4; o <<= 1) {
                u64 t0 = __shfl_xor_sync(0xffffffffu, b0, o);
                u64 t1 = __shfl_xor_sync(0xffffffffu, b1, o);
                if (t0 > b0) b0 = t0;
                if (t1 > b1) b1 = t1;
            }
            if (tg == 0) {
                atomicMax(&keys[m0], b0);
                atomicMax(&keys[m1], b1);
            }
        }
    } else {
#pragma unroll
        for (int mt = 0; mt < 4; mt++) {
            int m0 = bm + wm * 64 + mt * 16 + g;
            int m1 = m0 + 8;
            const float* add0 = (EPI == 0 && add)
                ? add + (size_t)((addPeriod > 0) ? (m0 % addPeriod) : m0) * N : nullptr;
            const float* add1 = (EPI == 0 && add)
                ? add + (size_t)((addPeriod > 0) ? (m1 % addPeriod) : m1) * N : nullptr;
#pragma unroll
            for (int nb = 0; nb < 8; nb++) {
                int n0 = bn + wn * 64 + nb * 8 + tg * 2;
                float v0 = acc[mt][nb][0], v1 = acc[mt][nb][1];
                float v2 = acc[mt][nb][2], v3 = acc[mt][nb][3];
                if (bias) {
                    float c0 = bias[n0], c1 = bias[n0 + 1];
                    v0 += c0; v1 += c1; v2 += c0; v3 += c1;
                }
                if (EPI == 0) {
                    if (add0) { v0 += add0[n0]; v1 += add0[n0 + 1]; }
                    if (add1) { v2 += add1[n0]; v3 += add1[n0 + 1]; }
                    *(float2*)(Co + (size_t)m0 * N + n0) = make_float2(v0, v1);
                    *(float2*)(Co + (size_t)m1 * N + n0) = make_float2(v2, v3);
                } else if (EPI == 4) {
                    *(float2*)(Co + (size_t)m0 * N + n0) = make_float2(v0, v1);
                    *(float2*)(Co + (size_t)m1 * N + n0) = make_float2(v2, v3);
                    __half2 h0 = __floats2half2_rn(v0, v1);
                    float2 f0 = __half22float2(h0);
                    __half2 l0 = __floats2half2_rn(v0 - f0.x, v1 - f0.y);
                    __half2 h1 = __floats2half2_rn(v2, v3);
                    float2 f1 = __half22float2(h1);
                    __half2 l1 = __floats2half2_rn(v2 - f1.x, v3 - f1.y);
                    *(__half2*)(Oh + (size_t)m0 * N + n0) = h0;
                    *(__half2*)(Ol + (size_t)m0 * N + n0) = l0;
                    *(__half2*)(Oh + (size_t)m1 * N + n0) = h1;
                    *(__half2*)(Ol + (size_t)m1 * N + n0) = l1;
                } else {  // EPI == 2
                    v0 = 0.5f * v0 * (1.0f + erff(v0 * 0.70710678118654752f));
                    v1 = 0.5f * v1 * (1.0f + erff(v1 * 0.70710678118654752f));
                    v2 = 0.5f * v2 * (1.0f + erff(v2 * 0.70710678118654752f));
                    v3 = 0.5f * v3 * (1.0f + erff(v3 * 0.70710678118654752f));
                    __half2 h0 = __floats2half2_rn(v0, v1);
                    float2 f0 = __half22float2(h0);
                    __half2 l0 = __floats2half2_rn(v0 - f0.x, v1 - f0.y);
                    __half2 h1 = __floats2half2_rn(v2, v3);
                    float2 f1 = __half22float2(h1);
                    __half2 l1 = __floats2half2_rn(v2 - f1.x, v3 - f1.y);
                    *(__half2*)(Oh + (size_t)m0 * N + n0) = h0;
                    *(__half2*)(Ol + (size_t)m0 * N + n0) = l0;
                    *(__half2*)(Oh + (size_t)m1 * N + n0) = h1;
                    *(__half2*)(Ol + (size_t)m1 * N + n0) = l1;
                }
            }
        }
    }
}

// ---------------- setup kernels ----------------
// one 96-thread block per codebook entry (coalesced); block NBQ*NEQ pads bd
__global__ __launch_bounds__(DD) void prep_books(
    const float* __restrict__ books, const float* __restrict__ bd,
    float* __restrict__ cn, float* __restrict__ bdp,
    __half* __restrict__ bh, __half* __restrict__ bl) {
    int e = blockIdx.x;
    int d = threadIdx.x;
    if (e == NBQ * NEQ) {
        // pad bd into bdp (DP entries; threads cover DD, thread 0 zeroes tail)
        bdp[d] = bd[d];
        if (d < DP - DD) bdp[DD + d] = 0.0f;
        return;
    }
    __shared__ float red[3];
    float v = books[(size_t)e * DD + d];
    __half h = __float2half_rn(v);
    bh[(size_t)e * DD + d] = h;
    bl[(size_t)e * DD + d] = __float2half_rn(v - __half2float(h));
    float s = v * v;
#pragma unroll
    for (int o = 16; o; o >>= 1) s += __shfl_xor_sync(0xffffffffu, s, o);
    int w = d >> 5;
    if ((d & 31) == 0) red[w] = s;
    __syncthreads();
    if (d == 0) cn[e] = 0.5f * (red[0] + red[1] + red[2]);
}

__global__ void split_f32(const float* __restrict__ src, __half* __restrict__ h,
                          __half* __restrict__ l, int n) {
    int i = blockIdx.x * 256 + threadIdx.x;
    if (i >= n) return;
    float v = src[i];
    __half hi = __float2half_rn(v);
    h[i] = hi;
    l[i] = __float2half_rn(v - __half2float(hi));
}

// ---------------- transposes ----------------
__global__ void transpose_split2(const float* __restrict__ inA, __half* __restrict__ ohA,
                                 __half* __restrict__ olA,
                                 const float* __restrict__ inB, __half* __restrict__ ohB,
                                 __half* __restrict__ olB, int Cdim, int Tdim) {
    __shared__ float tile[32][33];
    int which = blockIdx.z;
    const float* in = which ? inB : inA;
    __half* oh = which ? ohB : ohA;
    __half* ol = which ? olB : olA;
    int c0 = blockIdx.y * 32, t0 = blockIdx.x * 32;
    int x = threadIdx.x, y = threadIdx.y;
    for (int i = 0; i < 32; i += 8)
        tile[y + i][x] = in[(size_t)(c0 + y + i) * Tdim + t0 + x];
    __syncthreads();
    for (int i = 0; i < 32; i += 8) {
        float v = tile[x][y + i];
        __half h = __float2half_rn(v);
        size_t o = (size_t)(t0 + y + i) * Cdim + c0 + x;
        oh[o] = h;
        ol[o] = __float2half_rn(v - __half2float(h));
    }
}

template <int NANFIX>
__global__ void transpose_tc_to_ct(const float* __restrict__ in, float* __restrict__ out,
                                   int Cdim, int Tdim, int srcLd) {
    __shared__ float tile[32][33];
    int b = blockIdx.z;
    int c0 = blockIdx.y * 32, t0 = blockIdx.x * 32;
    int x = threadIdx.x, y = threadIdx.y;
    for (int i = 0; i < 32; i += 8)
        tile[y + i][x] = in[((size_t)b * Tdim + t0 + y + i) * srcLd + c0 + x];
    __syncthreads();
    for (int i = 0; i < 32; i += 8) {
        float v = tile[x][y + i];
        if (NANFIX) { if (!isfinite(v)) v = 0.0f; }
        out[((size_t)b * Cdim + c0 + y + i) * Tdim + t0 + x] = v;
    }
}

// ---------------- LN reading directly from (B,C,T) layout ----------------
template <int POST, int PE, int GATHER>
__global__ __launch_bounds__(256) void ln_ct(
    const float* __restrict__ ct, const float* __restrict__ in1,
    const float* __restrict__ gamma, const float* __restrict__ beta,
    const float* __restrict__ scale_ptr,
    __half* __restrict__ oh, __half* __restrict__ ol) {
    __shared__ float tile[CC * 9];
    const int tid = threadIdx.x;
    const int m8 = blockIdx.x * 8;
#pragma unroll
    for (int i = 0; i < 32; i++) {
        int idx = tid + i * 256;
        int c = idx >> 3, x = idx & 7;
        int m = m8 + x;
        size_t src;
        if (GATHER) {
            int b = m / NCHK, t = (m % NCHK) * 16;
            src = ((size_t)b * CC + c) * TT + t;
        } else {
            int b = m >> 11, t = m & (TT - 1);
            src = ((size_t)b * CC + c) * TT + t;
        }
        tile[c * 9 + x] = ct[src];
    }
    __syncthreads();

    const int w = tid >> 5, lane = tid & 31;
    const int m = m8 + w;
    float x[32];
    float s = 0.f;
#pragma unroll
    for (int k = 0; k < 32; k++) {
        int c = lane + k * 32;
        float v = tile[c * 9 + w];
        if (in1) v -= in1[(size_t)m * CC + c];
        if (PE == 1) v += pe_val(c, m & 15);
        x[k] = v;
        s += v;
    }
#pragma unroll
    for (int o = 16; o; o >>= 1) s += __shfl_xor_sync(0xffffffffu, s, o);
    float mean = s * (1.0f / (float)CC);
    float vs = 0.f;
#pragma unroll
    for (int k = 0; k < 32; k++) { float d = x[k] - mean; vs += d * d; }
#pragma unroll
    for (int o = 16; o; o >>= 1) vs += __shfl_xor_sync(0xffffffffu, vs, o);
    float rstd = rsqrtf(vs * (1.0f / (float)CC) + 1e-5f);
    float sc = 1.0f;
    if (POST == 1) {
        float t = scale_ptr[0];
        sc = fminf(fmaxf(t, 0.005f), 0.5f);
    }
#pragma unroll
    for (int k = 0; k < 32; k++) {
        int c = lane + k * 32;
        float yv = (x[k] - mean) * rstd * gamma[c] + beta[c];
        if (POST == 1) yv = tanhf(yv) * sc;
        __half h = __float2half_rn(yv);
        oh[(size_t)m * CC + c] = h;
        ol[(size_t)m * CC + c] = __float2half_rn(yv - __half2float(h));
    }
}

// ---------------- token-major LayerNorm ----------------
template <int POST, int SPLIT, int PE, int SRC>
__global__ __launch_bounds__(256) void ln_kernel(
    const float* __restrict__ in0, const float* __restrict__ in1,
    const float* __restrict__ gamma, const float* __restrict__ beta,
    const float* __restrict__ scale_ptr, float* __restrict__ out,
    __half* __restrict__ oh, __half* __restrict__ ol, int Mrows) {
    int m = blockIdx.x;
    if (m >= Mrows) return;
    int tid = threadIdx.x;
    int lane = tid & 31, warp = tid >> 5;
    __shared__ float red[8];
    float x[4];
#pragma unroll
    for (int k = 0; k < 4; k++) {
        int c = tid + k * 256;
        float v;
        if (SRC == 1) {
            v = (m & (NCHK - 1)) ? in0[((size_t)m * 16 - 1) * CC + c] : 0.0f;
        } else {
            v = in0 ? in0[(size_t)m * CC + c] : 0.0f;
        }
        if (in1) v -= in1[(size_t)m * CC + c];
        if (PE == 1) v += pe_val(c, m & 15);
        else if (PE == 2) v += pe_val(c, 0);
        x[k] = v;
    }
    float s = x[0] + x[1] + x[2] + x[3];
#pragma unroll
    for (int o = 16; o; o >>= 1) s += __shfl_xor_sync(0xffffffffu, s, o);
    if (lane == 0) red[warp] = s;
    __syncthreads();
    float mean;
    {
        float t = (lane < 8) ? red[lane] : 0.f;
#pragma unroll
        for (int o = 4; o; o >>= 1) t += __shfl_xor_sync(0xffffffffu, t, o);
        mean = __shfl_sync(0xffffffffu, t, 0) * (1.0f / (float)CC);
    }
    float vs = 0.f;
#pragma unroll
    for (int k = 0; k < 4; k++) { float d = x[k] - mean; vs += d * d; }
#pragma unroll
    for (int o = 16; o; o >>= 1) vs += __shfl_xor_sync(0xffffffffu, vs, o);
    __syncthreads();
    if (lane == 0) red[warp] = vs;
    __syncthreads();
    float var;
    {
        float t = (lane < 8) ? red[lane] : 0.f;
#pragma unroll
        for (int o = 4; o; o >>= 1) t += __shfl_xor_sync(0xffffffffu, t, o);
        var = __shfl_sync(0xffffffffu, t, 0) * (1.0f / (float)CC);
    }
    float rstd = rsqrtf(var + 1e-5f);
    float sc = 1.0f;
    if (POST == 1) {
        float t = scale_ptr[0];
        sc = fminf(fmaxf(t, 0.005f), 0.5f);
    }
#pragma unroll
    for (int k = 0; k < 4; k++) {
        int c = tid + k * 256;
        float yv = (x[k] - mean) * rstd * gamma[c] + beta[c];
        if (POST == 1) yv = tanhf(yv) * sc;
        if (SPLIT != 1) out[(size_t)m * CC + c] = yv;
        if (SPLIT >= 1) {
            __half h = __float2half_rn(yv);
            oh[(size_t)m * CC + c] = h;
            ol[(size_t)m * CC + c] = __float2half_rn(yv - __half2float(h));
        }
    }
}

// ---------------- f32x2 helpers (scalar GEMM for tiny Qc) ----------------
__device__ __forceinline__ u64 pack2(float x) {
    u64 r;
    asm("mov.b64 %0, {%1, %1};" : "=l"(r) : "f"(x));
    return r;
}
__device__ __forceinline__ float2 unpack2(u64 v) {
    float2 f;
    asm("mov.b64 {%0, %1}, %2;" : "=f"(f.x), "=f"(f.y) : "l"(v));
    return f;
}
#define FFMA2(d, a, b) asm("fma.rn.f32x2 %0, %1, %2, %0;" : "+l"(d) : "l"(a), "l"(b))

__device__ __forceinline__ void cpa16p(void* dst, const void* src, bool pred) {
    unsigned int d = (unsigned int)__cvta_generic_to_shared(dst);
    int sz = pred ? 16 : 0;
    asm volatile("cp.async.ca.shared.global [%0], [%1], 16, %2;\n" :: "r"(d), "l"(src), "r"(sz));
}

template <bool GUARD>
__global__ __launch_bounds__(256, 2) void sgemm2(
    const float* __restrict__ A, const float* __restrict__ Bm, float* __restrict__ Co,
    int M, int N, int K, const float* __restrict__ bias) {
    __shared__ __align__(16) float As[2][16][128];
    __shared__ __align__(16) float Bs[2][16][128];
    const int tid = threadIdx.x;
    const int bm = blockIdx.y * 128, bn = blockIdx.x * 128;
    const int tx = tid & 15, ty = tid >> 4;

    const int a_row  = tid >> 1;
    const int a_koff = (tid & 1) * 8;
    const int b_row  = tid >> 5;
    const int b_col  = (tid & 31) * 4;

    const bool a_ok = !GUARD || (bm + a_row < M);
    const bool b_ok = !GUARD || (bn + b_col < N);
    const float* a_src0 = A + (size_t)(GUARD ? (a_ok ? bm + a_row : 0) : (bm + a_row)) * K + a_koff;
    const float* b_src0 = Bm + (size_t)b_row * N + (GUARD ? (b_ok ? bn + b_col : 0) : (bn + b_col));
    const float* b_src1 = b_src0 + (size_t)8 * N;

    u64 acc2[8][4];
#pragma unroll
    for (int i = 0; i < 8; i++)
#pragma unroll
        for (int q = 0; q < 4; q++) acc2[i][q] = 0ull;

    float a_reg[8];
    const int nt = K / 16;

    {
        if (a_ok) {
            float4 v0 = *(const float4*)(a_src0);
            float4 v1 = *(const float4*)(a_src0 + 4);
            a_reg[0]=v0.x; a_reg[1]=v0.y; a_reg[2]=v0.z; a_reg[3]=v0.w;
            a_reg[4]=v1.x; a_reg[5]=v1.y; a_reg[6]=v1.z; a_reg[7]=v1.w;
        } else {
#pragma unroll
            for (int c = 0; c < 8; c++) a_reg[c] = 0.f;
        }
        cpa16p(&Bs[0][b_row][b_col],     b_src0, b_ok);
        cpa16p(&Bs[0][8 + b_row][b_col], b_src1, b_ok);
        cpa_commit();
#pragma unroll
        for (int c = 0; c < 8; c++) As[0][a_koff + c][a_row] = a_reg[c];
        cpa_wait0();
        __syncthreads();
    }

    int buf = 0;
    for (int t = 0; t < nt; t++) {
        const bool has_next = (t + 1 < nt);
        if (has_next) {
            const float* ap = a_src0 + (size_t)(t + 1) * 16;
            if (a_ok) {
                float4 v0 = *(const float4*)(ap);
                float4 v1 = *(const float4*)(ap + 4);
                a_reg[0]=v0.x; a_reg[1]=v0.y; a_reg[2]=v0.z; a_reg[3]=v0.w;
                a_reg[4]=v1.x; a_reg[5]=v1.y; a_reg[6]=v1.z; a_reg[7]=v1.w;
            }
            cpa16p(&Bs[buf ^ 1][b_row][b_col],     b_src0 + (size_t)(t + 1) * 16 * N, b_ok);
            cpa16p(&Bs[buf ^ 1][8 + b_row][b_col], b_src1 + (size_t)(t + 1) * 16 * N, b_ok);
            cpa_commit();
        }
#pragma unroll
        for (int kk = 0; kk < 16; kk++) {
            float4 a0 = *(const float4*)&As[buf][kk][ty * 8];
            float4 a1 = *(const float4*)&As[buf][kk][ty * 8 + 4];
            ulonglong2 bl = *(const ulonglong2*)&Bs[buf][kk][tx * 4];
            ulonglong2 bh = *(const ulonglong2*)&Bs[buf][kk][64 + tx * 4];
            float am[8] = {a0.x, a0.y, a0.z, a0.w, a1.x, a1.y, a1.z, a1.w};
#pragma unroll
            for (int i = 0; i < 8; i++) {
                u64 ai = pack2(am[i]);
                FFMA2(acc2[i][0], ai, bl.x);
                FFMA2(acc2[i][1], ai, bl.y);
                FFMA2(acc2[i][2], ai, bh.x);
                FFMA2(acc2[i][3], ai, bh.y);
            }
        }
        if (has_next) {
#pragma unroll
            for (int c = 0; c < 8; c++) As[buf ^ 1][a_koff + c][a_row] = a_reg[c];
            cpa_wait0();
            __syncthreads();
            buf ^= 1;
        }
    }

#pragma unroll
    for (int i = 0; i < 8; i++) {
        int m = bm + ty * 8 + i;
        if (GUARD && m >= M) continue;
#pragma unroll
        for (int q = 0; q < 4; q++) {
            float2 v2 = unpack2(acc2[i][q]);
            int n0 = bn + ((q < 2) ? (tx * 4 + q * 2) : (64 + tx * 4 + (q - 2) * 2));
#pragma unroll
            for (int h = 0; h < 2; h++) {
                int n = n0 + h;
                if (GUARD && n >= N) continue;
                float v = h ? v2.y : v2.x;
                if (bias) v += bias[n];
                Co[(size_t)m * N + n] = v;
            }
        }
    }
}

// ---------------- attention ----------------
__global__ __launch_bounds__(256) void attn_a(const float* __restrict__ KVb,
                                              const float* __restrict__ Qc,
                                              __half* __restrict__ ctxh,
                                              __half* __restrict__ ctxl) {
    int gb = blockIdx.x;
    int h = blockIdx.y;
    int tid = threadIdx.x;
    __shared__ float Ks[16][133], Vs[16][133], Qs[16][133];
    __shared__ float Ss[16][17];
    for (int i = tid; i < 16 * DH; i += 256) {
        int t = i >> 7, d = i & 127;
        size_t base = ((size_t)(gb * 16 + t)) * (2 * CC) + (size_t)h * DH + d;
        Ks[t][d] = KVb[base];
        Vs[t][d] = KVb[base + CC];
        Qs[t][d] = Qc[(size_t)t * CC + (size_t)h * DH + d];
    }
    __syncthreads();
    {
        int q = tid >> 4, k = tid & 15;
        float s = 0.f;
#pragma unroll 8
        for (int d = 0; d < DH; d++) s = fmaf(Qs[q][d], Ks[k][d], s);
        Ss[q][k] = s * 0.08838834764831845f;
    }
    __syncthreads();
    if (tid < 16) {
        float mx = -1e30f;
        for (int k = 0; k < 16; k++) mx = fmaxf(mx, Ss[tid][k]);
        float e[16], sum = 0.f;
        for (int k = 0; k < 16; k++) { e[k] = expf(Ss[tid][k] - mx); sum += e[k]; }
        float inv = 1.0f / sum;
        for (int k = 0; k < 16; k++) Ss[tid][k] = e[k] * inv;
    }
    __syncthreads();
    for (int i = tid; i < 16 * DH; i += 256) {
        int t = i >> 7, d = i & 127;
        float a = 0.f;
#pragma unroll
        for (int k = 0; k < 16; k++) a = fmaf(Ss[t][k], Vs[k][d], a);
        size_t o = ((size_t)(gb * 16 + t)) * CC + (size_t)h * DH + d;
        __half hh = __float2half_rn(a);
        ctxh[o] = hh;
        ctxl[o] = __float2half_rn(a - __half2float(hh));
    }
}

__global__ __launch_bounds__(128) void attn_b(const float* __restrict__ KVb,
                                              const float* __restrict__ Q0,
                                              __half* __restrict__ ctxh,
                                              __half* __restrict__ ctxl) {
    int p = blockIdx.x;
    int h = blockIdx.y;
    int tid = threadIdx.x;
    __shared__ float Ks[16][128], Vs[16][128], Qs[128];
    __shared__ float sc[16];
    for (int i = tid; i < 16 * DH; i += 128) {
        int t = i >> 7, d = i & 127;
        size_t base = ((size_t)(p * 16 + t)) * (2 * CC) + (size_t)h * DH + d;
        Ks[t][d] = KVb[base];
        Vs[t][d] = KVb[base + CC];
    }
    Qs[tid] = Q0[(size_t)p * CC + (size_t)h * DH + tid];
    __syncthreads();
    int w = tid >> 5, l = tid & 31;
    for (int k = w; k < 16; k += 4) {
        float s = Qs[l] * Ks[k][l] + Qs[l + 32] * Ks[k][l + 32] +
                  Qs[l + 64] * Ks[k][l + 64] + Qs[l + 96] * Ks[k][l + 96];
        for (int o = 16; o; o >>= 1) s += __shfl_xor_sync(0xffffffffu, s, o);
        if (l == 0) sc[k] = s * 0.08838834764831845f;
    }
    __syncthreads();
    if (tid == 0) {
        float mx = -1e30f;
        for (int k = 0; k < 16; k++) mx = fmaxf(mx, sc[k]);
        float e[16], sum = 0.f;
        for (int k = 0; k < 16; k++) { e[k] = expf(sc[k] - mx); sum += e[k]; }
        float inv = 1.0f / sum;
        for (int k = 0; k < 16; k++) sc[k] = e[k] * inv;
    }
    __syncthreads();
    float a = 0.f;
#pragma unroll
    for (int k = 0; k < 16; k++) a = fmaf(sc[k], Vs[k][tid], a);
    size_t o = (size_t)p * CC + (size_t)h * DH + tid;
    __half hh = __float2half_rn(a);
    ctxh[o] = hh;
    ctxl[o] = __float2half_rn(a - __half2float(hh));
}

// ---------------- RVQ update (padded stride DP; resets keys) ----------------
__global__ void rvq_update3(u64* __restrict__ keys,
                            const float* __restrict__ books_st,
                            const float* __restrict__ resid_in,
                            float* __restrict__ resid_out,
                            __half* __restrict__ resh, __half* __restrict__ resl,
                            float* __restrict__ qD,
                            __half* __restrict__ qDh, __half* __restrict__ qDl,
                            int firstStage, int lastStage) {
    int m = blockIdx.x;
    int d = threadIdx.x;   // 96 threads
    int idx = (int)(~(unsigned)(keys[m] & 0xffffffffu)) & (NEQ - 1);
    __syncthreads();
    if (d == 0) keys[m] = 0ull;
    float e = books_st[(size_t)idx * DD + d];
    float r = resid_in[(size_t)m * DP + d];
    float nr = r - e;
    resid_out[(size_t)m * DP + d] = nr;
    __half hh = __float2half_rn(nr);
    resh[(size_t)m * DP + d] = hh;
    resl[(size_t)m * DP + d] = __float2half_rn(nr - __half2float(hh));
    float q = firstStage ? e : (qD[(size_t)m * DP + d] + e);
    qD[(size_t)m * DP + d] = q;
    if (lastStage) {
        __half qh = __float2half_rn(q);
        qDh[(size_t)m * DP + d] = qh;
        qDl[(size_t)m * DP + d] = __float2half_rn(q - __half2float(qh));
    }
}

// ---------------- misc ----------------
// y-select: 0 -> zh0->zh (CC cols, ld CC); 1 -> rD0->rD (DD cols, ld DP)
__global__ void scatter_rows16_2(const float* __restrict__ inA, float* __restrict__ outA,
                                 const float* __restrict__ inB, float* __restrict__ outB) {
    int p = blockIdx.x;
    if (blockIdx.y == 0) {
        for (int c = threadIdx.x; c < CC; c += blockDim.x)
            outA[((size_t)p * 16) * CC + c] = inA[(size_t)p * CC + c];
    } else {
        for (int c = threadIdx.x; c < DD; c += blockDim.x)
            outB[((size_t)p * 16) * DP + c] = inB[(size_t)p * DP + c];
    }
}

// ---------------- host ----------------
static inline dim3 gemm_grid(int M, int N) { return dim3((N + 127) / 128, (M + 127) / 128); }
static inline dim3 hp_grid(int M, int N) { return dim3(N / 128, M / 128); }

extern "C" void kernel_launch(void* const* d_in, const int* in_sizes, int n_in,
                              void* d_out, int out_size) {
    const float* qa     = (const float*)d_in[0];
    const float* ztt    = (const float*)d_in[1];
    const float* ln_q_g = (const float*)d_in[2];
    const float* ln_q_b = (const float*)d_in[3];
    const float* ln_kv_g= (const float*)d_in[4];
    const float* ln_kv_b= (const float*)d_in[5];
    const float* Wq     = (const float*)d_in[6];
    const float* Wk     = (const float*)d_in[7];
    const float* Wv     = (const float*)d_in[8];
    const float* Wo     = (const float*)d_in[9];
    const float* ffg    = (const float*)d_in[10];
    const float* ffb    = (const float*)d_in[11];
    const float* W1     = (const float*)d_in[12];
    const float* b1     = (const float*)d_in[13];
    const float* W2     = (const float*)d_in[14];
    const float* b2     = (const float*)d_in[15];
    const float* tng    = (const float*)d_in[16];
    const float* tnb    = (const float*)d_in[17];
    const float* scale  = (const float*)d_in[18];
    const float* Wd     = (const float*)d_in[19];
    const float* bd     = (const float*)d_in[20];
    const float* Wu     = (const float*)d_in[21];
    const float* bu     = (const float*)d_in[22];
    const float* books  = (const float*)d_in[23];

    float* out = (float*)d_out;
    float* o_y = out;
    float* o_r = out + (size_t)BB * CC * TT;

#define SYMF(p, s) float* p; cudaGetSymbolAddress((void**)&p, s)
#define SYMH(p, s) __half* p; cudaGetSymbolAddress((void**)&p, s)
    SYMF(p_KVb, g_KVb);
    SYMF(p_y, g_y);     SYMF(p_zp, g_zp);   SYMF(p_zh, g_zh);
    SYMF(p_rD, g_rD);   SYMF(p_res, g_res); SYMF(p_qDv, g_qDv);
    SYMF(p_q0n, g_q0n); SYMF(p_Q0, g_Q0);
    SYMF(p_y0, g_y0);   SYMF(p_z0, g_z0);
    SYMF(p_zh0, g_zh0);
    SYMF(p_rD0, g_rD0); SYMF(p_res0, g_res0); SYMF(p_qD0, g_qD0);
    SYMF(p_qc, g_qc);   SYMF(p_Qc, g_Qc);
    SYMF(p_cn, g_cn);   SYMF(p_bdp, g_bdp);
    SYMH(p_kvnh, g_kvnh); SYMH(p_kvnl, g_kvnl);
    SYMH(p_ctxh, g_ctxh); SYMH(p_ctxl, g_ctxl);
    SYMH(p_hnh, g_hnh);   SYMH(p_hnl, g_hnl);
    SYMH(p_s1h, g_s1h);   SYMH(p_s1l, g_s1l);
    SYMH(p_rNsh, g_rNsh); SYMH(p_rNsl, g_rNsl);
    SYMH(p_rDh, g_rDh);   SYMH(p_rDl, g_rDl);
    SYMH(p_resh, g_resh); SYMH(p_resl, g_resl);
    SYMH(p_qDh, g_qDh);   SYMH(p_qDl, g_qDl);
    SYMH(p_q0nh, g_q0nh); SYMH(p_q0nl, g_q0nl);
    SYMH(p_c0h, g_c0h);   SYMH(p_c0l, g_c0l);
    SYMH(p_hn0h, g_hn0h); SYMH(p_hn0l, g_hn0l);
    SYMH(p_g10h, g_g10h); SYMH(p_g10l, g_g10l);
    SYMH(p_rD0h, g_rD0h); SYMH(p_rD0l, g_rD0l);
    SYMH(p_re0h, g_re0h); SYMH(p_re0l, g_re0l);
    SYMH(p_qD0h, g_qD0h); SYMH(p_qD0l, g_qD0l);
    SYMH(p_Wkvh, g_Wkvh); SYMH(p_Wkvl, g_Wkvl);
    SYMH(p_Wqh, g_Wqh); SYMH(p_Wql, g_Wql);
    SYMH(p_Woh, g_Woh); SYMH(p_Wol, g_Wol);
    SYMH(p_W1h, g_W1h); SYMH(p_W1l, g_W1l);
    SYMH(p_W2h, g_W2h); SYMH(p_W2l, g_W2l);
    SYMH(p_Wdh, g_Wdh); SYMH(p_Wdl, g_Wdl);
    SYMH(p_Wuh, g_Wuh); SYMH(p_Wul, g_Wul);
    SYMH(p_bkh, g_bkh); SYMH(p_bkl, g_bkl);
#undef SYMF
#undef SYMH
    u64* p_keys; cudaGetSymbolAddress((void**)&p_keys, g_keys);

    cudaFuncSetAttribute(hgemmP<0, CC, CC>, cudaFuncAttributeMaxDynamicSharedMemorySize, HP_SMEM);
    cudaFuncSetAttribute(hgemmP<2, CC, CC>, cudaFuncAttributeMaxDynamicSharedMemorySize, HP_SMEM);
    cudaFuncSetAttribute(hgemmP<0, 2 * CC, 2 * CC>, cudaFuncAttributeMaxDynamicSharedMemorySize, HP_SMEM);
    cudaFuncSetAttribute(hgemmP<4, CC, CC>, cudaFuncAttributeMaxDynamicSharedMemorySize, HP_SMEM);
    cudaFuncSetAttribute(hgemmP<3, DP, DD>, cudaFuncAttributeMaxDynamicSharedMemorySize, HP_SMEM);
    cudaFuncSetAttribute(hgemmP<0, DP, DD>, cudaFuncAttributeMaxDynamicSharedMemorySize, HP_SMEM);

    // ---- setup head; big KV GEMM early for ncu slot ----
    ln_ct<0, 1, 0><<<NTOK / 8, 256>>>(qa, nullptr, ln_kv_g, ln_kv_b, nullptr,
                                      p_kvnh, p_kvnl);                              // 1
    transpose_split2<<<dim3(32, 32, 2), dim3(32, 8)>>>(Wk, p_Wkvh, p_Wkvl,
                                                       Wv, p_Wkvh + (size_t)CC * CC,
                                                       p_Wkvl + (size_t)CC * CC, CC, CC); // 2
    hgemmP<0, CC, CC><<<hp_grid(NTOK, 2 * CC), 128, HP_SMEM>>>(p_kvnh, p_kvnl, p_Wkvh, p_Wkvl,
        p_KVb, nullptr, nullptr, NTOK, 2 * CC, CC, nullptr, nullptr, 0, nullptr, nullptr); // 3

    // ---- remaining setup ----
    prep_books<<<NBQ * NEQ + 1, DD>>>(books, bd, p_cn, p_bdp, p_bkh, p_bkl);
    transpose_split2<<<dim3(32, 32, 2), dim3(32, 8)>>>(Wq, p_Wqh, p_Wql,
                                                       Wo, p_Woh, p_Wol, CC, CC);
    transpose_split2<<<dim3(64, 32, 1), dim3(32, 8)>>>(W1, p_W1h, p_W1l,
                                                       nullptr, nullptr, nullptr, CC, 2 * CC);
    transpose_split2<<<dim3(32, 64, 1), dim3(32, 8)>>>(W2, p_W2h, p_W2l,
                                                       nullptr, nullptr, nullptr, 2 * CC, CC);
    split_f32<<<(DD * CC + 255) / 256, 256>>>(Wd, p_Wdh, p_Wdl, DD * CC);
    split_f32<<<(CC * DD + 255) / 256, 256>>>(Wu, p_Wuh, p_Wul, CC * DD);
    ln_kernel<0, 0, 1, 0><<<CHK, 256>>>(nullptr, nullptr, ln_q_g, ln_q_b, nullptr,
                                        p_qc, nullptr, nullptr, CHK);
    sgemm2<true><<<gemm_grid(CHK, CC), 256>>>(p_qc, Wq, p_Qc, CHK, CC, CC, nullptr);
    cudaMemsetAsync(p_keys, 0, (size_t)NTOK * sizeof(u64), 0);

    // ---- pass A ----
    attn_a<<<dim3(M2, HH), 256>>>(p_KVb, p_Qc, p_ctxh, p_ctxl);
    hgemmP<0, CC, CC><<<hp_grid(NTOK, CC), 128, HP_SMEM>>>(p_ctxh, p_ctxl, p_Woh, p_Wol,
        p_y, nullptr, nullptr, NTOK, CC, CC, nullptr, p_qc, CHK, nullptr, nullptr);
    ln_kernel<0, 1, 0, 0><<<NTOK, 256>>>(p_y, nullptr, ffg, ffb, nullptr,
                                         nullptr, p_hnh, p_hnl, NTOK);
    hgemmP<2, CC, CC><<<hp_grid(NTOK, 2 * CC), 128, HP_SMEM>>>(p_hnh, p_hnl, p_W1h, p_W1l,
        nullptr, p_s1h, p_s1l, NTOK, 2 * CC, CC, b1, nullptr, 0, nullptr, nullptr);
    hgemmP<0, 2 * CC, 2 * CC><<<hp_grid(NTOK, CC), 128, HP_SMEM>>>(p_s1h, p_s1l, p_W2h, p_W2l,
        p_zp, nullptr, nullptr, NTOK, CC, 2 * CC, b2, p_y, 0, nullptr, nullptr);
    ln_ct<1, 0, 0><<<NTOK / 8, 256>>>(ztt, p_zp, tng, tnb, scale, p_rNsh, p_rNsl);
    hgemmP<4, CC, CC><<<hp_grid(NTOK, DP), 128, HP_SMEM>>>(p_rNsh, p_rNsl, p_Wdh, p_Wdl,
        p_rD, p_rDh, p_rDl, NTOK, DP, CC, p_bdp, nullptr, 0, nullptr, nullptr);
    for (int st = 0; st < NBQ; st++) {
        const __half* Ahp = (st == 0) ? p_rDh : p_resh;
        const __half* Alp = (st == 0) ? p_rDl : p_resl;
        const float* Rin = (st == 0) ? p_rD : p_res;
        hgemmP<3, DP, DD><<<hp_grid(NTOK, NEQ), 128, HP_SMEM>>>(Ahp, Alp,
            p_bkh + (size_t)st * NEQ * DD, p_bkl + (size_t)st * NEQ * DD,
            nullptr, nullptr, nullptr, NTOK, NEQ, DD, nullptr, nullptr, 0,
            p_cn + (size_t)st * NEQ, p_keys);
        rvq_update3<<<NTOK, DD>>>(p_keys, books + (size_t)st * NEQ * DD,
                                  Rin, p_res, p_resh, p_resl,
                                  p_qDv, p_qDh, p_qDl,
                                  st == 0 ? 1 : 0, st == NBQ - 1 ? 1 : 0);
    }
    hgemmP<0, DP, DD><<<hp_grid(NTOK, CC), 128, HP_SMEM>>>(p_qDh, p_qDl, p_Wuh, p_Wul,
        p_zh, nullptr, nullptr, NTOK, CC, DD, bu, p_zp, 0, nullptr, nullptr);

    // ---- pass B ----
    ln_kernel<0, 2, 2, 1><<<M2, 256>>>(p_zh, nullptr, ln_q_g, ln_q_b, nullptr,
                                       p_q0n, p_q0nh, p_q0nl, M2);
    hgemmP<0, CC, CC><<<hp_grid(M2, CC), 128, HP_SMEM>>>(p_q0nh, p_q0nl, p_Wqh, p_Wql,
        p_Q0, nullptr, nullptr, M2, CC, CC, nullptr, nullptr, 0, nullptr, nullptr);
    attn_b<<<dim3(M2, HH), 128>>>(p_KVb, p_Q0, p_c0h, p_c0l);
    hgemmP<0, CC, CC><<<hp_grid(M2, CC), 128, HP_SMEM>>>(p_c0h, p_c0l, p_Woh, p_Wol,
        p_y0, nullptr, nullptr, M2, CC, CC, nullptr, p_q0n, 0, nullptr, nullptr);
    ln_kernel<0, 1, 0, 0><<<M2, 256>>>(p_y0, nullptr, ffg, ffb, nullptr,
                                       nullptr, p_hn0h, p_hn0l, M2);
    hgemmP<2, CC, CC><<<hp_grid(M2, 2 * CC), 128, HP_SMEM>>>(p_hn0h, p_hn0l, p_W1h, p_W1l,
        nullptr, p_g10h, p_g10l, M2, 2 * CC, CC, b1, nullptr, 0, nullptr, nullptr);
    hgemmP<0, 2 * CC, 2 * CC><<<hp_grid(M2, CC), 128, HP_SMEM>>>(p_g10h, p_g10l, p_W2h, p_W2l,
        p_z0, nullptr, nullptr, M2, CC, 2 * CC, b2, p_y0, 0, nullptr, nullptr);
    ln_ct<1, 0, 1><<<M2 / 8, 256>>>(ztt, p_z0, tng, tnb, scale, p_rNsh, p_rNsl);
    hgemmP<4, CC, CC><<<hp_grid(M2, DP), 128, HP_SMEM>>>(p_rNsh, p_rNsl, p_Wdh, p_Wdl,
        p_rD0, p_rD0h, p_rD0l, M2, DP, CC, p_bdp, nullptr, 0, nullptr, nullptr);
    for (int st = 0; st < NBQ; st++) {
        const __half* Ahp = (st == 0) ? p_rD0h : p_re0h;
        const __half* Alp = (st == 0) ? p_rD0l : p_re0l;
        const float* Rin = (st == 0) ? p_rD0 : p_res0;
        hgemmP<3, DP, DD><<<hp_grid(M2, NEQ), 128, HP_SMEM>>>(Ahp, Alp,
            p_bkh + (size_t)st * NEQ * DD, p_bkl + (size_t)st * NEQ * DD,
            nullptr, nullptr, nullptr, M2, NEQ, DD, nullptr, nullptr, 0,
            p_cn + (size_t)st * NEQ, p_keys);
        rvq_update3<<<M2, DD>>>(p_keys, books + (size_t)st * NEQ * DD,
                                Rin, p_res0, p_re0h, p_re0l,
                                p_qD0, p_qD0h, p_qD0l,
                                st == 0 ? 1 : 0, st == NBQ - 1 ? 1 : 0);
    }
    hgemmP<0, DP, DD><<<hp_grid(M2, CC), 128, HP_SMEM>>>(p_qD0h, p_qD0l, p_Wuh, p_Wul,
        p_zh0, nullptr, nullptr, M2, CC, DD, bu, p_z0, 0, nullptr, nullptr);
    scatter_rows16_2<<<dim3(M2, 2), 256>>>(p_zh0, p_zh, p_rD0, p_rD);

    // ---- outputs ----
    transpose_tc_to_ct<1><<<dim3(TT / 32, CC / 32, BB), dim3(32, 8)>>>(p_zh, o_y, CC, TT, CC);
    if ((size_t)out_size >= (size_t)BB * CC * TT + (size_t)BB * DD * TT)
        transpose_tc_to_ct<0><<<dim3(TT / 32, DD / 32, BB), dim3(32, 8)>>>(p_rD, o_r, DD, TT, DP);
}

// round 16
// speedup vs baseline: 1.0478x; 1.0055x over previous
#include <cuda_runtime.h>
#include <cuda_fp16.h>
#include <math.h>
#include <stdint.h>

// ---------------- problem constants ----------------
#define BB   16
#define CC   1024
#define TT   2048
#define DD   96
#define DP   128                 // padded D stride
#define NBQ  4
#define NEQ  2048
#define HH   8
#define CHK  16
#define NCHK 128
#define NTOK 32768
#define M2   2048
#define DH   128

typedef unsigned long long u64;

// ---------------- fp32 scratch ----------------
__device__ float g_KVb[(size_t)NTOK*2*CC];
__device__ float g_y  [(size_t)NTOK*CC];
__device__ float g_zp [(size_t)NTOK*CC];
__device__ float g_zh [(size_t)NTOK*CC];
__device__ float g_rD [(size_t)NTOK*DP];
__device__ float g_res[(size_t)NTOK*DP];
__device__ float g_qDv[(size_t)NTOK*DP];
__device__ u64   g_keys[(size_t)NTOK];
__device__ float g_part[(size_t)8*M2*2*CC];    // split-K partials (pass B)

__device__ float g_q0n [(size_t)M2*CC];
__device__ float g_Q0  [(size_t)M2*CC];
__device__ float g_y0  [(size_t)M2*CC];
__device__ float g_z0  [(size_t)M2*CC];
__device__ float g_zh0 [(size_t)M2*CC];
__device__ float g_rD0 [(size_t)M2*DP];
__device__ float g_res0[(size_t)M2*DP];
__device__ float g_qD0 [(size_t)M2*DP];

__device__ float g_qc  [(size_t)CHK*CC];
__device__ float g_Qc  [(size_t)CHK*CC];
__device__ float g_cn  [(size_t)NBQ*NEQ];
__device__ float g_bdp [DP];

// ---------------- half hi/lo scratch ----------------
__device__ __half g_kvnh[(size_t)NTOK*CC], g_kvnl[(size_t)NTOK*CC];
__device__ __half g_ctxh[(size_t)NTOK*CC], g_ctxl[(size_t)NTOK*CC];
__device__ __half g_hnh [(size_t)NTOK*CC], g_hnl [(size_t)NTOK*CC];
__device__ __half g_s1h [(size_t)NTOK*2*CC], g_s1l [(size_t)NTOK*2*CC];
__device__ __half g_rNsh[(size_t)NTOK*CC], g_rNsl[(size_t)NTOK*CC];
__device__ __half g_rDh [(size_t)NTOK*DP], g_rDl [(size_t)NTOK*DP];
__device__ __half g_resh[(size_t)NTOK*DP], g_resl[(size_t)NTOK*DP];
__device__ __half g_qDh [(size_t)NTOK*DP], g_qDl [(size_t)NTOK*DP];

__device__ __half g_q0nh[(size_t)M2*CC], g_q0nl[(size_t)M2*CC];
__device__ __half g_c0h [(size_t)M2*CC], g_c0l [(size_t)M2*CC];
__device__ __half g_hn0h[(size_t)M2*CC], g_hn0l[(size_t)M2*CC];
__device__ __half g_g10h[(size_t)M2*2*CC], g_g10l[(size_t)M2*2*CC];
__device__ __half g_rD0h[(size_t)M2*DP], g_rD0l[(size_t)M2*DP];
__device__ __half g_re0h[(size_t)M2*DP], g_re0l[(size_t)M2*DP];
__device__ __half g_qD0h[(size_t)M2*DP], g_qD0l[(size_t)M2*DP];

// split weights [N,K]
__device__ __half g_Wkvh[(size_t)2*CC*CC], g_Wkvl[(size_t)2*CC*CC];
__device__ __half g_Wqh[(size_t)CC*CC], g_Wql[(size_t)CC*CC];
__device__ __half g_Woh[(size_t)CC*CC], g_Wol[(size_t)CC*CC];
__device__ __half g_W1h[(size_t)2*CC*CC], g_W1l[(size_t)2*CC*CC];
__device__ __half g_W2h[(size_t)CC*2*CC], g_W2l[(size_t)CC*2*CC];
__device__ __half g_Wdh[(size_t)DP*CC], g_Wdl[(size_t)DP*CC];
__device__ __half g_Wuh[(size_t)CC*DD], g_Wul[(size_t)CC*DD];
__device__ __half g_bkh[(size_t)NBQ*NEQ*DD], g_bkl[(size_t)NBQ*NEQ*DD];

__device__ __forceinline__ uint32_t smem_u32(const void* p) {
    uint32_t a;
    asm("{ .reg .u64 t; cvta.to.shared.u64 t, %1; cvt.u32.u64 %0, t; }" : "=r"(a) : "l"(p));
    return a;
}
__device__ __forceinline__ void mma16816(float* c, const uint32_t* a, const uint32_t* b) {
    asm volatile(
        "mma.sync.aligned.m16n8k16.row.col.f32.f16.f16.f32 "
        "{%0,%1,%2,%3}, {%4,%5,%6,%7}, {%8,%9}, {%0,%1,%2,%3};"
        : "+f"(c[0]), "+f"(c[1]), "+f"(c[2]), "+f"(c[3])
        : "r"(a[0]), "r"(a[1]), "r"(a[2]), "r"(a[3]), "r"(b[0]), "r"(b[1]));
}
__device__ __forceinline__ void ldmat4(uint32_t* r, uint32_t addr) {
    asm volatile("ldmatrix.sync.aligned.m8n8.x4.shared.b16 {%0,%1,%2,%3}, [%4];"
                 : "=r"(r[0]), "=r"(r[1]), "=r"(r[2]), "=r"(r[3]) : "r"(addr));
}
__device__ __forceinline__ void cp16(uint32_t dst, const void* src) {
    asm volatile("cp.async.cg.shared.global [%0], [%1], 16;\n" :: "r"(dst), "l"(src));
}
__device__ __forceinline__ void cpa_commit() { asm volatile("cp.async.commit_group;\n"); }
#define CPA_WAIT2() asm volatile("cp.async.wait_group 2;\n")
__device__ __forceinline__ void cpa_wait0() { asm volatile("cp.async.wait_group 0;\n"); }

// swizzled smem address: 128 rows x 64B, chunk-XOR swizzle
__device__ __forceinline__ uint32_t sw_addr(int row, int q) {
    return (uint32_t)(row * 64 + ((q ^ ((row >> 1) & 3)) << 4));
}

__device__ __forceinline__ float pe_val(int c, int t) {
    int ii = c >> 1;
    float div = expf((float)(2 * ii) * (-9.210340371976184f / (float)CC));
    float ang = (float)t * div;
    return (c & 1) ? cosf(ang) : sinf(ang);
}

// ---------------- split-input 3xFP16 GEMM: 128x128 tile, 128 thr, 3-stage, occ 2 ----
#define HP_STAGE 32768
#define HP_SMEM  (3 * HP_STAGE)

template <int EPI, int LDA, int LDB>
__global__ __launch_bounds__(128, 2) void hgemmP(
    const __half* __restrict__ Ah, const __half* __restrict__ Al,
    const __half* __restrict__ Bh, const __half* __restrict__ Bl,
    float* __restrict__ Co, __half* __restrict__ Oh, __half* __restrict__ Ol,
    int M, int N, int K,
    const float* __restrict__ bias, const float* __restrict__ add, int addPeriod,
    const float* __restrict__ cn, u64* __restrict__ keys) {
    extern __shared__ char sm[];
    const uint32_t sb = smem_u32(sm);
    const int tid = threadIdx.x;
    const int wid = tid >> 5, lane = tid & 31;
    const int wm = wid >> 1, wn = wid & 1;
    const int bm = blockIdx.y * 128, bn = blockIdx.x * 128;
    const int g = lane >> 2, tg = lane & 3;
    const int nt = K / 32;

    float acc[4][8][4];
#pragma unroll
    for (int i = 0; i < 4; i++)
#pragma unroll
        for (int j = 0; j < 8; j++)
#pragma unroll
            for (int q = 0; q < 4; q++) acc[i][j][q] = 0.f;

    const int lrow = (lane & 7) + ((lane >> 3) & 1) * 8;
    const int lq   = (lane >> 4) & 1;
    const int brow = (lane & 7) + ((lane >> 4) ? 8 : 0);
    const int bq   = (lane >> 3) & 1;

#define HP_LOAD(T) do {                                                         \
    int _t = (T);                                                               \
    if (_t < nt) {                                                              \
        uint32_t d0 = sb + (_t % 3) * HP_STAGE;                                 \
        _Pragma("unroll")                                                       \
        for (int j = 0; j < 16; j++) {                                          \
            int c = tid + j * 128;                                              \
            int mat = c >> 9;                                                   \
            int cc = c & 511;                                                   \
            int row = cc >> 2, q = cc & 3;                                      \
            const __half* src;                                                  \
            if (mat == 0)      src = Ah + (size_t)(bm + row) * LDA + _t * 32 + q * 8; \
            else if (mat == 1) src = Al + (size_t)(bm + row) * LDA + _t * 32 + q * 8; \
            else if (mat == 2) src = Bh + (size_t)(bn + row) * LDB + _t * 32 + q * 8; \
            else               src = Bl + (size_t)(bn + row) * LDB + _t * 32 + q * 8; \
            cp16(d0 + mat * 8192 + sw_addr(row, q), src);                       \
        }                                                                       \
    }                                                                           \
    cpa_commit();                                                               \
} while (0)

    HP_LOAD(0);
    HP_LOAD(1);
    HP_LOAD(2);

    for (int t = 0; t < nt; t++) {
        CPA_WAIT2();
        __syncthreads();
        const uint32_t tb = sb + (t % 3) * HP_STAGE;
#pragma unroll
        for (int ks = 0; ks < 2; ks++) {
            uint32_t ah[4][4], al[4][4];
#pragma unroll
            for (int mt = 0; mt < 4; mt++) {
                int row = wm * 64 + mt * 16 + lrow;
                uint32_t ad = tb + sw_addr(row, ks * 2 + lq);
                ldmat4(ah[mt], ad);
                ldmat4(al[mt], ad + 8192);
            }
            uint32_t bf[4][4];
#pragma unroll
            for (int p = 0; p < 4; p++) {
                int row = wn * 64 + p * 16 + brow;
                uint32_t bd = tb + 16384 + sw_addr(row, ks * 2 + bq);
                ldmat4(bf[p], bd);
            }
#pragma unroll
            for (int mt = 0; mt < 4; mt++)
#pragma unroll
                for (int p = 0; p < 4; p++) {
                    mma16816(acc[mt][2 * p],     ah[mt], &bf[p][0]);
                    mma16816(acc[mt][2 * p + 1], ah[mt], &bf[p][2]);
                    mma16816(acc[mt][2 * p],     al[mt], &bf[p][0]);
                    mma16816(acc[mt][2 * p + 1], al[mt], &bf[p][2]);
                }
#pragma unroll
            for (int p = 0; p < 4; p++) {
                int row = wn * 64 + p * 16 + brow;
                uint32_t bd = tb + 24576 + sw_addr(row, ks * 2 + bq);
                ldmat4(bf[p], bd);
            }
#pragma unroll
            for (int mt = 0; mt < 4; mt++)
#pragma unroll
                for (int p = 0; p < 4; p++) {
                    mma16816(acc[mt][2 * p],     ah[mt], &bf[p][0]);
                    mma16816(acc[mt][2 * p + 1], ah[mt], &bf[p][2]);
                }
        }
        __syncthreads();
        HP_LOAD(t + 3);
    }
#undef HP_LOAD

    if (EPI == 3) {
#pragma unroll
        for (int mt = 0; mt < 4; mt++) {
            int m0 = bm + wm * 64 + mt * 16 + g;
            int m1 = m0 + 8;
            u64 b0 = 0ull, b1 = 0ull;
#pragma unroll
            for (int nb = 0; nb < 8; nb++) {
                int n0 = bn + wn * 64 + nb * 8 + tg * 2;
                float s00 = acc[mt][nb][0] - cn[n0];
                float s01 = acc[mt][nb][1] - cn[n0 + 1];
                float s10 = acc[mt][nb][2] - cn[n0];
                float s11 = acc[mt][nb][3] - cn[n0 + 1];
                unsigned u;
                u = __float_as_uint(s00); u = (u & 0x80000000u) ? ~u : (u | 0x80000000u);
                u64 k = ((u64)u << 32) | (unsigned)(~n0);
                if (k > b0) b0 = k;
                u = __float_as_uint(s01); u = (u & 0x80000000u) ? ~u : (u | 0x80000000u);
                k = ((u64)u << 32) | (unsigned)(~(n0 + 1));
                if (k > b0) b0 = k;
                u = __float_as_uint(s10); u = (u & 0x80000000u) ? ~u : (u | 0x80000000u);
                k = ((u64)u << 32) | (unsigned)(~n0);
                if (k > b1) b1 = k;
                u = __float_as_uint(s11); u = (u & 0x80000000u) ? ~u : (u | 0x80000000u);
                k = ((u64)u << 32) | (unsigned)(~(n0 + 1));
                if (k > b1) b1 = k;
            }
#pragma unroll
            for (int o = 1; o < 4; o <<= 1) {
                u64 t0 = __shfl_xor_sync(0xffffffffu, b0, o);
                u64 t1 = __shfl_xor_sync(0xffffffffu, b1, o);
                if (t0 > b0) b0 = t0;
                if (t1 > b1) b1 = t1;
            }
            if (tg == 0) {
                atomicMax(&keys[m0], b0);
                atomicMax(&keys[m1], b1);
            }
        }
    } else {
#pragma unroll
        for (int mt = 0; mt < 4; mt++) {
            int m0 = bm + wm * 64 + mt * 16 + g;
            int m1 = m0 + 8;
            const float* add0 = (EPI == 0 && add)
                ? add + (size_t)((addPeriod > 0) ? (m0 % addPeriod) : m0) * N : nullptr;
            const float* add1 = (EPI == 0 && add)
                ? add + (size_t)((addPeriod > 0) ? (m1 % addPeriod) : m1) * N : nullptr;
#pragma unroll
            for (int nb = 0; nb < 8; nb++) {
                int n0 = bn + wn * 64 + nb * 8 + tg * 2;
                float v0 = acc[mt][nb][0], v1 = acc[mt][nb][1];
                float v2 = acc[mt][nb][2], v3 = acc[mt][nb][3];
                if (bias) {
                    float c0 = bias[n0], c1 = bias[n0 + 1];
                    v0 += c0; v1 += c1; v2 += c0; v3 += c1;
                }
                if (EPI == 0) {
                    if (add0) { v0 += add0[n0]; v1 += add0[n0 + 1]; }
                    if (add1) { v2 += add1[n0]; v3 += add1[n0 + 1]; }
                    *(float2*)(Co + (size_t)m0 * N + n0) = make_float2(v0, v1);
                    *(float2*)(Co + (size_t)m1 * N + n0) = make_float2(v2, v3);
                } else if (EPI == 4) {
                    *(float2*)(Co + (size_t)m0 * N + n0) = make_float2(v0, v1);
                    *(float2*)(Co + (size_t)m1 * N + n0) = make_float2(v2, v3);
                    __half2 h0 = __floats2half2_rn(v0, v1);
                    float2 f0 = __half22float2(h0);
                    __half2 l0 = __floats2half2_rn(v0 - f0.x, v1 - f0.y);
                    __half2 h1 = __floats2half2_rn(v2, v3);
                    float2 f1 = __half22float2(h1);
                    __half2 l1 = __floats2half2_rn(v2 - f1.x, v3 - f1.y);
                    *(__half2*)(Oh + (size_t)m0 * N + n0) = h0;
                    *(__half2*)(Ol + (size_t)m0 * N + n0) = l0;
                    *(__half2*)(Oh + (size_t)m1 * N + n0) = h1;
                    *(__half2*)(Ol + (size_t)m1 * N + n0) = l1;
                } else {  // EPI == 2
                    v0 = 0.5f * v0 * (1.0f + erff(v0 * 0.70710678118654752f));
                    v1 = 0.5f * v1 * (1.0f + erff(v1 * 0.70710678118654752f));
                    v2 = 0.5f * v2 * (1.0f + erff(v2 * 0.70710678118654752f));
                    v3 = 0.5f * v3 * (1.0f + erff(v3 * 0.70710678118654752f));
                    __half2 h0 = __floats2half2_rn(v0, v1);
                    float2 f0 = __half22float2(h0);
                    __half2 l0 = __floats2half2_rn(v0 - f0.x, v1 - f0.y);
                    __half2 h1 = __floats2half2_rn(v2, v3);
                    float2 f1 = __half22float2(h1);
                    __half2 l1 = __floats2half2_rn(v2 - f1.x, v3 - f1.y);
                    *(__half2*)(Oh + (size_t)m0 * N + n0) = h0;
                    *(__half2*)(Ol + (size_t)m0 * N + n0) = l0;
                    *(__half2*)(Oh + (size_t)m1 * N + n0) = h1;
                    *(__half2*)(Ol + (size_t)m1 * N + n0) = l1;
                }
            }
        }
    }
}

// ---------------- split-K GEMM (pass B latency): K-chunk 256 per blockIdx.z ----
template <int LDA, int LDB>
__global__ __launch_bounds__(128, 2) void hgemmSK(
    const __half* __restrict__ Ah, const __half* __restrict__ Al,
    const __half* __restrict__ Bh, const __half* __restrict__ Bl,
    float* __restrict__ Po, int M, int N) {
    constexpr int KC = 256;
    constexpr int nt = KC / 32;   // 8
    extern __shared__ char sm[];
    const uint32_t sb = smem_u32(sm);
    const int tid = threadIdx.x;
    const int wid = tid >> 5, lane = tid & 31;
    const int wm = wid >> 1, wn = wid & 1;
    const int bm = blockIdx.y * 128, bn = blockIdx.x * 128;
    const int kz = blockIdx.z * KC;
    const int g = lane >> 2, tg = lane & 3;

    float acc[4][8][4];
#pragma unroll
    for (int i = 0; i < 4; i++)
#pragma unroll
        for (int j = 0; j < 8; j++)
#pragma unroll
            for (int q = 0; q < 4; q++) acc[i][j][q] = 0.f;

    const int lrow = (lane & 7) + ((lane >> 3) & 1) * 8;
    const int lq   = (lane >> 4) & 1;
    const int brow = (lane & 7) + ((lane >> 4) ? 8 : 0);
    const int bq   = (lane >> 3) & 1;

#define SK_LOAD(T) do {                                                         \
    int _t = (T);                                                               \
    if (_t < nt) {                                                              \
        uint32_t d0 = sb + (_t % 3) * HP_STAGE;                                 \
        _Pragma("unroll")                                                       \
        for (int j = 0; j < 16; j++) {                                          \
            int c = tid + j * 128;                                              \
            int mat = c >> 9;                                                   \
            int cc = c & 511;                                                   \
            int row = cc >> 2, q = cc & 3;                                      \
            const __half* src;                                                  \
            if (mat == 0)      src = Ah + (size_t)(bm + row) * LDA + kz + _t * 32 + q * 8; \
            else if (mat == 1) src = Al + (size_t)(bm + row) * LDA + kz + _t * 32 + q * 8; \
            else if (mat == 2) src = Bh + (size_t)(bn + row) * LDB + kz + _t * 32 + q * 8; \
            else               src = Bl + (size_t)(bn + row) * LDB + kz + _t * 32 + q * 8; \
            cp16(d0 + mat * 8192 + sw_addr(row, q), src);                       \
        }                                                                       \
    }                                                                           \
    cpa_commit();                                                               \
} while (0)

    SK_LOAD(0);
    SK_LOAD(1);
    SK_LOAD(2);

    for (int t = 0; t < nt; t++) {
        CPA_WAIT2();
        __syncthreads();
        const uint32_t tb = sb + (t % 3) * HP_STAGE;
#pragma unroll
        for (int ks = 0; ks < 2; ks++) {
            uint32_t ah[4][4], al[4][4];
#pragma unroll
            for (int mt = 0; mt < 4; mt++) {
                int row = wm * 64 + mt * 16 + lrow;
                uint32_t ad = tb + sw_addr(row, ks * 2 + lq);
                ldmat4(ah[mt], ad);
                ldmat4(al[mt], ad + 8192);
            }
            uint32_t bf[4][4];
#pragma unroll
            for (int p = 0; p < 4; p++) {
                int row = wn * 64 + p * 16 + brow;
                uint32_t bd = tb + 16384 + sw_addr(row, ks * 2 + bq);
                ldmat4(bf[p], bd);
            }
#pragma unroll
            for (int mt = 0; mt < 4; mt++)
#pragma unroll
                for (int p = 0; p < 4; p++) {
                    mma16816(acc[mt][2 * p],     ah[mt], &bf[p][0]);
                    mma16816(acc[mt][2 * p + 1], ah[mt], &bf[p][2]);
                    mma16816(acc[mt][2 * p],     al[mt], &bf[p][0]);
                    mma16816(acc[mt][2 * p + 1], al[mt], &bf[p][2]);
                }
#pragma unroll
            for (int p = 0; p < 4; p++) {
                int row = wn * 64 + p * 16 + brow;
                uint32_t bd = tb + 24576 + sw_addr(row, ks * 2 + bq);
                ldmat4(bf[p], bd);
            }
#pragma unroll
            for (int mt = 0; mt < 4; mt++)
#pragma unroll
                for (int p = 0; p < 4; p++) {
                    mma16816(acc[mt][2 * p],     ah[mt], &bf[p][0]);
                    mma16816(acc[mt][2 * p + 1], ah[mt], &bf[p][2]);
                }
        }
        __syncthreads();
        SK_LOAD(t + 3);
    }
#undef SK_LOAD

    float* base = Po + (size_t)blockIdx.z * M * N;
#pragma unroll
    for (int mt = 0; mt < 4; mt++) {
        int m0 = bm + wm * 64 + mt * 16 + g;
        int m1 = m0 + 8;
#pragma unroll
        for (int nb = 0; nb < 8; nb++) {
            int n0 = bn + wn * 64 + nb * 8 + tg * 2;
            *(float2*)(base + (size_t)m0 * N + n0) = make_float2(acc[mt][nb][0], acc[mt][nb][1]);
            *(float2*)(base + (size_t)m1 * N + n0) = make_float2(acc[mt][nb][2], acc[mt][nb][3]);
        }
    }
}

// reduce Z split-K partials + epilogue. EPI 0: fp32 (+bias)(+add[m]);
// EPI 2: gelu(+bias) -> halves; EPI 4: fp32 (+bias) AND halves.
template <int EPI>
__global__ void reduceK(const float* __restrict__ part, int Z, int M, int N,
                        const float* __restrict__ bias, const float* __restrict__ add,
                        float* __restrict__ Co, __half* __restrict__ Oh,
                        __half* __restrict__ Ol) {
    size_t i = ((size_t)blockIdx.x * 256 + threadIdx.x) * 4;
    size_t total = (size_t)M * N;
    if (i >= total) return;
    float4 s = *(const float4*)(part + i);
    for (int z = 1; z < Z; z++) {
        float4 p = *(const float4*)(part + (size_t)z * total + i);
        s.x += p.x; s.y += p.y; s.z += p.z; s.w += p.w;
    }
    int n = (int)(i % (size_t)N);
    size_t mrow = i - n;   // m*N
    float v[4] = {s.x, s.y, s.z, s.w};
    if (bias) {
#pragma unroll
        for (int j = 0; j < 4; j++) v[j] += bias[n + j];
    }
    if (EPI == 0) {
        if (add) {
#pragma unroll
            for (int j = 0; j < 4; j++) v[j] += add[mrow + n + j];
        }
        *(float4*)(Co + i) = make_float4(v[0], v[1], v[2], v[3]);
    } else if (EPI == 2) {
#pragma unroll
        for (int j = 0; j < 4; j++)
            v[j] = 0.5f * v[j] * (1.0f + erff(v[j] * 0.70710678118654752f));
        __half2 h0 = __floats2half2_rn(v[0], v[1]);
        float2 f0 = __half22float2(h0);
        __half2 l0 = __floats2half2_rn(v[0] - f0.x, v[1] - f0.y);
        __half2 h1 = __floats2half2_rn(v[2], v[3]);
        float2 f1 = __half22float2(h1);
        __half2 l1 = __floats2half2_rn(v[2] - f1.x, v[3] - f1.y);
        *(__half2*)(Oh + i) = h0; *(__half2*)(Oh + i + 2) = h1;
        *(__half2*)(Ol + i) = l0; *(__half2*)(Ol + i + 2) = l1;
    } else {  // EPI == 4
        *(float4*)(Co + i) = make_float4(v[0], v[1], v[2], v[3]);
        __half2 h0 = __floats2half2_rn(v[0], v[1]);
        float2 f0 = __half22float2(h0);
        __half2 l0 = __floats2half2_rn(v[0] - f0.x, v[1] - f0.y);
        __half2 h1 = __floats2half2_rn(v[2], v[3]);
        float2 f1 = __half22float2(h1);
        __half2 l1 = __floats2half2_rn(v[2] - f1.x, v[3] - f1.y);
        *(__half2*)(Oh + i) = h0; *(__half2*)(Oh + i + 2) = h1;
        *(__half2*)(Ol + i) = l0; *(__half2*)(Ol + i + 2) = l1;
    }
}

// ---------------- setup kernels ----------------
__global__ __launch_bounds__(DD) void prep_books(
    const float* __restrict__ books, const float* __restrict__ bd,
    float* __restrict__ cn, float* __restrict__ bdp,
    __half* __restrict__ bh, __half* __restrict__ bl) {
    int e = blockIdx.x;
    int d = threadIdx.x;
    if (e == NBQ * NEQ) {
        bdp[d] = bd[d];
        if (d < DP - DD) bdp[DD + d] = 0.0f;
        return;
    }
    __shared__ float red[3];
    float v = books[(size_t)e * DD + d];
    __half h = __float2half_rn(v);
    bh[(size_t)e * DD + d] = h;
    bl[(size_t)e * DD + d] = __float2half_rn(v - __half2float(h));
    float s = v * v;
#pragma unroll
    for (int o = 16; o; o >>= 1) s += __shfl_xor_sync(0xffffffffu, s, o);
    int w = d >> 5;
    if ((d & 31) == 0) red[w] = s;
    __syncthreads();
    if (d == 0) cn[e] = 0.5f * (red[0] + red[1] + red[2]);
}

__global__ void split_f32(const float* __restrict__ src, __half* __restrict__ h,
                          __half* __restrict__ l, int n) {
    int i = blockIdx.x * 256 + threadIdx.x;
    if (i >= n) return;
    float v = src[i];
    __half hi = __float2half_rn(v);
    h[i] = hi;
    l[i] = __float2half_rn(v - __half2float(hi));
}

// ---------------- transposes ----------------
__global__ void transpose_split2(const float* __restrict__ inA, __half* __restrict__ ohA,
                                 __half* __restrict__ olA,
                                 const float* __restrict__ inB, __half* __restrict__ ohB,
                                 __half* __restrict__ olB, int Cdim, int Tdim) {
    __shared__ float tile[32][33];
    int which = blockIdx.z;
    const float* in = which ? inB : inA;
    __half* oh = which ? ohB : ohA;
    __half* ol = which ? olB : olA;
    int c0 = blockIdx.y * 32, t0 = blockIdx.x * 32;
    int x = threadIdx.x, y = threadIdx.y;
    for (int i = 0; i < 32; i += 8)
        tile[y + i][x] = in[(size_t)(c0 + y + i) * Tdim + t0 + x];
    __syncthreads();
    for (int i = 0; i < 32; i += 8) {
        float v = tile[x][y + i];
        __half h = __float2half_rn(v);
        size_t o = (size_t)(t0 + y + i) * Cdim + c0 + x;
        oh[o] = h;
        ol[o] = __float2half_rn(v - __half2float(h));
    }
}

template <int NANFIX>
__global__ void transpose_tc_to_ct(const float* __restrict__ in, float* __restrict__ out,
                                   int Cdim, int Tdim, int srcLd) {
    __shared__ float tile[32][33];
    int b = blockIdx.z;
    int c0 = blockIdx.y * 32, t0 = blockIdx.x * 32;
    int x = threadIdx.x, y = threadIdx.y;
    for (int i = 0; i < 32; i += 8)
        tile[y + i][x] = in[((size_t)b * Tdim + t0 + y + i) * srcLd + c0 + x];
    __syncthreads();
    for (int i = 0; i < 32; i += 8) {
        float v = tile[x][y + i];
        if (NANFIX) { if (!isfinite(v)) v = 0.0f; }
        out[((size_t)b * Cdim + c0 + y + i) * Tdim + t0 + x] = v;
    }
}

// ---------------- LN reading directly from (B,C,T) layout ----------------
template <int POST, int PE, int GATHER>
__global__ __launch_bounds__(256) void ln_ct(
    const float* __restrict__ ct, const float* __restrict__ in1,
    const float* __restrict__ gamma, const float* __restrict__ beta,
    const float* __restrict__ scale_ptr,
    __half* __restrict__ oh, __half* __restrict__ ol) {
    __shared__ float tile[CC * 9];
    const int tid = threadIdx.x;
    const int m8 = blockIdx.x * 8;
#pragma unroll
    for (int i = 0; i < 32; i++) {
        int idx = tid + i * 256;
        int c = idx >> 3, x = idx & 7;
        int m = m8 + x;
        size_t src;
        if (GATHER) {
            int b = m / NCHK, t = (m % NCHK) * 16;
            src = ((size_t)b * CC + c) * TT + t;
        } else {
            int b = m >> 11, t = m & (TT - 1);
            src = ((size_t)b * CC + c) * TT + t;
        }
        tile[c * 9 + x] = ct[src];
    }
    __syncthreads();

    const int w = tid >> 5, lane = tid & 31;
    const int m = m8 + w;
    float x[32];
    float s = 0.f;
#pragma unroll
    for (int k = 0; k < 32; k++) {
        int c = lane + k * 32;
        float v = tile[c * 9 + w];
        if (in1) v -= in1[(size_t)m * CC + c];
        if (PE == 1) v += pe_val(c, m & 15);
        x[k] = v;
        s += v;
    }
#pragma unroll
    for (int o = 16; o; o >>= 1) s += __shfl_xor_sync(0xffffffffu, s, o);
    float mean = s * (1.0f / (float)CC);
    float vs = 0.f;
#pragma unroll
    for (int k = 0; k < 32; k++) { float d = x[k] - mean; vs += d * d; }
#pragma unroll
    for (int o = 16; o; o >>= 1) vs += __shfl_xor_sync(0xffffffffu, vs, o);
    float rstd = rsqrtf(vs * (1.0f / (float)CC) + 1e-5f);
    float sc = 1.0f;
    if (POST == 1) {
        float t = scale_ptr[0];
        sc = fminf(fmaxf(t, 0.005f), 0.5f);
    }
#pragma unroll
    for (int k = 0; k < 32; k++) {
        int c = lane + k * 32;
        float yv = (x[k] - mean) * rstd * gamma[c] + beta[c];
        if (POST == 1) yv = tanhf(yv) * sc;
        __half h = __float2half_rn(yv);
        oh[(size_t)m * CC + c] = h;
        ol[(size_t)m * CC + c] = __float2half_rn(yv - __half2float(h));
    }
}

// ---------------- token-major LayerNorm ----------------
template <int POST, int SPLIT, int PE, int SRC>
__global__ __launch_bounds__(256) void ln_kernel(
    const float* __restrict__ in0, const float* __restrict__ in1,
    const float* __restrict__ gamma, const float* __restrict__ beta,
    const float* __restrict__ scale_ptr, float* __restrict__ out,
    __half* __restrict__ oh, __half* __restrict__ ol, int Mrows) {
    int m = blockIdx.x;
    if (m >= Mrows) return;
    int tid = threadIdx.x;
    int lane = tid & 31, warp = tid >> 5;
    __shared__ float red[8];
    float x[4];
#pragma unroll
    for (int k = 0; k < 4; k++) {
        int c = tid + k * 256;
        float v;
        if (SRC == 1) {
            v = (m & (NCHK - 1)) ? in0[((size_t)m * 16 - 1) * CC + c] : 0.0f;
        } else {
            v = in0 ? in0[(size_t)m * CC + c] : 0.0f;
        }
        if (in1) v -= in1[(size_t)m * CC + c];
        if (PE == 1) v += pe_val(c, m & 15);
        else if (PE == 2) v += pe_val(c, 0);
        x[k] = v;
    }
    float s = x[0] + x[1] + x[2] + x[3];
#pragma unroll
    for (int o = 16; o; o >>= 1) s += __shfl_xor_sync(0xffffffffu, s, o);
    if (lane == 0) red[warp] = s;
    __syncthreads();
    float mean;
    {
        float t = (lane < 8) ? red[lane] : 0.f;
#pragma unroll
        for (int o = 4; o; o >>= 1) t += __shfl_xor_sync(0xffffffffu, t, o);
        mean = __shfl_sync(0xffffffffu, t, 0) * (1.0f / (float)CC);
    }
    float vs = 0.f;
#pragma unroll
    for (int k = 0; k < 4; k++) { float d = x[k] - mean; vs += d * d; }
#pragma unroll
    for (int o = 16; o; o >>= 1) vs += __shfl_xor_sync(0xffffffffu, vs, o);
    __syncthreads();
    if (lane == 0) red[warp] = vs;
    __syncthreads();
    float var;
    {
        float t = (lane < 8) ? red[lane] : 0.f;
#pragma unroll
        for (int o = 4; o; o >>= 1) t += __shfl_xor_sync(0xffffffffu, t, o);
        var = __shfl_sync(0xffffffffu, t, 0) * (1.0f / (float)CC);
    }
    float rstd = rsqrtf(var + 1e-5f);
    float sc = 1.0f;
    if (POST == 1) {
        float t = scale_ptr[0];
        sc = fminf(fmaxf(t, 0.005f), 0.5f);
    }
#pragma unroll
    for (int k = 0; k < 4; k++) {
        int c = tid + k * 256;
        float yv = (x[k] - mean) * rstd * gamma[c] + beta[c];
        if (POST == 1) yv = tanhf(yv) * sc;
        if (SPLIT != 1) out[(size_t)m * CC + c] = yv;
        if (SPLIT >= 1) {
            __half h = __float2half_rn(yv);
            oh[(size_t)m * CC + c] = h;
            ol[(size_t)m * CC + c] = __float2half_rn(yv - __half2float(h));
        }
    }
}

// ---------------- f32x2 helpers (scalar GEMM for tiny Qc) ----------------
__device__ __forceinline__ u64 pack2(float x) {
    u64 r;
    asm("mov.b64 %0, {%1, %1};" : "=l"(r) : "f"(x));
    return r;
}
__device__ __forceinline__ float2 unpack2(u64 v) {
    float2 f;
    asm("mov.b64 {%0, %1}, %2;" : "=f"(f.x), "=f"(f.y) : "l"(v));
    return f;
}
#define FFMA2(d, a, b) asm("fma.rn.f32x2 %0, %1, %2, %0;" : "+l"(d) : "l"(a), "l"(b))

__device__ __forceinline__ void cpa16p(void* dst, const void* src, bool pred) {
    unsigned int d = (unsigned int)__cvta_generic_to_shared(dst);
    int sz = pred ? 16 : 0;
    asm volatile("cp.async.ca.shared.global [%0], [%1], 16, %2;\n" :: "r"(d), "l"(src), "r"(sz));
}

template <bool GUARD>
__global__ __launch_bounds__(256, 2) void sgemm2(
    const float* __restrict__ A, const float* __restrict__ Bm, float* __restrict__ Co,
    int M, int N, int K, const float* __restrict__ bias) {
    __shared__ __align__(16) float As[2][16][128];
    __shared__ __align__(16) float Bs[2][16][128];
    const int tid = threadIdx.x;
    const int bm = blockIdx.y * 128, bn = blockIdx.x * 128;
    const int tx = tid & 15, ty = tid >> 4;

    const int a_row  = tid >> 1;
    const int a_koff = (tid & 1) * 8;
    const int b_row  = tid >> 5;
    const int b_col  = (tid & 31) * 4;

    const bool a_ok = !GUARD || (bm + a_row < M);
    const bool b_ok = !GUARD || (bn + b_col < N);
    const float* a_src0 = A + (size_t)(GUARD ? (a_ok ? bm + a_row : 0) : (bm + a_row)) * K + a_koff;
    const float* b_src0 = Bm + (size_t)b_row * N + (GUARD ? (b_ok ? bn + b_col : 0) : (bn + b_col));
    const float* b_src1 = b_src0 + (size_t)8 * N;

    u64 acc2[8][4];
#pragma unroll
    for (int i = 0; i < 8; i++)
#pragma unroll
        for (int q = 0; q < 4; q++) acc2[i][q] = 0ull;

    float a_reg[8];
    const int nt = K / 16;

    {
        if (a_ok) {
            float4 v0 = *(const float4*)(a_src0);
            float4 v1 = *(const float4*)(a_src0 + 4);
            a_reg[0]=v0.x; a_reg[1]=v0.y; a_reg[2]=v0.z; a_reg[3]=v0.w;
            a_reg[4]=v1.x; a_reg[5]=v1.y; a_reg[6]=v1.z; a_reg[7]=v1.w;
        } else {
#pragma unroll
            for (int c = 0; c < 8; c++) a_reg[c] = 0.f;
        }
        cpa16p(&Bs[0][b_row][b_col],     b_src0, b_ok);
        cpa16p(&Bs[0][8 + b_row][b_col], b_src1, b_ok);
        cpa_commit();
#pragma unroll
        for (int c = 0; c < 8; c++) As[0][a_koff + c][a_row] = a_reg[c];
        cpa_wait0();
        __syncthreads();
    }

    int buf = 0;
    for (int t = 0; t < nt; t++) {
        const bool has_next = (t + 1 < nt);
        if (has_next) {
            const float* ap = a_src0 + (size_t)(t + 1) * 16;
            if (a_ok) {
                float4 v0 = *(const float4*)(ap);
                float4 v1 = *(const float4*)(ap + 4);
                a_reg[0]=v0.x; a_reg[1]=v0.y; a_reg[2]=v0.z; a_reg[3]=v0.w;
                a_reg[4]=v1.x; a_reg[5]=v1.y; a_reg[6]=v1.z; a_reg[7]=v1.w;
            }
            cpa16p(&Bs[buf ^ 1][b_row][b_col],     b_src0 + (size_t)(t + 1) * 16 * N, b_ok);
            cpa16p(&Bs[buf ^ 1][8 + b_row][b_col], b_src1 + (size_t)(t + 1) * 16 * N, b_ok);
            cpa_commit();
        }
#pragma unroll
        for (int kk = 0; kk < 16; kk++) {
            float4 a0 = *(const float4*)&As[buf][kk][ty * 8];
            float4 a1 = *(const float4*)&As[buf][kk][ty * 8 + 4];
            ulonglong2 bl = *(const ulonglong2*)&Bs[buf][kk][tx * 4];
            ulonglong2 bh = *(const ulonglong2*)&Bs[buf][kk][64 + tx * 4];
            float am[8] = {a0.x, a0.y, a0.z, a0.w, a1.x, a1.y, a1.z, a1.w};
#pragma unroll
            for (int i = 0; i < 8; i++) {
                u64 ai = pack2(am[i]);
                FFMA2(acc2[i][0], ai, bl.x);
                FFMA2(acc2[i][1], ai, bl.y);
                FFMA2(acc2[i][2], ai, bh.x);
                FFMA2(acc2[i][3], ai, bh.y);
            }
        }
        if (has_next) {
#pragma unroll
            for (int c = 0; c < 8; c++) As[buf ^ 1][a_koff + c][a_row] = a_reg[c];
            cpa_wait0();
            __syncthreads();
            buf ^= 1;
        }
    }

#pragma unroll
    for (int i = 0; i < 8; i++) {
        int m = bm + ty * 8 + i;
        if (GUARD && m >= M) continue;
#pragma unroll
        for (int q = 0; q < 4; q++) {
            float2 v2 = unpack2(acc2[i][q]);
            int n0 = bn + ((q < 2) ? (tx * 4 + q * 2) : (64 + tx * 4 + (q - 2) * 2));
#pragma unroll
            for (int h = 0; h < 2; h++) {
                int n = n0 + h;
                if (GUARD && n >= N) continue;
                float v = h ? v2.y : v2.x;
                if (bias) v += bias[n];
                Co[(size_t)m * N + n] = v;
            }
        }
    }
}

// ---------------- attention ----------------
__global__ __launch_bounds__(256) void attn_a(const float* __restrict__ KVb,
                                              const float* __restrict__ Qc,
                                              __half* __restrict__ ctxh,
                                              __half* __restrict__ ctxl) {
    int gb = blockIdx.x;
    int h = blockIdx.y;
    int tid = threadIdx.x;
    __shared__ float Ks[16][133], Vs[16][133], Qs[16][133];
    __shared__ float Ss[16][17];
    for (int i = tid; i < 16 * DH; i += 256) {
        int t = i >> 7, d = i & 127;
        size_t base = ((size_t)(gb * 16 + t)) * (2 * CC) + (size_t)h * DH + d;
        Ks[t][d] = KVb[base];
        Vs[t][d] = KVb[base + CC];
        Qs[t][d] = Qc[(size_t)t * CC + (size_t)h * DH + d];
    }
    __syncthreads();
    {
        int q = tid >> 4, k = tid & 15;
        float s = 0.f;
#pragma unroll 8
        for (int d = 0; d < DH; d++) s = fmaf(Qs[q][d], Ks[k][d], s);
        Ss[q][k] = s * 0.08838834764831845f;
    }
    __syncthreads();
    if (tid < 16) {
        float mx = -1e30f;
        for (int k = 0; k < 16; k++) mx = fmaxf(mx, Ss[tid][k]);
        float e[16], sum = 0.f;
        for (int k = 0; k < 16; k++) { e[k] = expf(Ss[tid][k] - mx); sum += e[k]; }
        float inv = 1.0f / sum;
        for (int k = 0; k < 16; k++) Ss[tid][k] = e[k] * inv;
    }
    __syncthreads();
    for (int i = tid; i < 16 * DH; i += 256) {
        int t = i >> 7, d = i & 127;
        float a = 0.f;
#pragma unroll
        for (int k = 0; k < 16; k++) a = fmaf(Ss[t][k], Vs[k][d], a);
        size_t o = ((size_t)(gb * 16 + t)) * CC + (size_t)h * DH + d;
        __half hh = __float2half_rn(a);
        ctxh[o] = hh;
        ctxl[o] = __float2half_rn(a - __half2float(hh));
    }
}

__global__ __launch_bounds__(128) void attn_b(const float* __restrict__ KVb,
                                              const float* __restrict__ Q0,
                                              __half* __restrict__ ctxh,
                                              __half* __restrict__ ctxl) {
    int p = blockIdx.x;
    int h = blockIdx.y;
    int tid = threadIdx.x;
    __shared__ float Ks[16][128], Vs[16][128], Qs[128];
    __shared__ float sc[16];
    for (int i = tid; i < 16 * DH; i += 128) {
        int t = i >> 7, d = i & 127;
        size_t base = ((size_t)(p * 16 + t)) * (2 * CC) + (size_t)h * DH + d;
        Ks[t][d] = KVb[base];
        Vs[t][d] = KVb[base + CC];
    }
    Qs[tid] = Q0[(size_t)p * CC + (size_t)h * DH + tid];
    __syncthreads();
    int w = tid >> 5, l = tid & 31;
    for (int k = w; k < 16; k += 4) {
        float s = Qs[l] * Ks[k][l] + Qs[l + 32] * Ks[k][l + 32] +
                  Qs[l + 64] * Ks[k][l + 64] + Qs[l + 96] * Ks[k][l + 96];
        for (int o = 16; o; o >>= 1) s += __shfl_xor_sync(0xffffffffu, s, o);
        if (l == 0) sc[k] = s * 0.08838834764831845f;
    }
    __syncthreads();
    if (tid == 0) {
        float mx = -1e30f;
        for (int k = 0; k < 16; k++) mx = fmaxf(mx, sc[k]);
        float e[16], sum = 0.f;
        for (int k = 0; k < 16; k++) { e[k] = expf(sc[k] - mx); sum += e[k]; }
        float inv = 1.0f / sum;
        for (int k = 0; k < 16; k++) sc[k] = e[k] * inv;
    }
    __syncthreads();
    float a = 0.f;
#pragma unroll
    for (int k = 0; k < 16; k++) a = fmaf(sc[k], Vs[k][tid], a);
    size_t o = (size_t)p * CC + (size_t)h * DH + tid;
    __half hh = __float2half_rn(a);
    ctxh[o] = hh;
    ctxl[o] = __float2half_rn(a - __half2float(hh));
}

// ---------------- RVQ update (padded stride DP; resets keys) ----------------
__global__ void rvq_update3(u64* __restrict__ keys,
                            const float* __restrict__ books_st,
                            const float* __restrict__ resid_in,
                            float* __restrict__ resid_out,
                            __half* __restrict__ resh, __half* __restrict__ resl,
                            float* __restrict__ qD,
                            __half* __restrict__ qDh, __half* __restrict__ qDl,
                            int firstStage, int lastStage) {
    int m = blockIdx.x;
    int d = threadIdx.x;   // 96 threads
    int idx = (int)(~(unsigned)(keys[m] & 0xffffffffu)) & (NEQ - 1);
    __syncthreads();
    if (d == 0) keys[m] = 0ull;
    float e = books_st[(size_t)idx * DD + d];
    float r = resid_in[(size_t)m * DP + d];
    float nr = r - e;
    resid_out[(size_t)m * DP + d] = nr;
    __half hh = __float2half_rn(nr);
    resh[(size_t)m * DP + d] = hh;
    resl[(size_t)m * DP + d] = __float2half_rn(nr - __half2float(hh));
    float q = firstStage ? e : (qD[(size_t)m * DP + d] + e);
    qD[(size_t)m * DP + d] = q;
    if (lastStage) {
        __half qh = __float2half_rn(q);
        qDh[(size_t)m * DP + d] = qh;
        qDl[(size_t)m * DP + d] = __float2half_rn(q - __half2float(qh));
    }
}

// ---------------- misc ----------------
__global__ void scatter_rows16_2(const float* __restrict__ inA, float* __restrict__ outA,
                                 const float* __restrict__ inB, float* __restrict__ outB) {
    int p = blockIdx.x;
    if (blockIdx.y == 0) {
        for (int c = threadIdx.x; c < CC; c += blockDim.x)
            outA[((size_t)p * 16) * CC + c] = inA[(size_t)p * CC + c];
    } else {
        for (int c = threadIdx.x; c < DD; c += blockDim.x)
            outB[((size_t)p * 16) * DP + c] = inB[(size_t)p * DP + c];
    }
}

// ---------------- host ----------------
static inline dim3 gemm_grid(int M, int N) { return dim3((N + 127) / 128, (M + 127) / 128); }
static inline dim3 hp_grid(int M, int N) { return dim3(N / 128, M / 128); }

extern "C" void kernel_launch(void* const* d_in, const int* in_sizes, int n_in,
                              void* d_out, int out_size) {
    const float* qa     = (const float*)d_in[0];
    const float* ztt    = (const float*)d_in[1];
    const float* ln_q_g = (const float*)d_in[2];
    const float* ln_q_b = (const float*)d_in[3];
    const float* ln_kv_g= (const float*)d_in[4];
    const float* ln_kv_b= (const float*)d_in[5];
    const float* Wq     = (const float*)d_in[6];
    const float* Wk     = (const float*)d_in[7];
    const float* Wv     = (const float*)d_in[8];
    const float* Wo     = (const float*)d_in[9];
    const float* ffg    = (const float*)d_in[10];
    const float* ffb    = (const float*)d_in[11];
    const float* W1     = (const float*)d_in[12];
    const float* b1     = (const float*)d_in[13];
    const float* W2     = (const float*)d_in[14];
    const float* b2     = (const float*)d_in[15];
    const float* tng    = (const float*)d_in[16];
    const float* tnb    = (const float*)d_in[17];
    const float* scale  = (const float*)d_in[18];
    const float* Wd     = (const float*)d_in[19];
    const float* bd     = (const float*)d_in[20];
    const float* Wu     = (const float*)d_in[21];
    const float* bu     = (const float*)d_in[22];
    const float* books  = (const float*)d_in[23];

    float* out = (float*)d_out;
    float* o_y = out;
    float* o_r = out + (size_t)BB * CC * TT;

#define SYMF(p, s) float* p; cudaGetSymbolAddress((void**)&p, s)
#define SYMH(p, s) __half* p; cudaGetSymbolAddress((void**)&p, s)
    SYMF(p_KVb, g_KVb);
    SYMF(p_y, g_y);     SYMF(p_zp, g_zp);   SYMF(p_zh, g_zh);
    SYMF(p_rD, g_rD);   SYMF(p_res, g_res); SYMF(p_qDv, g_qDv);
    SYMF(p_part, g_part);
    SYMF(p_q0n, g_q0n); SYMF(p_Q0, g_Q0);
    SYMF(p_y0, g_y0);   SYMF(p_z0, g_z0);
    SYMF(p_zh0, g_zh0);
    SYMF(p_rD0, g_rD0); SYMF(p_res0, g_res0); SYMF(p_qD0, g_qD0);
    SYMF(p_qc, g_qc);   SYMF(p_Qc, g_Qc);
    SYMF(p_cn, g_cn);   SYMF(p_bdp, g_bdp);
    SYMH(p_kvnh, g_kvnh); SYMH(p_kvnl, g_kvnl);
    SYMH(p_ctxh, g_ctxh); SYMH(p_ctxl, g_ctxl);
    SYMH(p_hnh, g_hnh);   SYMH(p_hnl, g_hnl);
    SYMH(p_s1h, g_s1h);   SYMH(p_s1l, g_s1l);
    SYMH(p_rNsh, g_rNsh); SYMH(p_rNsl, g_rNsl);
    SYMH(p_rDh, g_rDh);   SYMH(p_rDl, g_rDl);
    SYMH(p_resh, g_resh); SYMH(p_resl, g_resl);
    SYMH(p_qDh, g_qDh);   SYMH(p_qDl, g_qDl);
    SYMH(p_q0nh, g_q0nh); SYMH(p_q0nl, g_q0nl);
    SYMH(p_c0h, g_c0h);   SYMH(p_c0l, g_c0l);
    SYMH(p_hn0h, g_hn0h); SYMH(p_hn0l, g_hn0l);
    SYMH(p_g10h, g_g10h); SYMH(p_g10l, g_g10l);
    SYMH(p_rD0h, g_rD0h); SYMH(p_rD0l, g_rD0l);
    SYMH(p_re0h, g_re0h); SYMH(p_re0l, g_re0l);
    SYMH(p_qD0h, g_qD0h); SYMH(p_qD0l, g_qD0l);
    SYMH(p_Wkvh, g_Wkvh); SYMH(p_Wkvl, g_Wkvl);
    SYMH(p_Wqh, g_Wqh); SYMH(p_Wql, g_Wql);
    SYMH(p_Woh, g_Woh); SYMH(p_Wol, g_Wol);
    SYMH(p_W1h, g_W1h); SYMH(p_W1l, g_W1l);
    SYMH(p_W2h, g_W2h); SYMH(p_W2l, g_W2l);
    SYMH(p_Wdh, g_Wdh); SYMH(p_Wdl, g_Wdl);
    SYMH(p_Wuh, g_Wuh); SYMH(p_Wul, g_Wul);
    SYMH(p_bkh, g_bkh); SYMH(p_bkl, g_bkl);
#undef SYMF
#undef SYMH
    u64* p_keys; cudaGetSymbolAddress((void**)&p_keys, g_keys);

    cudaFuncSetAttribute(hgemmP<0, CC, CC>, cudaFuncAttributeMaxDynamicSharedMemorySize, HP_SMEM);
    cudaFuncSetAttribute(hgemmP<2, CC, CC>, cudaFuncAttributeMaxDynamicSharedMemorySize, HP_SMEM);
    cudaFuncSetAttribute(hgemmP<0, 2 * CC, 2 * CC>, cudaFuncAttributeMaxDynamicSharedMemorySize, HP_SMEM);
    cudaFuncSetAttribute(hgemmP<4, CC, CC>, cudaFuncAttributeMaxDynamicSharedMemorySize, HP_SMEM);
    cudaFuncSetAttribute(hgemmP<3, DP, DD>, cudaFuncAttributeMaxDynamicSharedMemorySize, HP_SMEM);
    cudaFuncSetAttribute(hgemmP<0, DP, DD>, cudaFuncAttributeMaxDynamicSharedMemorySize, HP_SMEM);
    cudaFuncSetAttribute(hgemmSK<CC, CC>, cudaFuncAttributeMaxDynamicSharedMemorySize, HP_SMEM);
    cudaFuncSetAttribute(hgemmSK<2 * CC, 2 * CC>, cudaFuncAttributeMaxDynamicSharedMemorySize, HP_SMEM);

    // ---- setup head; big KV GEMM early ----
    ln_ct<0, 1, 0><<<NTOK / 8, 256>>>(qa, nullptr, ln_kv_g, ln_kv_b, nullptr,
                                      p_kvnh, p_kvnl);
    transpose_split2<<<dim3(32, 32, 2), dim3(32, 8)>>>(Wk, p_Wkvh, p_Wkvl,
                                                       Wv, p_Wkvh + (size_t)CC * CC,
                                                       p_Wkvl + (size_t)CC * CC, CC, CC);
    hgemmP<0, CC, CC><<<hp_grid(NTOK, 2 * CC), 128, HP_SMEM>>>(p_kvnh, p_kvnl, p_Wkvh, p_Wkvl,
        p_KVb, nullptr, nullptr, NTOK, 2 * CC, CC, nullptr, nullptr, 0, nullptr, nullptr);

    // ---- remaining setup ----
    prep_books<<<NBQ * NEQ + 1, DD>>>(books, bd, p_cn, p_bdp, p_bkh, p_bkl);
    transpose_split2<<<dim3(32, 32, 2), dim3(32, 8)>>>(Wq, p_Wqh, p_Wql,
                                                       Wo, p_Woh, p_Wol, CC, CC);
    transpose_split2<<<dim3(64, 32, 1), dim3(32, 8)>>>(W1, p_W1h, p_W1l,
                                                       nullptr, nullptr, nullptr, CC, 2 * CC);
    transpose_split2<<<dim3(32, 64, 1), dim3(32, 8)>>>(W2, p_W2h, p_W2l,
                                                       nullptr, nullptr, nullptr, 2 * CC, CC);
    split_f32<<<(DD * CC + 255) / 256, 256>>>(Wd, p_Wdh, p_Wdl, DD * CC);
    split_f32<<<(CC * DD + 255) / 256, 256>>>(Wu, p_Wuh, p_Wul, CC * DD);
    ln_kernel<0, 0, 1, 0><<<CHK, 256>>>(nullptr, nullptr, ln_q_g, ln_q_b, nullptr,
                                        p_qc, nullptr, nullptr, CHK);
    sgemm2<true><<<gemm_grid(CHK, CC), 256>>>(p_qc, Wq, p_Qc, CHK, CC, CC, nullptr);
    cudaMemsetAsync(p_keys, 0, (size_t)NTOK * sizeof(u64), 0);

    // ---- pass A ----
    attn_a<<<dim3(M2, HH), 256>>>(p_KVb, p_Qc, p_ctxh, p_ctxl);
    hgemmP<0, CC, CC><<<hp_grid(NTOK, CC), 128, HP_SMEM>>>(p_ctxh, p_ctxl, p_Woh, p_Wol,
        p_y, nullptr, nullptr, NTOK, CC, CC, nullptr, p_qc, CHK, nullptr, nullptr);
    ln_kernel<0, 1, 0, 0><<<NTOK, 256>>>(p_y, nullptr, ffg, ffb, nullptr,
                                         nullptr, p_hnh, p_hnl, NTOK);
    hgemmP<2, CC, CC><<<hp_grid(NTOK, 2 * CC), 128, HP_SMEM>>>(p_hnh, p_hnl, p_W1h, p_W1l,
        nullptr, p_s1h, p_s1l, NTOK, 2 * CC, CC, b1, nullptr, 0, nullptr, nullptr);
    hgemmP<0, 2 * CC, 2 * CC><<<hp_grid(NTOK, CC), 128, HP_SMEM>>>(p_s1h, p_s1l, p_W2h, p_W2l,
        p_zp, nullptr, nullptr, NTOK, CC, 2 * CC, b2, p_y, 0, nullptr, nullptr);
    ln_ct<1, 0, 0><<<NTOK / 8, 256>>>(ztt, p_zp, tng, tnb, scale, p_rNsh, p_rNsl);
    hgemmP<4, CC, CC><<<hp_grid(NTOK, DP), 128, HP_SMEM>>>(p_rNsh, p_rNsl, p_Wdh, p_Wdl,
        p_rD, p_rDh, p_rDl, NTOK, DP, CC, p_bdp, nullptr, 0, nullptr, nullptr);
    for (int st = 0; st < NBQ; st++) {
        const __half* Ahp = (st == 0) ? p_rDh : p_resh;
        const __half* Alp = (st == 0) ? p_rDl : p_resl;
        const float* Rin = (st == 0) ? p_rD : p_res;
        hgemmP<3, DP, DD><<<hp_grid(NTOK, NEQ), 128, HP_SMEM>>>(Ahp, Alp,
            p_bkh + (size_t)st * NEQ * DD, p_bkl + (size_t)st * NEQ * DD,
            nullptr, nullptr, nullptr, NTOK, NEQ, DD, nullptr, nullptr, 0,
            p_cn + (size_t)st * NEQ, p_keys);
        rvq_update3<<<NTOK, DD>>>(p_keys, books + (size_t)st * NEQ * DD,
                                  Rin, p_res, p_resh, p_resl,
                                  p_qDv, p_qDh, p_qDl,
                                  st == 0 ? 1 : 0, st == NBQ - 1 ? 1 : 0);
    }
    hgemmP<0, DP, DD><<<hp_grid(NTOK, CC), 128, HP_SMEM>>>(p_qDh, p_qDl, p_Wuh, p_Wul,
        p_zh, nullptr, nullptr, NTOK, CC, DD, bu, p_zp, 0, nullptr, nullptr);

    // ---- pass B (split-K for latency-bound GEMMs) ----
    ln_kernel<0, 2, 2, 1><<<M2, 256>>>(p_zh, nullptr, ln_q_g, ln_q_b, nullptr,
                                       p_q0n, p_q0nh, p_q0nl, M2);
    hgemmSK<CC, CC><<<dim3(CC / 128, M2 / 128, 4), 128, HP_SMEM>>>(
        p_q0nh, p_q0nl, p_Wqh, p_Wql, p_part, M2, CC);
    reduceK<0><<<(M2 * CC / 4 + 255) / 256, 256>>>(p_part, 4, M2, CC,
        nullptr, nullptr, p_Q0, nullptr, nullptr);
    attn_b<<<dim3(M2, HH), 128>>>(p_KVb, p_Q0, p_c0h, p_c0l);
    hgemmSK<CC, CC><<<dim3(CC / 128, M2 / 128, 4), 128, HP_SMEM>>>(
        p_c0h, p_c0l, p_Woh, p_Wol, p_part, M2, CC);
    reduceK<0><<<(M2 * CC / 4 + 255) / 256, 256>>>(p_part, 4, M2, CC,
        nullptr, p_q0n, p_y0, nullptr, nullptr);
    ln_kernel<0, 1, 0, 0><<<M2, 256>>>(p_y0, nullptr, ffg, ffb, nullptr,
                                       nullptr, p_hn0h, p_hn0l, M2);
    hgemmP<2, CC, CC><<<hp_grid(M2, 2 * CC), 128, HP_SMEM>>>(p_hn0h, p_hn0l, p_W1h, p_W1l,
        nullptr, p_g10h, p_g10l, M2, 2 * CC, CC, b1, nullptr, 0, nullptr, nullptr);
    hgemmSK<2 * CC, 2 * CC><<<dim3(CC / 128, M2 / 128, 8), 128, HP_SMEM>>>(
        p_g10h, p_g10l, p_W2h, p_W2l, p_part, M2, CC);
    reduceK<0><<<(M2 * CC / 4 + 255) / 256, 256>>>(p_part, 8, M2, CC,
        b2, p_y0, p_z0, nullptr, nullptr);
    ln_ct<1, 0, 1><<<M2 / 8, 256>>>(ztt, p_z0, tng, tnb, scale, p_rNsh, p_rNsl);
    hgemmSK<CC, CC><<<dim3(DP / 128, M2 / 128, 4), 128, HP_SMEM>>>(
        p_rNsh, p_rNsl, p_Wdh, p_Wdl, p_part, M2, DP);
    reduceK<4><<<(M2 * DP / 4 + 255) / 256, 256>>>(p_part, 4, M2, DP,
        p_bdp, nullptr, p_rD0, p_rD0h, p_rD0l);
    for (int st = 0; st < NBQ; st++) {
        const __half* Ahp = (st == 0) ? p_rD0h : p_re0h;
        const __half* Alp = (st == 0) ? p_rD0l : p_re0l;
        const float* Rin = (st == 0) ? p_rD0 : p_res0;
        hgemmP<3, DP, DD><<<hp_grid(M2, NEQ), 128, HP_SMEM>>>(Ahp, Alp,
            p_bkh + (size_t)st * NEQ * DD, p_bkl + (size_t)st * NEQ * DD,
            nullptr, nullptr, nullptr, M2, NEQ, DD, nullptr, nullptr, 0,
            p_cn + (size_t)st * NEQ, p_keys);
        rvq_update3<<<M2, DD>>>(p_keys, books + (size_t)st * NEQ * DD,
                                Rin, p_res0, p_re0h, p_re0l,
                                p_qD0, p_qD0h, p_qD0l,
                                st == 0 ? 1 : 0, st == NBQ - 1 ? 1 : 0);
    }
    hgemmP<0, DP, DD><<<hp_grid(M2, CC), 128, HP_SMEM>>>(p_qD0h, p_qD0l, p_Wuh, p_Wul,
        p_zh0, nullptr, nullptr, M2, CC, DD, bu, p_z0, 0, nullptr, nullptr);
    scatter_rows16_2<<<dim3(M2, 2), 256>>>(p_zh0, p_zh, p_rD0, p_rD);

    // ---- outputs ----
    transpose_tc_to_ct<1><<<dim3(TT / 32, CC / 32, BB), dim3(32, 8)>>>(p_zh, o_y, CC, TT, CC);
    if ((size_t)out_size >= (size_t)BB * CC * TT + (size_t)BB * DD * TT)
        transpose_tc_to_ct<0><<<dim3(TT / 32, DD / 32, BB), dim3(32, 8)>>>(p_rD, o_r, DD, TT, DP);
}